// round 1
// baseline (speedup 1.0000x reference)
#include <cuda_runtime.h>
#include <math.h>

// Problem constants (fixed by the reference setup_inputs)
#define BB 4
#define NN 2048
#define MM 2048
#define DQ 512
#define DC 768
#define HH 8
#define DH 64
#define INNER 512
#define ROWS (BB*NN)   // 8192 rows for x-side, also BB*MM = 8192 for cond-side

// ---------------------------------------------------------------------------
// Scratch (device globals -- no allocation allowed)
// ---------------------------------------------------------------------------
__device__ float g_xn[BB*NN*DQ];      // 16 MB  LN(x)
__device__ float g_cn[BB*MM*DC];      // 24 MB  LN(cond)
__device__ float g_q [BB*NN*INNER];   // 16 MB
__device__ float g_k [BB*MM*INNER];   // 16 MB
__device__ float g_v [BB*MM*INNER];   // 16 MB
__device__ float g_ao[BB*NN*INNER];   // 16 MB  attention output (b n (h d))
__device__ float g_y [BB*NN*DQ];      // 16 MB  pre-final-LN

// ---------------------------------------------------------------------------
// LayerNorm: one block per row
// ---------------------------------------------------------------------------
template<int D>
__global__ void ln_kernel(const float* __restrict__ in,
                          const float* __restrict__ g,
                          const float* __restrict__ b,
                          float* __restrict__ out)
{
    const int row = blockIdx.x;
    const float* x = in + (size_t)row * D;
    float* o = out + (size_t)row * D;

    float s = 0.f, sq = 0.f;
    for (int i = threadIdx.x; i < D; i += blockDim.x) {
        float v = x[i];
        s += v; sq += v * v;
    }
    __shared__ float red0[32], red1[32];
    #pragma unroll
    for (int off = 16; off; off >>= 1) {
        s  += __shfl_xor_sync(0xffffffffu, s,  off);
        sq += __shfl_xor_sync(0xffffffffu, sq, off);
    }
    int wid = threadIdx.x >> 5, lid = threadIdx.x & 31;
    if (lid == 0) { red0[wid] = s; red1[wid] = sq; }
    __syncthreads();
    int nw = blockDim.x >> 5;
    if (wid == 0) {
        s  = (lid < nw) ? red0[lid] : 0.f;
        sq = (lid < nw) ? red1[lid] : 0.f;
        #pragma unroll
        for (int off = 16; off; off >>= 1) {
            s  += __shfl_xor_sync(0xffffffffu, s,  off);
            sq += __shfl_xor_sync(0xffffffffu, sq, off);
        }
        if (lid == 0) { red0[0] = s; red1[0] = sq; }
    }
    __syncthreads();
    const float mu  = red0[0] * (1.0f / D);
    const float var = red1[0] * (1.0f / D) - mu * mu;
    const float rstd = rsqrtf(var + 1e-5f);
    for (int i = threadIdx.x; i < D; i += blockDim.x) {
        o[i] = (x[i] - mu) * rstd * g[i] + b[i];
    }
}

// ---------------------------------------------------------------------------
// Tiled GEMM: C[R,N] = A[R,K] @ W[K,N] (+bias, +residual)
// 64x64 block tile, BK=16, 256 threads, 4x4 microtile per thread.
// Columns mapped as (tx + 16*j) so smem B reads are bank-conflict free.
// ---------------------------------------------------------------------------
__global__ void gemm64_kernel(const float* __restrict__ A,
                              const float* __restrict__ W,
                              float* __restrict__ C,
                              int R, int K, int N,
                              const float* __restrict__ bias,
                              const float* __restrict__ resid)
{
    __shared__ float As[16][65];   // [k][row], padded
    __shared__ float Bs[16][65];   // [k][col], padded
    const int tx = threadIdx.x & 15;
    const int ty = threadIdx.x >> 4;
    const int m0 = blockIdx.y * 64;
    const int n0 = blockIdx.x * 64;

    float acc[4][4] = {};

    for (int k0 = 0; k0 < K; k0 += 16) {
        #pragma unroll
        for (int t = 0; t < 4; t++) {
            int lin = threadIdx.x + t * 256;       // 0..1023
            int ar = lin >> 4, ac = lin & 15;      // row, k
            As[ac][ar] = A[(size_t)(m0 + ar) * K + (k0 + ac)];
        }
        #pragma unroll
        for (int t = 0; t < 4; t++) {
            int lin = threadIdx.x + t * 256;
            int br = lin >> 6, bc = lin & 63;      // k, col
            Bs[br][bc] = W[(size_t)(k0 + br) * N + (n0 + bc)];
        }
        __syncthreads();
        #pragma unroll
        for (int kk = 0; kk < 16; kk++) {
            float a[4], bv[4];
            #pragma unroll
            for (int i = 0; i < 4; i++) a[i]  = As[kk][ty * 4 + i];
            #pragma unroll
            for (int j = 0; j < 4; j++) bv[j] = Bs[kk][tx + 16 * j];
            #pragma unroll
            for (int i = 0; i < 4; i++)
                #pragma unroll
                for (int j = 0; j < 4; j++)
                    acc[i][j] += a[i] * bv[j];
        }
        __syncthreads();
    }

    #pragma unroll
    for (int i = 0; i < 4; i++) {
        int r = m0 + ty * 4 + i;
        #pragma unroll
        for (int j = 0; j < 4; j++) {
            int c = n0 + tx + 16 * j;
            float v = acc[i][j];
            if (bias)  v += bias[c];
            if (resid) v += resid[(size_t)r * N + c];
            C[(size_t)r * N + c] = v;
        }
    }
}

// ---------------------------------------------------------------------------
// Flash attention: per (b,h) head, Q[2048,64] K[2048,64] V[2048,64].
// Block = 64 query rows, streams over keys in 64-row chunks, online softmax.
// 256 threads, 4x4 microtile; all smem padded to 65 -> conflict-free.
// ---------------------------------------------------------------------------
__global__ void attn_kernel(const float* __restrict__ Qg,
                            const float* __restrict__ Kg,
                            const float* __restrict__ Vg,
                            float* __restrict__ Og)
{
    extern __shared__ float sm[];
    float* Qs = sm;                 // 64*65
    float* Ks = Qs + 64 * 65;
    float* Vs = Ks + 64 * 65;
    float* Ps = Vs + 64 * 65;

    const int tx = threadIdx.x & 15;
    const int ty = threadIdx.x >> 4;
    const int it = blockIdx.x;      // query tile
    const int h  = blockIdx.y;
    const int b  = blockIdx.z;

    const float* qb = Qg + ((size_t)b * NN + it * 64) * INNER + h * DH;
    const float* kb = Kg + (size_t)b * MM * INNER + h * DH;
    const float* vb = Vg + (size_t)b * MM * INNER + h * DH;

    // load Q tile
    #pragma unroll
    for (int t = 0; t < 16; t++) {
        int lin = threadIdx.x + t * 256;
        int r = lin >> 6, c = lin & 63;
        Qs[r * 65 + c] = qb[(size_t)r * INNER + c];
    }

    float o[4][4] = {};
    float m[4], l[4];
    #pragma unroll
    for (int i = 0; i < 4; i++) { m[i] = -INFINITY; l[i] = 0.f; }
    const float scale = 0.125f;  // 1/sqrt(64)

    for (int j0 = 0; j0 < MM; j0 += 64) {
        __syncthreads();   // previous chunk's Ks/Vs/Ps reads complete
        #pragma unroll
        for (int t = 0; t < 16; t++) {
            int lin = threadIdx.x + t * 256;
            int r = lin >> 6, c = lin & 63;
            Ks[r * 65 + c] = kb[(size_t)(j0 + r) * INNER + c];
            Vs[r * 65 + c] = vb[(size_t)(j0 + r) * INNER + c];
        }
        __syncthreads();

        // S = Q K^T
        float s[4][4] = {};
        #pragma unroll 8
        for (int k = 0; k < 64; k++) {
            float a[4], kk[4];
            #pragma unroll
            for (int i = 0; i < 4; i++) a[i]  = Qs[(ty * 4 + i) * 65 + k];
            #pragma unroll
            for (int j = 0; j < 4; j++) kk[j] = Ks[(tx + 16 * j) * 65 + k];
            #pragma unroll
            for (int i = 0; i < 4; i++)
                #pragma unroll
                for (int j = 0; j < 4; j++)
                    s[i][j] += a[i] * kk[j];
        }

        // online softmax (row reductions over the 16-lane tx group)
        #pragma unroll
        for (int i = 0; i < 4; i++) {
            float rm = -INFINITY;
            #pragma unroll
            for (int j = 0; j < 4; j++) {
                s[i][j] *= scale;
                rm = fmaxf(rm, s[i][j]);
            }
            #pragma unroll
            for (int off = 8; off; off >>= 1)
                rm = fmaxf(rm, __shfl_xor_sync(0xffffffffu, rm, off));
            float mn = fmaxf(m[i], rm);
            float corr = __expf(m[i] - mn);
            m[i] = mn;
            l[i] *= corr;
            #pragma unroll
            for (int j = 0; j < 4; j++) o[i][j] *= corr;
            float rs = 0.f;
            #pragma unroll
            for (int j = 0; j < 4; j++) {
                float p = __expf(s[i][j] - mn);
                s[i][j] = p;
                rs += p;
            }
            #pragma unroll
            for (int off = 8; off; off >>= 1)
                rs += __shfl_xor_sync(0xffffffffu, rs, off);
            l[i] += rs;
            #pragma unroll
            for (int j = 0; j < 4; j++)
                Ps[(ty * 4 + i) * 65 + tx + 16 * j] = s[i][j];
        }
        __syncthreads();

        // O += P @ V
        #pragma unroll 8
        for (int k = 0; k < 64; k++) {
            float a[4], vv[4];
            #pragma unroll
            for (int i = 0; i < 4; i++) a[i]  = Ps[(ty * 4 + i) * 65 + k];
            #pragma unroll
            for (int j = 0; j < 4; j++) vv[j] = Vs[k * 65 + tx + 16 * j];
            #pragma unroll
            for (int i = 0; i < 4; i++)
                #pragma unroll
                for (int j = 0; j < 4; j++)
                    o[i][j] += a[i] * vv[j];
        }
    }

    // epilogue: normalize and scatter to (b, n, h*64+d)
    #pragma unroll
    for (int i = 0; i < 4; i++) {
        float inv = 1.f / l[i];
        int r = it * 64 + ty * 4 + i;
        #pragma unroll
        for (int j = 0; j < 4; j++) {
            Og[((size_t)b * NN + r) * INNER + h * DH + tx + 16 * j] = o[i][j] * inv;
        }
    }
}

// ---------------------------------------------------------------------------
// Launch
// ---------------------------------------------------------------------------
extern "C" void kernel_launch(void* const* d_in, const int* in_sizes, int n_in,
                              void* d_out, int out_size)
{
    (void)in_sizes; (void)n_in; (void)out_size;
    const float* x     = (const float*)d_in[0];
    const float* cond  = (const float*)d_in[1];
    const float* lnx_g = (const float*)d_in[2];
    const float* lnx_b = (const float*)d_in[3];
    const float* lnc_g = (const float*)d_in[4];
    const float* lnc_b = (const float*)d_in[5];
    const float* Wq    = (const float*)d_in[6];
    const float* Wk    = (const float*)d_in[7];
    const float* Wv    = (const float*)d_in[8];
    const float* Wo    = (const float*)d_in[9];
    const float* bo    = (const float*)d_in[10];
    const float* lnf_g = (const float*)d_in[11];
    const float* lnf_b = (const float*)d_in[12];
    float* out = (float*)d_out;

    float *xn, *cn, *q, *k, *v, *ao, *y;
    cudaGetSymbolAddress((void**)&xn, g_xn);
    cudaGetSymbolAddress((void**)&cn, g_cn);
    cudaGetSymbolAddress((void**)&q,  g_q);
    cudaGetSymbolAddress((void**)&k,  g_k);
    cudaGetSymbolAddress((void**)&v,  g_v);
    cudaGetSymbolAddress((void**)&ao, g_ao);
    cudaGetSymbolAddress((void**)&y,  g_y);

    // LayerNorms of inputs
    ln_kernel<DQ><<<BB * NN, 256>>>(x, lnx_g, lnx_b, xn);
    ln_kernel<DC><<<BB * MM, 256>>>(cond, lnc_g, lnc_b, cn);

    // Projections
    dim3 gthr(256);
    dim3 gq(INNER / 64, (BB * NN) / 64);
    gemm64_kernel<<<gq, gthr>>>(xn, Wq, q, BB * NN, DQ, INNER, nullptr, nullptr);
    dim3 gk(INNER / 64, (BB * MM) / 64);
    gemm64_kernel<<<gk, gthr>>>(cn, Wk, k, BB * MM, DC, INNER, nullptr, nullptr);
    gemm64_kernel<<<gk, gthr>>>(cn, Wv, v, BB * MM, DC, INNER, nullptr, nullptr);

    // Flash attention
    const int attn_smem = 4 * 64 * 65 * (int)sizeof(float);  // 66560 B
    cudaFuncSetAttribute(attn_kernel, cudaFuncAttributeMaxDynamicSharedMemorySize, attn_smem);
    dim3 ga(NN / 64, HH, BB);
    attn_kernel<<<ga, gthr, attn_smem>>>(q, k, v, ao);

    // Output projection + bias + residual
    dim3 go(DQ / 64, (BB * NN) / 64);
    gemm64_kernel<<<go, gthr>>>(ao, Wo, y, BB * NN, INNER, DQ, bo, x);

    // Final LayerNorm -> d_out
    ln_kernel<DQ><<<BB * NN, 256>>>(y, lnf_g, lnf_b, out);
}

// round 2
// speedup vs baseline: 3.0705x; 3.0705x over previous
#include <cuda_runtime.h>
#include <math.h>
#include <stdint.h>

#define BB 4
#define NN 2048
#define MM 2048
#define DQ 512
#define DC 768
#define HH 8
#define DH 64
#define INNER 512

// ---------------------------------------------------------------------------
// Scratch (device globals -- no allocation allowed)
// ---------------------------------------------------------------------------
__device__ float g_xn[BB*NN*DQ];
__device__ float g_cn[BB*MM*DC];
__device__ float g_q [BB*NN*INNER];
__device__ float g_k [BB*MM*INNER];
__device__ float g_v [BB*MM*INNER];
__device__ float g_ao[BB*NN*INNER];
__device__ float g_y [BB*NN*DQ];

// ---------------------------------------------------------------------------
// PTX helpers
// ---------------------------------------------------------------------------
__device__ __forceinline__ uint32_t cvt_tf32(float x) {
    uint32_t r;
    asm("cvt.rna.tf32.f32 %0, %1;" : "=r"(r) : "f"(x));
    return r;
}
__device__ __forceinline__ void ldsm4(uint32_t& r0, uint32_t& r1, uint32_t& r2, uint32_t& r3, uint32_t a) {
    asm volatile("ldmatrix.sync.aligned.m8n8.x4.shared.b16 {%0,%1,%2,%3}, [%4];"
                 : "=r"(r0), "=r"(r1), "=r"(r2), "=r"(r3) : "r"(a));
}
__device__ __forceinline__ void mma8(float* c, uint32_t a0, uint32_t a1, uint32_t a2, uint32_t a3,
                                     uint32_t b0, uint32_t b1) {
    asm volatile(
        "mma.sync.aligned.m16n8k8.row.col.f32.tf32.tf32.f32 "
        "{%0,%1,%2,%3},{%4,%5,%6,%7},{%8,%9},{%0,%1,%2,%3};"
        : "+f"(c[0]), "+f"(c[1]), "+f"(c[2]), "+f"(c[3])
        : "r"(a0), "r"(a1), "r"(a2), "r"(a3), "r"(b0), "r"(b1));
}

// ---------------------------------------------------------------------------
// LayerNorm: one block per row, vectorized
// ---------------------------------------------------------------------------
template<int D>
__global__ void ln_kernel(const float* __restrict__ in,
                          const float* __restrict__ gw,
                          const float* __restrict__ bw,
                          float* __restrict__ out)
{
    const int row = blockIdx.x;
    const float4* x4 = (const float4*)(in + (size_t)row * D);
    float4* o4 = (float4*)(out + (size_t)row * D);

    float s = 0.f, sq = 0.f;
    for (int i = threadIdx.x; i < D / 4; i += blockDim.x) {
        float4 v = x4[i];
        s  += v.x + v.y + v.z + v.w;
        sq += v.x * v.x + v.y * v.y + v.z * v.z + v.w * v.w;
    }
    __shared__ float red0[8], red1[8];
    #pragma unroll
    for (int off = 16; off; off >>= 1) {
        s  += __shfl_xor_sync(0xffffffffu, s,  off);
        sq += __shfl_xor_sync(0xffffffffu, sq, off);
    }
    int wid = threadIdx.x >> 5, lid = threadIdx.x & 31;
    if (lid == 0) { red0[wid] = s; red1[wid] = sq; }
    __syncthreads();
    int nw = blockDim.x >> 5;
    if (wid == 0) {
        s  = (lid < nw) ? red0[lid] : 0.f;
        sq = (lid < nw) ? red1[lid] : 0.f;
        #pragma unroll
        for (int off = 4; off; off >>= 1) {
            s  += __shfl_xor_sync(0xffffffffu, s,  off);
            sq += __shfl_xor_sync(0xffffffffu, sq, off);
        }
        if (lid == 0) { red0[0] = s; red1[0] = sq; }
    }
    __syncthreads();
    const float mu   = red0[0] * (1.0f / D);
    const float var  = red1[0] * (1.0f / D) - mu * mu;
    const float rstd = rsqrtf(var + 1e-5f);
    const float4* g4 = (const float4*)gw;
    const float4* b4 = (const float4*)bw;
    for (int i = threadIdx.x; i < D / 4; i += blockDim.x) {
        float4 v = x4[i], g = g4[i], b = b4[i], r;
        r.x = (v.x - mu) * rstd * g.x + b.x;
        r.y = (v.y - mu) * rstd * g.y + b.y;
        r.z = (v.z - mu) * rstd * g.z + b.z;
        r.w = (v.w - mu) * rstd * g.w + b.w;
        o4[i] = r;
    }
}

// ---------------------------------------------------------------------------
// tf32 tensor-core GEMM: C[R,N] = A[R,K] @ W[K,N] (+bias, +resid)
// 128x128x16 CTA tile, 8 warps (2x4), warp tile 64x32.
// A frags via ldmatrix (As stride 20 -> conflict-free), B frags via LDS.32
// from natural [k][n] layout (stride 132 -> conflict-free).
// ---------------------------------------------------------------------------
__global__ __launch_bounds__(256) void gemm_tc(
    const float* __restrict__ A, const float* __restrict__ W, float* __restrict__ C,
    int R, int K, int N, const float* __restrict__ bias, const float* __restrict__ resid)
{
    __shared__ float As[128][20];
    __shared__ float Bs[16][132];

    const int tid = threadIdx.x;
    const int lane = tid & 31, warp = tid >> 5;
    const int wm = (warp >> 2) * 64;
    const int wn = (warp & 3) * 32;
    const int m0 = blockIdx.y * 128;
    const int n0 = blockIdx.x * 128;
    const int g = lane >> 2, t = lane & 3;

    // global-load mapping
    const int ar = tid >> 2, ac = (tid & 3) * 4;   // A: 64 rows x 16k per pass
    const int br = tid >> 5, bc = (tid & 31) * 4;  // B: 8 k-rows x 128n per pass

    // ldmatrix per-thread row/col within a 16x8 A tile
    const int lrow = (lane & 7) + ((lane >> 3) & 1) * 8;
    const int lcol = ((lane >> 4) & 1) * 4;
    const uint32_t as_base = (uint32_t)__cvta_generic_to_shared(&As[0][0]);

    float acc[4][4][4];
    #pragma unroll
    for (int i = 0; i < 4; i++)
        #pragma unroll
        for (int j = 0; j < 4; j++)
            #pragma unroll
            for (int q = 0; q < 4; q++) acc[i][j][q] = 0.f;

    float4 pa0, pa1, pb0, pb1;
    {
        pa0 = *(const float4*)&A[(size_t)(m0 + ar) * K + ac];
        pa1 = *(const float4*)&A[(size_t)(m0 + ar + 64) * K + ac];
        pb0 = *(const float4*)&W[(size_t)(br)     * N + n0 + bc];
        pb1 = *(const float4*)&W[(size_t)(br + 8) * N + n0 + bc];
    }

    const int ntiles = K / 16;
    for (int kt = 0; kt < ntiles; kt++) {
        __syncthreads();
        {
            uint4 u0 = { cvt_tf32(pa0.x), cvt_tf32(pa0.y), cvt_tf32(pa0.z), cvt_tf32(pa0.w) };
            uint4 u1 = { cvt_tf32(pa1.x), cvt_tf32(pa1.y), cvt_tf32(pa1.z), cvt_tf32(pa1.w) };
            uint4 u2 = { cvt_tf32(pb0.x), cvt_tf32(pb0.y), cvt_tf32(pb0.z), cvt_tf32(pb0.w) };
            uint4 u3 = { cvt_tf32(pb1.x), cvt_tf32(pb1.y), cvt_tf32(pb1.z), cvt_tf32(pb1.w) };
            *(uint4*)&As[ar][ac]       = u0;
            *(uint4*)&As[ar + 64][ac]  = u1;
            *(uint4*)&Bs[br][bc]       = u2;
            *(uint4*)&Bs[br + 8][bc]   = u3;
        }
        __syncthreads();
        if (kt + 1 < ntiles) {
            int k0 = (kt + 1) * 16;
            pa0 = *(const float4*)&A[(size_t)(m0 + ar) * K + k0 + ac];
            pa1 = *(const float4*)&A[(size_t)(m0 + ar + 64) * K + k0 + ac];
            pb0 = *(const float4*)&W[(size_t)(k0 + br)     * N + n0 + bc];
            pb1 = *(const float4*)&W[(size_t)(k0 + br + 8) * N + n0 + bc];
        }
        #pragma unroll
        for (int ks = 0; ks < 2; ks++) {
            const int Cc = ks * 8;
            uint32_t af[4][4];
            #pragma unroll
            for (int mt = 0; mt < 4; mt++) {
                uint32_t addr = as_base + (uint32_t)(((wm + mt * 16 + lrow) * 20 + Cc + lcol) << 2);
                ldsm4(af[mt][0], af[mt][1], af[mt][2], af[mt][3], addr);
            }
            uint32_t bf[4][2];
            #pragma unroll
            for (int nt = 0; nt < 4; nt++) {
                bf[nt][0] = __float_as_uint(Bs[Cc + t][wn + nt * 8 + g]);
                bf[nt][1] = __float_as_uint(Bs[Cc + t + 4][wn + nt * 8 + g]);
            }
            #pragma unroll
            for (int mt = 0; mt < 4; mt++)
                #pragma unroll
                for (int nt = 0; nt < 4; nt++)
                    mma8(acc[mt][nt], af[mt][0], af[mt][1], af[mt][2], af[mt][3],
                         bf[nt][0], bf[nt][1]);
        }
    }

    // epilogue
    #pragma unroll
    for (int mt = 0; mt < 4; mt++) {
        int row = m0 + wm + mt * 16 + g;
        #pragma unroll
        for (int nt = 0; nt < 4; nt++) {
            int col = n0 + wn + nt * 8 + 2 * t;
            float2 r01 = { acc[mt][nt][0], acc[mt][nt][1] };
            float2 r23 = { acc[mt][nt][2], acc[mt][nt][3] };
            if (bias) {
                float2 bb = *(const float2*)&bias[col];
                r01.x += bb.x; r01.y += bb.y;
                r23.x += bb.x; r23.y += bb.y;
            }
            if (resid) {
                float2 e0 = *(const float2*)&resid[(size_t)row * N + col];
                float2 e1 = *(const float2*)&resid[(size_t)(row + 8) * N + col];
                r01.x += e0.x; r01.y += e0.y;
                r23.x += e1.x; r23.y += e1.y;
            }
            *(float2*)&C[(size_t)row * N + col]       = r01;
            *(float2*)&C[(size_t)(row + 8) * N + col] = r23;
        }
    }
}

// ---------------------------------------------------------------------------
// tf32 tensor-core flash attention
// Block: 128 q-rows, 8 warps x 16 rows (full 64-key width per warp).
// Q frags pinned in registers; P via per-warp-private smem (syncwarp only).
// ---------------------------------------------------------------------------
__global__ __launch_bounds__(256) void attn_tc(
    const float* __restrict__ Qg, const float* __restrict__ Kg,
    const float* __restrict__ Vg, float* __restrict__ Og)
{
    extern __shared__ float sm[];
    float (*Ks)[68] = (float(*)[68])sm;
    float (*Vs)[68] = (float(*)[68])(sm + 64 * 68);
    float (*Ps)[68] = (float(*)[68])(sm + 2 * 64 * 68);  // 128 rows; also Q staging

    const int tid  = threadIdx.x;
    const int lane = tid & 31, warp = tid >> 5;
    const int g = lane >> 2, t = lane & 3;
    const int Rr = warp * 16;
    const int it = blockIdx.x, h = blockIdx.y, b = blockIdx.z;

    const float* qb = Qg + ((size_t)b * NN + it * 128) * INNER + h * DH;
    const float* kb = Kg + (size_t)b * MM * INNER + h * DH;
    const float* vb = Vg + (size_t)b * MM * INNER + h * DH;

    // stage Q (tf32) into Ps, pull fragments to registers
    {
        int r = tid >> 4, w4 = (tid & 15) * 4;
        #pragma unroll
        for (int i = 0; i < 8; i++) {
            float4 v = *(const float4*)&qb[(size_t)(r + 16 * i) * INNER + w4];
            uint4 u = { cvt_tf32(v.x), cvt_tf32(v.y), cvt_tf32(v.z), cvt_tf32(v.w) };
            *(uint4*)&Ps[r + 16 * i][w4] = u;
        }
    }
    __syncthreads();
    uint32_t qf[8][4];
    #pragma unroll
    for (int ks = 0; ks < 8; ks++) {
        qf[ks][0] = __float_as_uint(Ps[Rr + g][ks * 8 + t]);
        qf[ks][1] = __float_as_uint(Ps[Rr + 8 + g][ks * 8 + t]);
        qf[ks][2] = __float_as_uint(Ps[Rr + g][ks * 8 + t + 4]);
        qf[ks][3] = __float_as_uint(Ps[Rr + 8 + g][ks * 8 + t + 4]);
    }

    float of[8][4];
    #pragma unroll
    for (int i = 0; i < 8; i++)
        #pragma unroll
        for (int q = 0; q < 4; q++) of[i][q] = 0.f;
    float m0r = -INFINITY, m1r = -INFINITY, l0 = 0.f, l1 = 0.f;
    const float scale = 0.125f;  // 1/sqrt(64)

    for (int j0 = 0; j0 < MM; j0 += 64) {
        __syncthreads();
        {
            int r = tid >> 4, w4 = (tid & 15) * 4;
            #pragma unroll
            for (int i = 0; i < 4; i++) {
                float4 kv = *(const float4*)&kb[(size_t)(j0 + r + 16 * i) * INNER + w4];
                uint4 uk = { cvt_tf32(kv.x), cvt_tf32(kv.y), cvt_tf32(kv.z), cvt_tf32(kv.w) };
                *(uint4*)&Ks[r + 16 * i][w4] = uk;
                float4 vv = *(const float4*)&vb[(size_t)(j0 + r + 16 * i) * INNER + w4];
                uint4 uv = { cvt_tf32(vv.x), cvt_tf32(vv.y), cvt_tf32(vv.z), cvt_tf32(vv.w) };
                *(uint4*)&Vs[r + 16 * i][w4] = uv;
            }
        }
        __syncthreads();

        // S = Q K^T  (16 rows x 64 keys per warp)
        float sacc[8][4];
        #pragma unroll
        for (int i = 0; i < 8; i++)
            #pragma unroll
            for (int q = 0; q < 4; q++) sacc[i][q] = 0.f;
        #pragma unroll
        for (int ks = 0; ks < 8; ks++) {
            #pragma unroll
            for (int nt = 0; nt < 8; nt++) {
                uint32_t b0 = __float_as_uint(Ks[nt * 8 + g][ks * 8 + t]);
                uint32_t b1 = __float_as_uint(Ks[nt * 8 + g][ks * 8 + t + 4]);
                mma8(sacc[nt], qf[ks][0], qf[ks][1], qf[ks][2], qf[ks][3], b0, b1);
            }
        }

        // online softmax
        float rmax0 = -INFINITY, rmax1 = -INFINITY;
        #pragma unroll
        for (int nt = 0; nt < 8; nt++) {
            sacc[nt][0] *= scale; sacc[nt][1] *= scale;
            sacc[nt][2] *= scale; sacc[nt][3] *= scale;
            rmax0 = fmaxf(rmax0, fmaxf(sacc[nt][0], sacc[nt][1]));
            rmax1 = fmaxf(rmax1, fmaxf(sacc[nt][2], sacc[nt][3]));
        }
        rmax0 = fmaxf(rmax0, __shfl_xor_sync(0xffffffffu, rmax0, 1));
        rmax0 = fmaxf(rmax0, __shfl_xor_sync(0xffffffffu, rmax0, 2));
        rmax1 = fmaxf(rmax1, __shfl_xor_sync(0xffffffffu, rmax1, 1));
        rmax1 = fmaxf(rmax1, __shfl_xor_sync(0xffffffffu, rmax1, 2));
        float mn0 = fmaxf(m0r, rmax0), mn1 = fmaxf(m1r, rmax1);
        float c0 = __expf(m0r - mn0), c1 = __expf(m1r - mn1);
        m0r = mn0; m1r = mn1;

        float rs0 = 0.f, rs1 = 0.f;
        #pragma unroll
        for (int nt = 0; nt < 8; nt++) {
            float p0 = __expf(sacc[nt][0] - mn0);
            float p1 = __expf(sacc[nt][1] - mn0);
            float p2 = __expf(sacc[nt][2] - mn1);
            float p3 = __expf(sacc[nt][3] - mn1);
            rs0 += p0 + p1; rs1 += p2 + p3;
            uint2 w01 = { cvt_tf32(p0), cvt_tf32(p1) };
            uint2 w23 = { cvt_tf32(p2), cvt_tf32(p3) };
            *(uint2*)&Ps[Rr + g][nt * 8 + 2 * t]     = w01;
            *(uint2*)&Ps[Rr + 8 + g][nt * 8 + 2 * t] = w23;
        }
        rs0 += __shfl_xor_sync(0xffffffffu, rs0, 1);
        rs0 += __shfl_xor_sync(0xffffffffu, rs0, 2);
        rs1 += __shfl_xor_sync(0xffffffffu, rs1, 1);
        rs1 += __shfl_xor_sync(0xffffffffu, rs1, 2);
        l0 = l0 * c0 + rs0;
        l1 = l1 * c1 + rs1;
        #pragma unroll
        for (int nt = 0; nt < 8; nt++) {
            of[nt][0] *= c0; of[nt][1] *= c0;
            of[nt][2] *= c1; of[nt][3] *= c1;
        }
        __syncwarp();

        // O += P @ V
        #pragma unroll
        for (int ks = 0; ks < 8; ks++) {
            uint32_t a0 = __float_as_uint(Ps[Rr + g][ks * 8 + t]);
            uint32_t a1 = __float_as_uint(Ps[Rr + 8 + g][ks * 8 + t]);
            uint32_t a2 = __float_as_uint(Ps[Rr + g][ks * 8 + t + 4]);
            uint32_t a3 = __float_as_uint(Ps[Rr + 8 + g][ks * 8 + t + 4]);
            #pragma unroll
            for (int nt = 0; nt < 8; nt++) {
                uint32_t b0v = __float_as_uint(Vs[ks * 8 + t][nt * 8 + g]);
                uint32_t b1v = __float_as_uint(Vs[ks * 8 + t + 4][nt * 8 + g]);
                mma8(of[nt], a0, a1, a2, a3, b0v, b1v);
            }
        }
    }

    // epilogue
    float inv0 = 1.f / l0, inv1 = 1.f / l1;
    int row0 = it * 128 + Rr + g, row1 = row0 + 8;
    #pragma unroll
    for (int nt = 0; nt < 8; nt++) {
        float2 w0 = { of[nt][0] * inv0, of[nt][1] * inv0 };
        float2 w1 = { of[nt][2] * inv1, of[nt][3] * inv1 };
        *(float2*)&Og[((size_t)b * NN + row0) * INNER + h * DH + nt * 8 + 2 * t] = w0;
        *(float2*)&Og[((size_t)b * NN + row1) * INNER + h * DH + nt * 8 + 2 * t] = w1;
    }
}

// ---------------------------------------------------------------------------
// Launch
// ---------------------------------------------------------------------------
extern "C" void kernel_launch(void* const* d_in, const int* in_sizes, int n_in,
                              void* d_out, int out_size)
{
    (void)in_sizes; (void)n_in; (void)out_size;
    const float* x     = (const float*)d_in[0];
    const float* cond  = (const float*)d_in[1];
    const float* lnx_g = (const float*)d_in[2];
    const float* lnx_b = (const float*)d_in[3];
    const float* lnc_g = (const float*)d_in[4];
    const float* lnc_b = (const float*)d_in[5];
    const float* Wq    = (const float*)d_in[6];
    const float* Wk    = (const float*)d_in[7];
    const float* Wv    = (const float*)d_in[8];
    const float* Wo    = (const float*)d_in[9];
    const float* bo    = (const float*)d_in[10];
    const float* lnf_g = (const float*)d_in[11];
    const float* lnf_b = (const float*)d_in[12];
    float* out = (float*)d_out;

    float *xn, *cn, *q, *k, *v, *ao, *y;
    cudaGetSymbolAddress((void**)&xn, g_xn);
    cudaGetSymbolAddress((void**)&cn, g_cn);
    cudaGetSymbolAddress((void**)&q,  g_q);
    cudaGetSymbolAddress((void**)&k,  g_k);
    cudaGetSymbolAddress((void**)&v,  g_v);
    cudaGetSymbolAddress((void**)&ao, g_ao);
    cudaGetSymbolAddress((void**)&y,  g_y);

    ln_kernel<DQ><<<BB * NN, 128>>>(x, lnx_g, lnx_b, xn);
    ln_kernel<DC><<<BB * MM, 128>>>(cond, lnc_g, lnc_b, cn);

    dim3 gthr(256);
    dim3 gp(INNER / 128, (BB * NN) / 128);   // 4 x 64
    gemm_tc<<<gp, gthr>>>(xn, Wq, q, BB * NN, DQ, INNER, nullptr, nullptr);
    gemm_tc<<<gp, gthr>>>(cn, Wk, k, BB * MM, DC, INNER, nullptr, nullptr);
    gemm_tc<<<gp, gthr>>>(cn, Wv, v, BB * MM, DC, INNER, nullptr, nullptr);

    const int attn_smem = (2 * 64 * 68 + 128 * 68) * (int)sizeof(float);  // 69632
    cudaFuncSetAttribute(attn_tc, cudaFuncAttributeMaxDynamicSharedMemorySize, attn_smem);
    dim3 ga(NN / 128, HH, BB);   // 16 x 8 x 4
    attn_tc<<<ga, gthr, attn_smem>>>(q, k, v, ao);

    dim3 go(DQ / 128, (BB * NN) / 128);
    gemm_tc<<<go, gthr>>>(ao, Wo, y, BB * NN, INNER, DQ, bo, x);

    ln_kernel<DQ><<<BB * NN, 128>>>(y, lnf_g, lnf_b, out);
}

// round 3
// speedup vs baseline: 3.4805x; 1.1335x over previous
#include <cuda_runtime.h>
#include <math.h>
#include <stdint.h>

#define BB 4
#define NN 2048
#define MM 2048
#define DQ 512
#define DC 768
#define HH 8
#define DH 64
#define INNER 512

// ---------------------------------------------------------------------------
// Scratch (device globals -- no allocation allowed)
// ---------------------------------------------------------------------------
__device__ float g_xn[BB*NN*DQ];
__device__ float g_cn[BB*MM*DC];
__device__ float g_q [BB*NN*INNER];
__device__ float g_k [BB*MM*INNER];
__device__ float g_v [BB*MM*INNER];
__device__ float g_ao[BB*NN*INNER];
__device__ float g_y [BB*NN*DQ];

// ---------------------------------------------------------------------------
// PTX helpers
// ---------------------------------------------------------------------------
__device__ __forceinline__ void cp16(void* dst_smem, const void* src) {
    uint32_t d = (uint32_t)__cvta_generic_to_shared(dst_smem);
    asm volatile("cp.async.ca.shared.global [%0], [%1], 16;" :: "r"(d), "l"(src));
}
__device__ __forceinline__ void cp_commit() {
    asm volatile("cp.async.commit_group;" ::: "memory");
}
__device__ __forceinline__ void cp_wait1() {
    asm volatile("cp.async.wait_group 1;" ::: "memory");
}
__device__ __forceinline__ void ldsm4(uint32_t& r0, uint32_t& r1, uint32_t& r2, uint32_t& r3, uint32_t a) {
    asm volatile("ldmatrix.sync.aligned.m8n8.x4.shared.b16 {%0,%1,%2,%3}, [%4];"
                 : "=r"(r0), "=r"(r1), "=r"(r2), "=r"(r3) : "r"(a));
}
// raw fp32 registers fed as tf32 (hardware truncates low mantissa bits)
__device__ __forceinline__ void mma8(float* c, uint32_t a0, uint32_t a1, uint32_t a2, uint32_t a3,
                                     uint32_t b0, uint32_t b1) {
    asm volatile(
        "mma.sync.aligned.m16n8k8.row.col.f32.tf32.tf32.f32 "
        "{%0,%1,%2,%3},{%4,%5,%6,%7},{%8,%9},{%0,%1,%2,%3};"
        : "+f"(c[0]), "+f"(c[1]), "+f"(c[2]), "+f"(c[3])
        : "r"(a0), "r"(a1), "r"(a2), "r"(a3), "r"(b0), "r"(b1));
}

// ---------------------------------------------------------------------------
// LayerNorm
// ---------------------------------------------------------------------------
template<int D>
__global__ void ln_kernel(const float* __restrict__ in,
                          const float* __restrict__ gw,
                          const float* __restrict__ bw,
                          float* __restrict__ out)
{
    const int row = blockIdx.x;
    const float4* x4 = (const float4*)(in + (size_t)row * D);
    float4* o4 = (float4*)(out + (size_t)row * D);

    float s = 0.f, sq = 0.f;
    for (int i = threadIdx.x; i < D / 4; i += blockDim.x) {
        float4 v = x4[i];
        s  += v.x + v.y + v.z + v.w;
        sq += v.x * v.x + v.y * v.y + v.z * v.z + v.w * v.w;
    }
    __shared__ float red0[8], red1[8];
    #pragma unroll
    for (int off = 16; off; off >>= 1) {
        s  += __shfl_xor_sync(0xffffffffu, s,  off);
        sq += __shfl_xor_sync(0xffffffffu, sq, off);
    }
    int wid = threadIdx.x >> 5, lid = threadIdx.x & 31;
    if (lid == 0) { red0[wid] = s; red1[wid] = sq; }
    __syncthreads();
    int nw = blockDim.x >> 5;
    if (wid == 0) {
        s  = (lid < nw) ? red0[lid] : 0.f;
        sq = (lid < nw) ? red1[lid] : 0.f;
        #pragma unroll
        for (int off = 4; off; off >>= 1) {
            s  += __shfl_xor_sync(0xffffffffu, s,  off);
            sq += __shfl_xor_sync(0xffffffffu, sq, off);
        }
        if (lid == 0) { red0[0] = s; red1[0] = sq; }
    }
    __syncthreads();
    const float mu   = red0[0] * (1.0f / D);
    const float var  = red1[0] * (1.0f / D) - mu * mu;
    const float rstd = rsqrtf(var + 1e-5f);
    const float4* g4 = (const float4*)gw;
    const float4* b4 = (const float4*)bw;
    for (int i = threadIdx.x; i < D / 4; i += blockDim.x) {
        float4 v = x4[i], g = g4[i], b = b4[i], r;
        r.x = (v.x - mu) * rstd * g.x + b.x;
        r.y = (v.y - mu) * rstd * g.y + b.y;
        r.z = (v.z - mu) * rstd * g.z + b.z;
        r.w = (v.w - mu) * rstd * g.w + b.w;
        o4[i] = r;
    }
}

// ---------------------------------------------------------------------------
// tf32 tensor-core GEMM, cp.async double-buffered, BK=32
// CTA tile 128x128, 8 warps (2x4), warp tile 64x32.
// As stride 36 (ldmatrix conflict-free, 16B-aligned rows),
// Bs stride 136 (scalar LDS bank = 8t+g: conflict-free).
// ---------------------------------------------------------------------------
#define GEMM_SMEM ((2*128*36 + 2*32*136) * 4)

__global__ __launch_bounds__(256) void gemm_tc(
    const float* __restrict__ A, const float* __restrict__ W, float* __restrict__ C,
    int R, int K, int N, const float* __restrict__ bias, const float* __restrict__ resid)
{
    extern __shared__ float sm[];
    float* AsB = sm;                  // [2][128][36]
    float* BsB = sm + 2 * 128 * 36;   // [2][32][136]
    #define AS(buf,r,c) AsB[(buf)*4608 + (r)*36 + (c)]
    #define BS(buf,r,c) BsB[(buf)*4352 + (r)*136 + (c)]

    const int tid = threadIdx.x;
    const int lane = tid & 31, warp = tid >> 5;
    const int wm = (warp >> 2) * 64;
    const int wn = (warp & 3) * 32;
    const int m0 = blockIdx.y * 128;
    const int n0 = blockIdx.x * 128;
    const int g = lane >> 2, t = lane & 3;

    // load mapping: A 128x32 (thread: 2 rows x 8 cols), B 32x128 (4 rows x 4 cols)
    const int ar = tid >> 2, acl = (tid & 3) * 8;
    const int br = tid >> 5, bcl = (tid & 31) * 4;

    const int lrow = (lane & 7) + ((lane >> 3) & 1) * 8;
    const int lcol = ((lane >> 4) & 1) * 4;
    const uint32_t as_base = (uint32_t)__cvta_generic_to_shared(AsB);

    float acc[4][4][4];
    #pragma unroll
    for (int i = 0; i < 4; i++)
        #pragma unroll
        for (int j = 0; j < 4; j++)
            #pragma unroll
            for (int q = 0; q < 4; q++) acc[i][j][q] = 0.f;

    auto load_tile = [&](int buf, int kt) {
        int k0 = kt * 32;
        const float* a0 = &A[(size_t)(m0 + ar) * K + k0 + acl];
        cp16(&AS(buf, ar, acl),     a0);
        cp16(&AS(buf, ar, acl + 4), a0 + 4);
        const float* a1 = &A[(size_t)(m0 + ar + 64) * K + k0 + acl];
        cp16(&AS(buf, ar + 64, acl),     a1);
        cp16(&AS(buf, ar + 64, acl + 4), a1 + 4);
        #pragma unroll
        for (int rr = 0; rr < 4; rr++)
            cp16(&BS(buf, br + rr * 8, bcl), &W[(size_t)(k0 + br + rr * 8) * N + n0 + bcl]);
    };

    load_tile(0, 0);
    cp_commit();

    const int ntiles = K / 32;
    for (int kt = 0; kt < ntiles; kt++) {
        const int cur = kt & 1;
        __syncthreads();
        if (kt + 1 < ntiles) load_tile(cur ^ 1, kt + 1);
        cp_commit();
        cp_wait1();
        __syncthreads();

        #pragma unroll
        for (int ks = 0; ks < 4; ks++) {
            const int Cc = ks * 8;
            uint32_t af[4][4];
            #pragma unroll
            for (int mt = 0; mt < 4; mt++) {
                uint32_t addr = as_base +
                    (uint32_t)((cur * 4608 + (wm + mt * 16 + lrow) * 36 + Cc + lcol) << 2);
                ldsm4(af[mt][0], af[mt][1], af[mt][2], af[mt][3], addr);
            }
            uint32_t bf[4][2];
            #pragma unroll
            for (int nt = 0; nt < 4; nt++) {
                bf[nt][0] = __float_as_uint(BS(cur, Cc + t,     wn + nt * 8 + g));
                bf[nt][1] = __float_as_uint(BS(cur, Cc + t + 4, wn + nt * 8 + g));
            }
            #pragma unroll
            for (int mt = 0; mt < 4; mt++)
                #pragma unroll
                for (int nt = 0; nt < 4; nt++)
                    mma8(acc[mt][nt], af[mt][0], af[mt][1], af[mt][2], af[mt][3],
                         bf[nt][0], bf[nt][1]);
        }
    }

    #pragma unroll
    for (int mt = 0; mt < 4; mt++) {
        int row = m0 + wm + mt * 16 + g;
        #pragma unroll
        for (int nt = 0; nt < 4; nt++) {
            int col = n0 + wn + nt * 8 + 2 * t;
            float2 r01 = { acc[mt][nt][0], acc[mt][nt][1] };
            float2 r23 = { acc[mt][nt][2], acc[mt][nt][3] };
            if (bias) {
                float2 bb = *(const float2*)&bias[col];
                r01.x += bb.x; r01.y += bb.y;
                r23.x += bb.x; r23.y += bb.y;
            }
            if (resid) {
                float2 e0 = *(const float2*)&resid[(size_t)row * N + col];
                float2 e1 = *(const float2*)&resid[(size_t)(row + 8) * N + col];
                r01.x += e0.x; r01.y += e0.y;
                r23.x += e1.x; r23.y += e1.y;
            }
            *(float2*)&C[(size_t)row * N + col]       = r01;
            *(float2*)&C[(size_t)(row + 8) * N + col] = r23;
        }
    }
    #undef AS
    #undef BS
}

// ---------------------------------------------------------------------------
// tf32 flash attention, cp.async double-buffered K/V
// Block: 128 q-rows, 8 warps x 16 rows (full 64-key width per warp).
// ---------------------------------------------------------------------------
#define ATTN_SMEM ((2*64*68 + 2*64*72 + 128*68) * 4)

__global__ __launch_bounds__(256) void attn_tc(
    const float* __restrict__ Qg, const float* __restrict__ Kg,
    const float* __restrict__ Vg, float* __restrict__ Og)
{
    extern __shared__ float sm[];
    float* KsB = sm;                        // [2][64][68]
    float* VsB = sm + 2 * 64 * 68;          // [2][64][72]
    float* PsB = sm + 2 * 64 * 68 + 2 * 64 * 72;  // [128][68]
    #define KS(buf,r,c) KsB[(buf)*4352 + (r)*68 + (c)]
    #define VS(buf,r,c) VsB[(buf)*4608 + (r)*72 + (c)]
    #define PS(r,c)     PsB[(r)*68 + (c)]

    const int tid  = threadIdx.x;
    const int lane = tid & 31, warp = tid >> 5;
    const int g = lane >> 2, t = lane & 3;
    const int Rr = warp * 16;
    const int it = blockIdx.x, h = blockIdx.y, b = blockIdx.z;

    const float* qb = Qg + ((size_t)b * NN + it * 128) * INNER + h * DH;
    const float* kb = Kg + (size_t)b * MM * INNER + h * DH;
    const float* vb = Vg + (size_t)b * MM * INNER + h * DH;

    const int r = tid >> 4, w4 = (tid & 15) * 4;

    auto load_chunk = [&](int buf, int j0) {
        #pragma unroll
        for (int i = 0; i < 4; i++) {
            cp16(&KS(buf, r + 16 * i, w4), &kb[(size_t)(j0 + r + 16 * i) * INNER + w4]);
            cp16(&VS(buf, r + 16 * i, w4), &vb[(size_t)(j0 + r + 16 * i) * INNER + w4]);
        }
    };

    // stage Q (raw fp32) into Ps
    #pragma unroll
    for (int i = 0; i < 8; i++)
        cp16(&PS(r + 16 * i, w4), &qb[(size_t)(r + 16 * i) * INNER + w4]);
    cp_commit();
    load_chunk(0, 0);
    cp_commit();
    cp_wait1();          // Q group done
    __syncthreads();

    uint32_t qf[8][4];
    #pragma unroll
    for (int ks = 0; ks < 8; ks++) {
        qf[ks][0] = __float_as_uint(PS(Rr + g,     ks * 8 + t));
        qf[ks][1] = __float_as_uint(PS(Rr + 8 + g, ks * 8 + t));
        qf[ks][2] = __float_as_uint(PS(Rr + g,     ks * 8 + t + 4));
        qf[ks][3] = __float_as_uint(PS(Rr + 8 + g, ks * 8 + t + 4));
    }

    float of[8][4];
    #pragma unroll
    for (int i = 0; i < 8; i++)
        #pragma unroll
        for (int q = 0; q < 4; q++) of[i][q] = 0.f;
    float m0r = -INFINITY, m1r = -INFINITY, l0 = 0.f, l1 = 0.f;
    const float scale = 0.125f;

    const int nch = MM / 64;
    for (int ch = 0; ch < nch; ch++) {
        const int cur = ch & 1;
        __syncthreads();                       // prior compute done reading buf cur^1
        if (ch + 1 < nch) load_chunk(cur ^ 1, (ch + 1) * 64);
        cp_commit();
        cp_wait1();
        __syncthreads();

        // S = Q K^T
        float sacc[8][4];
        #pragma unroll
        for (int i = 0; i < 8; i++)
            #pragma unroll
            for (int q = 0; q < 4; q++) sacc[i][q] = 0.f;
        #pragma unroll
        for (int ks = 0; ks < 8; ks++) {
            #pragma unroll
            for (int nt = 0; nt < 8; nt++) {
                uint32_t b0 = __float_as_uint(KS(cur, nt * 8 + g, ks * 8 + t));
                uint32_t b1 = __float_as_uint(KS(cur, nt * 8 + g, ks * 8 + t + 4));
                mma8(sacc[nt], qf[ks][0], qf[ks][1], qf[ks][2], qf[ks][3], b0, b1);
            }
        }

        // online softmax
        float rmax0 = -INFINITY, rmax1 = -INFINITY;
        #pragma unroll
        for (int nt = 0; nt < 8; nt++) {
            sacc[nt][0] *= scale; sacc[nt][1] *= scale;
            sacc[nt][2] *= scale; sacc[nt][3] *= scale;
            rmax0 = fmaxf(rmax0, fmaxf(sacc[nt][0], sacc[nt][1]));
            rmax1 = fmaxf(rmax1, fmaxf(sacc[nt][2], sacc[nt][3]));
        }
        rmax0 = fmaxf(rmax0, __shfl_xor_sync(0xffffffffu, rmax0, 1));
        rmax0 = fmaxf(rmax0, __shfl_xor_sync(0xffffffffu, rmax0, 2));
        rmax1 = fmaxf(rmax1, __shfl_xor_sync(0xffffffffu, rmax1, 1));
        rmax1 = fmaxf(rmax1, __shfl_xor_sync(0xffffffffu, rmax1, 2));
        float mn0 = fmaxf(m0r, rmax0), mn1 = fmaxf(m1r, rmax1);
        float c0 = __expf(m0r - mn0), c1 = __expf(m1r - mn1);
        m0r = mn0; m1r = mn1;

        float rs0 = 0.f, rs1 = 0.f;
        #pragma unroll
        for (int nt = 0; nt < 8; nt++) {
            float p0 = __expf(sacc[nt][0] - mn0);
            float p1 = __expf(sacc[nt][1] - mn0);
            float p2 = __expf(sacc[nt][2] - mn1);
            float p3 = __expf(sacc[nt][3] - mn1);
            rs0 += p0 + p1; rs1 += p2 + p3;
            *(float2*)&PS(Rr + g,     nt * 8 + 2 * t) = make_float2(p0, p1);
            *(float2*)&PS(Rr + 8 + g, nt * 8 + 2 * t) = make_float2(p2, p3);
        }
        rs0 += __shfl_xor_sync(0xffffffffu, rs0, 1);
        rs0 += __shfl_xor_sync(0xffffffffu, rs0, 2);
        rs1 += __shfl_xor_sync(0xffffffffu, rs1, 1);
        rs1 += __shfl_xor_sync(0xffffffffu, rs1, 2);
        l0 = l0 * c0 + rs0;
        l1 = l1 * c1 + rs1;
        #pragma unroll
        for (int nt = 0; nt < 8; nt++) {
            of[nt][0] *= c0; of[nt][1] *= c0;
            of[nt][2] *= c1; of[nt][3] *= c1;
        }
        __syncwarp();

        // O += P @ V
        #pragma unroll
        for (int ks = 0; ks < 8; ks++) {
            uint32_t a0 = __float_as_uint(PS(Rr + g,     ks * 8 + t));
            uint32_t a1 = __float_as_uint(PS(Rr + 8 + g, ks * 8 + t));
            uint32_t a2 = __float_as_uint(PS(Rr + g,     ks * 8 + t + 4));
            uint32_t a3 = __float_as_uint(PS(Rr + 8 + g, ks * 8 + t + 4));
            #pragma unroll
            for (int nt = 0; nt < 8; nt++) {
                uint32_t b0v = __float_as_uint(VS(cur, ks * 8 + t,     nt * 8 + g));
                uint32_t b1v = __float_as_uint(VS(cur, ks * 8 + t + 4, nt * 8 + g));
                mma8(of[nt], a0, a1, a2, a3, b0v, b1v);
            }
        }
    }

    float inv0 = 1.f / l0, inv1 = 1.f / l1;
    int row0 = it * 128 + Rr + g, row1 = row0 + 8;
    #pragma unroll
    for (int nt = 0; nt < 8; nt++) {
        float2 w0 = { of[nt][0] * inv0, of[nt][1] * inv0 };
        float2 w1 = { of[nt][2] * inv1, of[nt][3] * inv1 };
        *(float2*)&Og[((size_t)b * NN + row0) * INNER + h * DH + nt * 8 + 2 * t] = w0;
        *(float2*)&Og[((size_t)b * NN + row1) * INNER + h * DH + nt * 8 + 2 * t] = w1;
    }
    #undef KS
    #undef VS
    #undef PS
}

// ---------------------------------------------------------------------------
// Launch
// ---------------------------------------------------------------------------
extern "C" void kernel_launch(void* const* d_in, const int* in_sizes, int n_in,
                              void* d_out, int out_size)
{
    (void)in_sizes; (void)n_in; (void)out_size;
    const float* x     = (const float*)d_in[0];
    const float* cond  = (const float*)d_in[1];
    const float* lnx_g = (const float*)d_in[2];
    const float* lnx_b = (const float*)d_in[3];
    const float* lnc_g = (const float*)d_in[4];
    const float* lnc_b = (const float*)d_in[5];
    const float* Wq    = (const float*)d_in[6];
    const float* Wk    = (const float*)d_in[7];
    const float* Wv    = (const float*)d_in[8];
    const float* Wo    = (const float*)d_in[9];
    const float* bo    = (const float*)d_in[10];
    const float* lnf_g = (const float*)d_in[11];
    const float* lnf_b = (const float*)d_in[12];
    float* out = (float*)d_out;

    float *xn, *cn, *q, *k, *v, *ao, *y;
    cudaGetSymbolAddress((void**)&xn, g_xn);
    cudaGetSymbolAddress((void**)&cn, g_cn);
    cudaGetSymbolAddress((void**)&q,  g_q);
    cudaGetSymbolAddress((void**)&k,  g_k);
    cudaGetSymbolAddress((void**)&v,  g_v);
    cudaGetSymbolAddress((void**)&ao, g_ao);
    cudaGetSymbolAddress((void**)&y,  g_y);

    cudaFuncSetAttribute(gemm_tc, cudaFuncAttributeMaxDynamicSharedMemorySize, GEMM_SMEM);
    cudaFuncSetAttribute(attn_tc, cudaFuncAttributeMaxDynamicSharedMemorySize, ATTN_SMEM);

    ln_kernel<DQ><<<BB * NN, 128>>>(x, lnx_g, lnx_b, xn);
    ln_kernel<DC><<<BB * MM, 128>>>(cond, lnc_g, lnc_b, cn);

    dim3 gthr(256);
    dim3 gp(INNER / 128, (BB * NN) / 128);
    gemm_tc<<<gp, gthr, GEMM_SMEM>>>(xn, Wq, q, BB * NN, DQ, INNER, nullptr, nullptr);
    gemm_tc<<<gp, gthr, GEMM_SMEM>>>(cn, Wk, k, BB * MM, DC, INNER, nullptr, nullptr);
    gemm_tc<<<gp, gthr, GEMM_SMEM>>>(cn, Wv, v, BB * MM, DC, INNER, nullptr, nullptr);

    dim3 ga(NN / 128, HH, BB);
    attn_tc<<<ga, gthr, ATTN_SMEM>>>(q, k, v, ao);

    dim3 go(DQ / 128, (BB * NN) / 128);
    gemm_tc<<<go, gthr, GEMM_SMEM>>>(ao, Wo, y, BB * NN, INNER, DQ, bo, x);

    ln_kernel<DQ><<<BB * NN, 128>>>(y, lnf_g, lnf_b, out);
}

// round 5
// speedup vs baseline: 3.6633x; 1.0525x over previous
#include <cuda_runtime.h>
#include <math.h>
#include <stdint.h>

#define BB 4
#define NN 2048
#define MM 2048
#define DQ 512
#define DC 768
#define HH 8
#define DH 64
#define INNER 512

// ---------------------------------------------------------------------------
// Scratch (device globals -- no allocation allowed)
// ---------------------------------------------------------------------------
__device__ float g_xn[BB*NN*DQ];
__device__ float g_cn[BB*MM*DC];
__device__ float g_q [BB*NN*INNER];
__device__ float g_k [BB*MM*INNER];
__device__ float g_v [BB*MM*INNER];
__device__ float g_ao[BB*NN*INNER];
__device__ float g_y [BB*NN*DQ];

// ---------------------------------------------------------------------------
// PTX helpers
// ---------------------------------------------------------------------------
__device__ __forceinline__ void cp16g(void* dst_smem, const void* src) {
    uint32_t d = (uint32_t)__cvta_generic_to_shared(dst_smem);
    asm volatile("cp.async.cg.shared.global [%0], [%1], 16;" :: "r"(d), "l"(src));
}
__device__ __forceinline__ void cp_commit() {
    asm volatile("cp.async.commit_group;" ::: "memory");
}
__device__ __forceinline__ void cp_wait1() {
    asm volatile("cp.async.wait_group 1;" ::: "memory");
}
__device__ __forceinline__ void ldsm4(uint32_t& r0, uint32_t& r1, uint32_t& r2, uint32_t& r3, uint32_t a) {
    asm volatile("ldmatrix.sync.aligned.m8n8.x4.shared.b16 {%0,%1,%2,%3}, [%4];"
                 : "=r"(r0), "=r"(r1), "=r"(r2), "=r"(r3) : "r"(a));
}
// raw fp32 registers fed as tf32 (hardware truncates low mantissa bits)
__device__ __forceinline__ void mma8(float* c, uint32_t a0, uint32_t a1, uint32_t a2, uint32_t a3,
                                     uint32_t b0, uint32_t b1) {
    asm volatile(
        "mma.sync.aligned.m16n8k8.row.col.f32.tf32.tf32.f32 "
        "{%0,%1,%2,%3},{%4,%5,%6,%7},{%8,%9},{%0,%1,%2,%3};"
        : "+f"(c[0]), "+f"(c[1]), "+f"(c[2]), "+f"(c[3])
        : "r"(a0), "r"(a1), "r"(a2), "r"(a3), "r"(b0), "r"(b1));
}

// ---------------------------------------------------------------------------
// LayerNorm
// ---------------------------------------------------------------------------
template<int D>
__global__ void ln_kernel(const float* __restrict__ in,
                          const float* __restrict__ gw,
                          const float* __restrict__ bw,
                          float* __restrict__ out)
{
    const int row = blockIdx.x;
    const float4* x4 = (const float4*)(in + (size_t)row * D);
    float4* o4 = (float4*)(out + (size_t)row * D);

    float s = 0.f, sq = 0.f;
    for (int i = threadIdx.x; i < D / 4; i += blockDim.x) {
        float4 v = x4[i];
        s  += v.x + v.y + v.z + v.w;
        sq += v.x * v.x + v.y * v.y + v.z * v.z + v.w * v.w;
    }
    __shared__ float red0[8], red1[8];
    #pragma unroll
    for (int off = 16; off; off >>= 1) {
        s  += __shfl_xor_sync(0xffffffffu, s,  off);
        sq += __shfl_xor_sync(0xffffffffu, sq, off);
    }
    int wid = threadIdx.x >> 5, lid = threadIdx.x & 31;
    if (lid == 0) { red0[wid] = s; red1[wid] = sq; }
    __syncthreads();
    int nw = blockDim.x >> 5;
    if (wid == 0) {
        s  = (lid < nw) ? red0[lid] : 0.f;
        sq = (lid < nw) ? red1[lid] : 0.f;
        #pragma unroll
        for (int off = 4; off; off >>= 1) {
            s  += __shfl_xor_sync(0xffffffffu, s,  off);
            sq += __shfl_xor_sync(0xffffffffu, sq, off);
        }
        if (lid == 0) { red0[0] = s; red1[0] = sq; }
    }
    __syncthreads();
    const float mu   = red0[0] * (1.0f / D);
    const float var  = red1[0] * (1.0f / D) - mu * mu;
    const float rstd = rsqrtf(var + 1e-5f);
    const float4* g4 = (const float4*)gw;
    const float4* b4 = (const float4*)bw;
    for (int i = threadIdx.x; i < D / 4; i += blockDim.x) {
        float4 v = x4[i], g = g4[i], b = b4[i], r;
        r.x = (v.x - mu) * rstd * g.x + b.x;
        r.y = (v.y - mu) * rstd * g.y + b.y;
        r.z = (v.z - mu) * rstd * g.z + b.z;
        r.w = (v.w - mu) * rstd * g.w + b.w;
        o4[i] = r;
    }
}

// ---------------------------------------------------------------------------
// tf32 tensor-core GEMM, 3-stage cp.async pipeline, BK=32, single sync/tile.
// CTA tile 128x128, 8 warps (2x4), warp tile 64x32.
// As stride 36 (ldmatrix conflict-free, 16B-aligned rows),
// Bs stride 136 (scalar LDS bank = 8t+g: conflict-free).
// ---------------------------------------------------------------------------
#define STG_FLOATS 8960               // 128*36 + 32*136
#define GEMM_SMEM (3 * STG_FLOATS * 4)  // 107520 bytes

__global__ __launch_bounds__(256, 2) void gemm_tc(
    const float* __restrict__ A, const float* __restrict__ W, float* __restrict__ C,
    int K, int N, const float* __restrict__ bias, const float* __restrict__ resid)
{
    extern __shared__ float sm[];
    #define AS(buf,r,c) sm[(buf)*STG_FLOATS + (r)*36 + (c)]
    #define BS(buf,r,c) sm[(buf)*STG_FLOATS + 4608 + (r)*136 + (c)]

    const int tid = threadIdx.x;
    const int lane = tid & 31, warp = tid >> 5;
    const int wm = (warp >> 2) * 64;
    const int wn = (warp & 3) * 32;
    const int m0 = blockIdx.y * 128;
    const int n0 = blockIdx.x * 128;
    const int g = lane >> 2, t = lane & 3;

    const int ar = tid >> 2, acl = (tid & 3) * 8;   // A: 2x(64 rows x 32k)
    const int br = tid >> 5, bcl = (tid & 31) * 4;  // B: 4x(8 k-rows x 128n)

    const int lrow = (lane & 7) + ((lane >> 3) & 1) * 8;
    const int lcol = ((lane >> 4) & 1) * 4;
    const uint32_t as_base = (uint32_t)__cvta_generic_to_shared(sm);

    float acc[4][4][4];
    #pragma unroll
    for (int i = 0; i < 4; i++)
        #pragma unroll
        for (int j = 0; j < 4; j++)
            #pragma unroll
            for (int q = 0; q < 4; q++) acc[i][j][q] = 0.f;

    auto load_tile = [&](int kt, int buf) {
        int k0 = kt * 32;
        const float* a0 = &A[(size_t)(m0 + ar) * K + k0 + acl];
        cp16g(&AS(buf, ar, acl),     a0);
        cp16g(&AS(buf, ar, acl + 4), a0 + 4);
        const float* a1 = &A[(size_t)(m0 + ar + 64) * K + k0 + acl];
        cp16g(&AS(buf, ar + 64, acl),     a1);
        cp16g(&AS(buf, ar + 64, acl + 4), a1 + 4);
        #pragma unroll
        for (int rr = 0; rr < 4; rr++)
            cp16g(&BS(buf, br + rr * 8, bcl), &W[(size_t)(k0 + br + rr * 8) * N + n0 + bcl]);
    };

    const int ntiles = K / 32;
    load_tile(0, 0); cp_commit();
    load_tile(1, 1); cp_commit();
    cp_wait1();            // tile 0 resident
    __syncthreads();

    for (int kt = 0; kt < ntiles; kt++) {
        const int cur = kt % 3;
        // issue load for kt+2 into buffer (kt+2)%3 == (kt-1)%3 (safe: read
        // finished by all warps before the barrier that ended iter kt-1)
        if (kt + 2 < ntiles) load_tile(kt + 2, (kt + 2) % 3);
        cp_commit();

        #pragma unroll
        for (int ks = 0; ks < 4; ks++) {
            const int Cc = ks * 8;
            uint32_t af[4][4];
            #pragma unroll
            for (int mt = 0; mt < 4; mt++) {
                uint32_t addr = as_base +
                    (uint32_t)((cur * STG_FLOATS + (wm + mt * 16 + lrow) * 36 + Cc + lcol) << 2);
                ldsm4(af[mt][0], af[mt][1], af[mt][2], af[mt][3], addr);
            }
            uint32_t bf[4][2];
            #pragma unroll
            for (int nt = 0; nt < 4; nt++) {
                bf[nt][0] = __float_as_uint(BS(cur, Cc + t,     wn + nt * 8 + g));
                bf[nt][1] = __float_as_uint(BS(cur, Cc + t + 4, wn + nt * 8 + g));
            }
            #pragma unroll
            for (int mt = 0; mt < 4; mt++)
                #pragma unroll
                for (int nt = 0; nt < 4; nt++)
                    mma8(acc[mt][nt], af[mt][0], af[mt][1], af[mt][2], af[mt][3],
                         bf[nt][0], bf[nt][1]);
        }

        cp_wait1();        // tile kt+1 resident for next iteration
        __syncthreads();
    }

    #pragma unroll
    for (int mt = 0; mt < 4; mt++) {
        int row = m0 + wm + mt * 16 + g;
        #pragma unroll
        for (int nt = 0; nt < 4; nt++) {
            int col = n0 + wn + nt * 8 + 2 * t;
            float2 r01 = { acc[mt][nt][0], acc[mt][nt][1] };
            float2 r23 = { acc[mt][nt][2], acc[mt][nt][3] };
            if (bias) {
                float2 bb = *(const float2*)&bias[col];
                r01.x += bb.x; r01.y += bb.y;
                r23.x += bb.x; r23.y += bb.y;
            }
            if (resid) {
                float2 e0 = *(const float2*)&resid[(size_t)row * N + col];
                float2 e1 = *(const float2*)&resid[(size_t)(row + 8) * N + col];
                r01.x += e0.x; r01.y += e0.y;
                r23.x += e1.x; r23.y += e1.y;
            }
            *(float2*)&C[(size_t)row * N + col]       = r01;
            *(float2*)&C[(size_t)(row + 8) * N + col] = r23;
        }
    }
    #undef AS
    #undef BS
}

// ---------------------------------------------------------------------------
// tf32 flash attention (mma.sync), cp.async double-buffered K/V
// (unchanged from round 3 -- measured near the mma.sync tensor ceiling)
// ---------------------------------------------------------------------------
#define ATTN_SMEM ((2*64*68 + 2*64*72 + 128*68) * 4)

__global__ __launch_bounds__(256) void attn_tc(
    const float* __restrict__ Qg, const float* __restrict__ Kg,
    const float* __restrict__ Vg, float* __restrict__ Og)
{
    extern __shared__ float sm[];
    float* KsB = sm;
    float* VsB = sm + 2 * 64 * 68;
    float* PsB = sm + 2 * 64 * 68 + 2 * 64 * 72;
    #define KS(buf,r,c) KsB[(buf)*4352 + (r)*68 + (c)]
    #define VS(buf,r,c) VsB[(buf)*4608 + (r)*72 + (c)]
    #define PS(r,c)     PsB[(r)*68 + (c)]

    const int tid  = threadIdx.x;
    const int lane = tid & 31, warp = tid >> 5;
    const int g = lane >> 2, t = lane & 3;
    const int Rr = warp * 16;
    const int it = blockIdx.x, h = blockIdx.y, b = blockIdx.z;

    const float* qb = Qg + ((size_t)b * NN + it * 128) * INNER + h * DH;
    const float* kb = Kg + (size_t)b * MM * INNER + h * DH;
    const float* vb = Vg + (size_t)b * MM * INNER + h * DH;

    const int r = tid >> 4, w4 = (tid & 15) * 4;

    auto load_chunk = [&](int buf, int j0) {
        #pragma unroll
        for (int i = 0; i < 4; i++) {
            cp16g(&KS(buf, r + 16 * i, w4), &kb[(size_t)(j0 + r + 16 * i) * INNER + w4]);
            cp16g(&VS(buf, r + 16 * i, w4), &vb[(size_t)(j0 + r + 16 * i) * INNER + w4]);
        }
    };

    #pragma unroll
    for (int i = 0; i < 8; i++)
        cp16g(&PS(r + 16 * i, w4), &qb[(size_t)(r + 16 * i) * INNER + w4]);
    cp_commit();
    load_chunk(0, 0);
    cp_commit();
    cp_wait1();
    __syncthreads();

    uint32_t qf[8][4];
    #pragma unroll
    for (int ks = 0; ks < 8; ks++) {
        qf[ks][0] = __float_as_uint(PS(Rr + g,     ks * 8 + t));
        qf[ks][1] = __float_as_uint(PS(Rr + 8 + g, ks * 8 + t));
        qf[ks][2] = __float_as_uint(PS(Rr + g,     ks * 8 + t + 4));
        qf[ks][3] = __float_as_uint(PS(Rr + 8 + g, ks * 8 + t + 4));
    }

    float of[8][4];
    #pragma unroll
    for (int i = 0; i < 8; i++)
        #pragma unroll
        for (int q = 0; q < 4; q++) of[i][q] = 0.f;
    float m0r = -INFINITY, m1r = -INFINITY, l0 = 0.f, l1 = 0.f;
    const float scale = 0.125f;

    const int nch = MM / 64;
    for (int ch = 0; ch < nch; ch++) {
        const int cur = ch & 1;
        __syncthreads();
        if (ch + 1 < nch) load_chunk(cur ^ 1, (ch + 1) * 64);
        cp_commit();
        cp_wait1();
        __syncthreads();

        float sacc[8][4];
        #pragma unroll
        for (int i = 0; i < 8; i++)
            #pragma unroll
            for (int q = 0; q < 4; q++) sacc[i][q] = 0.f;
        #pragma unroll
        for (int ks = 0; ks < 8; ks++) {
            #pragma unroll
            for (int nt = 0; nt < 8; nt++) {
                uint32_t b0 = __float_as_uint(KS(cur, nt * 8 + g, ks * 8 + t));
                uint32_t b1 = __float_as_uint(KS(cur, nt * 8 + g, ks * 8 + t + 4));
                mma8(sacc[nt], qf[ks][0], qf[ks][1], qf[ks][2], qf[ks][3], b0, b1);
            }
        }

        float rmax0 = -INFINITY, rmax1 = -INFINITY;
        #pragma unroll
        for (int nt = 0; nt < 8; nt++) {
            sacc[nt][0] *= scale; sacc[nt][1] *= scale;
            sacc[nt][2] *= scale; sacc[nt][3] *= scale;
            rmax0 = fmaxf(rmax0, fmaxf(sacc[nt][0], sacc[nt][1]));
            rmax1 = fmaxf(rmax1, fmaxf(sacc[nt][2], sacc[nt][3]));
        }
        rmax0 = fmaxf(rmax0, __shfl_xor_sync(0xffffffffu, rmax0, 1));
        rmax0 = fmaxf(rmax0, __shfl_xor_sync(0xffffffffu, rmax0, 2));
        rmax1 = fmaxf(rmax1, __shfl_xor_sync(0xffffffffu, rmax1, 1));
        rmax1 = fmaxf(rmax1, __shfl_xor_sync(0xffffffffu, rmax1, 2));
        float mn0 = fmaxf(m0r, rmax0), mn1 = fmaxf(m1r, rmax1);
        float c0 = __expf(m0r - mn0), c1 = __expf(m1r - mn1);
        m0r = mn0; m1r = mn1;

        float rs0 = 0.f, rs1 = 0.f;
        #pragma unroll
        for (int nt = 0; nt < 8; nt++) {
            float p0 = __expf(sacc[nt][0] - mn0);
            float p1 = __expf(sacc[nt][1] - mn0);
            float p2 = __expf(sacc[nt][2] - mn1);
            float p3 = __expf(sacc[nt][3] - mn1);
            rs0 += p0 + p1; rs1 += p2 + p3;
            *(float2*)&PS(Rr + g,     nt * 8 + 2 * t) = make_float2(p0, p1);
            *(float2*)&PS(Rr + 8 + g, nt * 8 + 2 * t) = make_float2(p2, p3);
        }
        rs0 += __shfl_xor_sync(0xffffffffu, rs0, 1);
        rs0 += __shfl_xor_sync(0xffffffffu, rs0, 2);
        rs1 += __shfl_xor_sync(0xffffffffu, rs1, 1);
        rs1 += __shfl_xor_sync(0xffffffffu, rs1, 2);
        l0 = l0 * c0 + rs0;
        l1 = l1 * c1 + rs1;
        #pragma unroll
        for (int nt = 0; nt < 8; nt++) {
            of[nt][0] *= c0; of[nt][1] *= c0;
            of[nt][2] *= c1; of[nt][3] *= c1;
        }
        __syncwarp();

        #pragma unroll
        for (int ks = 0; ks < 8; ks++) {
            uint32_t a0 = __float_as_uint(PS(Rr + g,     ks * 8 + t));
            uint32_t a1 = __float_as_uint(PS(Rr + 8 + g, ks * 8 + t));
            uint32_t a2 = __float_as_uint(PS(Rr + g,     ks * 8 + t + 4));
            uint32_t a3 = __float_as_uint(PS(Rr + 8 + g, ks * 8 + t + 4));
            #pragma unroll
            for (int nt = 0; nt < 8; nt++) {
                uint32_t b0v = __float_as_uint(VS(cur, ks * 8 + t,     nt * 8 + g));
                uint32_t b1v = __float_as_uint(VS(cur, ks * 8 + t + 4, nt * 8 + g));
                mma8(of[nt], a0, a1, a2, a3, b0v, b1v);
            }
        }
    }

    float inv0 = 1.f / l0, inv1 = 1.f / l1;
    int row0 = it * 128 + Rr + g, row1 = row0 + 8;
    #pragma unroll
    for (int nt = 0; nt < 8; nt++) {
        float2 w0 = { of[nt][0] * inv0, of[nt][1] * inv0 };
        float2 w1 = { of[nt][2] * inv1, of[nt][3] * inv1 };
        *(float2*)&Og[((size_t)b * NN + row0) * INNER + h * DH + nt * 8 + 2 * t] = w0;
        *(float2*)&Og[((size_t)b * NN + row1) * INNER + h * DH + nt * 8 + 2 * t] = w1;
    }
    #undef KS
    #undef VS
    #undef PS
}

// ---------------------------------------------------------------------------
// Launch
// ---------------------------------------------------------------------------
extern "C" void kernel_launch(void* const* d_in, const int* in_sizes, int n_in,
                              void* d_out, int out_size)
{
    (void)in_sizes; (void)n_in; (void)out_size;
    const float* x     = (const float*)d_in[0];
    const float* cond  = (const float*)d_in[1];
    const float* lnx_g = (const float*)d_in[2];
    const float* lnx_b = (const float*)d_in[3];
    const float* lnc_g = (const float*)d_in[4];
    const float* lnc_b = (const float*)d_in[5];
    const float* Wq    = (const float*)d_in[6];
    const float* Wk    = (const float*)d_in[7];
    const float* Wv    = (const float*)d_in[8];
    const float* Wo    = (const float*)d_in[9];
    const float* bo    = (const float*)d_in[10];
    const float* lnf_g = (const float*)d_in[11];
    const float* lnf_b = (const float*)d_in[12];
    float* out = (float*)d_out;

    float *xn, *cn, *q, *k, *v, *ao, *y;
    cudaGetSymbolAddress((void**)&xn, g_xn);
    cudaGetSymbolAddress((void**)&cn, g_cn);
    cudaGetSymbolAddress((void**)&q,  g_q);
    cudaGetSymbolAddress((void**)&k,  g_k);
    cudaGetSymbolAddress((void**)&v,  g_v);
    cudaGetSymbolAddress((void**)&ao, g_ao);
    cudaGetSymbolAddress((void**)&y,  g_y);

    cudaFuncSetAttribute(gemm_tc, cudaFuncAttributeMaxDynamicSharedMemorySize, GEMM_SMEM);
    cudaFuncSetAttribute(attn_tc, cudaFuncAttributeMaxDynamicSharedMemorySize, ATTN_SMEM);

    ln_kernel<DQ><<<BB * NN, 128>>>(x, lnx_g, lnx_b, xn);
    ln_kernel<DC><<<BB * MM, 128>>>(cond, lnc_g, lnc_b, cn);

    dim3 gthr(256);
    dim3 gp(INNER / 128, (BB * NN) / 128);
    gemm_tc<<<gp, gthr, GEMM_SMEM>>>(xn, Wq, q, DQ, INNER, nullptr, nullptr);
    gemm_tc<<<gp, gthr, GEMM_SMEM>>>(cn, Wk, k, DC, INNER, nullptr, nullptr);
    gemm_tc<<<gp, gthr, GEMM_SMEM>>>(cn, Wv, v, DC, INNER, nullptr, nullptr);

    dim3 ga(NN / 128, HH, BB);
    attn_tc<<<ga, gthr, ATTN_SMEM>>>(q, k, v, ao);

    dim3 go(DQ / 128, (BB * NN) / 128);
    gemm_tc<<<go, gthr, GEMM_SMEM>>>(ao, Wo, y, INNER, DQ, bo, x);

    ln_kernel<DQ><<<BB * NN, 128>>>(y, lnf_g, lnf_b, out);
}

// round 6
// speedup vs baseline: 6.0612x; 1.6545x over previous
#include <cuda_runtime.h>
#include <cuda_fp16.h>
#include <math.h>
#include <stdint.h>

#define BB 4
#define NN 2048
#define MM 2048
#define DQ 512
#define DC 768
#define HH 8
#define DH 64
#define INNER 512

// ---------------------------------------------------------------------------
// Scratch (device globals -- no allocation allowed)
// ---------------------------------------------------------------------------
__device__ __half g_xn[BB*NN*DQ];
__device__ __half g_cn[BB*MM*DC];
__device__ __half g_q [BB*NN*INNER];
__device__ __half g_k [BB*MM*INNER];
__device__ __half g_v [BB*MM*INNER];
__device__ __half g_ao[BB*NN*INNER];
__device__ float  g_y [BB*NN*DQ];
__device__ __half g_wq[DQ*INNER];
__device__ __half g_wk[DC*INNER];
__device__ __half g_wv[DC*INNER];
__device__ __half g_wo[INNER*DQ];

// ---------------------------------------------------------------------------
// PTX helpers
// ---------------------------------------------------------------------------
__device__ __forceinline__ void cp16g(void* dst_smem, const void* src) {
    uint32_t d = (uint32_t)__cvta_generic_to_shared(dst_smem);
    asm volatile("cp.async.cg.shared.global [%0], [%1], 16;" :: "r"(d), "l"(src));
}
__device__ __forceinline__ void cp_commit() {
    asm volatile("cp.async.commit_group;" ::: "memory");
}
__device__ __forceinline__ void cp_wait1() {
    asm volatile("cp.async.wait_group 1;" ::: "memory");
}
__device__ __forceinline__ void ldsm4(uint32_t& r0, uint32_t& r1, uint32_t& r2, uint32_t& r3, uint32_t a) {
    asm volatile("ldmatrix.sync.aligned.m8n8.x4.shared.b16 {%0,%1,%2,%3}, [%4];"
                 : "=r"(r0), "=r"(r1), "=r"(r2), "=r"(r3) : "r"(a));
}
__device__ __forceinline__ void ldsm4t(uint32_t& r0, uint32_t& r1, uint32_t& r2, uint32_t& r3, uint32_t a) {
    asm volatile("ldmatrix.sync.aligned.m8n8.x4.trans.shared.b16 {%0,%1,%2,%3}, [%4];"
                 : "=r"(r0), "=r"(r1), "=r"(r2), "=r"(r3) : "r"(a));
}
__device__ __forceinline__ void mma16(float* c, uint32_t a0, uint32_t a1, uint32_t a2, uint32_t a3,
                                      uint32_t b0, uint32_t b1) {
    asm volatile(
        "mma.sync.aligned.m16n8k16.row.col.f32.f16.f16.f32 "
        "{%0,%1,%2,%3},{%4,%5,%6,%7},{%8,%9},{%0,%1,%2,%3};"
        : "+f"(c[0]), "+f"(c[1]), "+f"(c[2]), "+f"(c[3])
        : "r"(a0), "r"(a1), "r"(a2), "r"(a3), "r"(b0), "r"(b1));
}

// ---------------------------------------------------------------------------
// fp32 -> fp16 weight conversion
// ---------------------------------------------------------------------------
__global__ void f2h_kernel(const float4* __restrict__ src, __half2* __restrict__ dst, int n4)
{
    int i = blockIdx.x * blockDim.x + threadIdx.x;
    if (i < n4) {
        float4 v = src[i];
        dst[2*i]   = __floats2half2_rn(v.x, v.y);
        dst[2*i+1] = __floats2half2_rn(v.z, v.w);
    }
}

// ---------------------------------------------------------------------------
// LayerNorm (fp32 in; fp16 or fp32 out)
// ---------------------------------------------------------------------------
template<int D, bool HALF>
__global__ void ln_kernel(const float* __restrict__ in,
                          const float* __restrict__ gw,
                          const float* __restrict__ bw,
                          void* __restrict__ outp)
{
    const int row = blockIdx.x;
    const float4* x4 = (const float4*)(in + (size_t)row * D);

    float s = 0.f, sq = 0.f;
    for (int i = threadIdx.x; i < D / 4; i += blockDim.x) {
        float4 v = x4[i];
        s  += v.x + v.y + v.z + v.w;
        sq += v.x * v.x + v.y * v.y + v.z * v.z + v.w * v.w;
    }
    __shared__ float red0[8], red1[8];
    #pragma unroll
    for (int off = 16; off; off >>= 1) {
        s  += __shfl_xor_sync(0xffffffffu, s,  off);
        sq += __shfl_xor_sync(0xffffffffu, sq, off);
    }
    int wid = threadIdx.x >> 5, lid = threadIdx.x & 31;
    if (lid == 0) { red0[wid] = s; red1[wid] = sq; }
    __syncthreads();
    int nw = blockDim.x >> 5;
    if (wid == 0) {
        s  = (lid < nw) ? red0[lid] : 0.f;
        sq = (lid < nw) ? red1[lid] : 0.f;
        #pragma unroll
        for (int off = 4; off; off >>= 1) {
            s  += __shfl_xor_sync(0xffffffffu, s,  off);
            sq += __shfl_xor_sync(0xffffffffu, sq, off);
        }
        if (lid == 0) { red0[0] = s; red1[0] = sq; }
    }
    __syncthreads();
    const float mu   = red0[0] * (1.0f / D);
    const float var  = red1[0] * (1.0f / D) - mu * mu;
    const float rstd = rsqrtf(var + 1e-5f);
    const float4* g4 = (const float4*)gw;
    const float4* b4 = (const float4*)bw;
    for (int i = threadIdx.x; i < D / 4; i += blockDim.x) {
        float4 v = x4[i], g = g4[i], b = b4[i], r;
        r.x = (v.x - mu) * rstd * g.x + b.x;
        r.y = (v.y - mu) * rstd * g.y + b.y;
        r.z = (v.z - mu) * rstd * g.z + b.z;
        r.w = (v.w - mu) * rstd * g.w + b.w;
        if (HALF) {
            __half2* o2 = (__half2*)outp + (size_t)row * (D / 2);
            o2[2*i]   = __floats2half2_rn(r.x, r.y);
            o2[2*i+1] = __floats2half2_rn(r.z, r.w);
        } else {
            float4* o4 = (float4*)outp + (size_t)row * (D / 4);
            o4[i] = r;
        }
    }
}

// ---------------------------------------------------------------------------
// fp16 tensor-core GEMM, 3-stage cp.async pipeline, BK=64.
// CTA tile 128x128, 8 warps (2x4), warp tile 64x32.
// A smem [128][72] halves (ldsm conflict-free), B smem [64][136] halves
// (ldsm.trans conflict-free). Output fp16 (q/k/v) or fp32+bias+resid (O proj).
// ---------------------------------------------------------------------------
#define GS_A 9216                      // 128*72 halves
#define GS_B 8704                      // 64*136 halves
#define GSTG (GS_A + GS_B)             // 17920 halves / stage
#define GEMM_SMEM (3 * GSTG * 2)       // 107520 bytes

__global__ __launch_bounds__(256, 2) void gemm_h(
    const __half* __restrict__ A, const __half* __restrict__ W,
    __half* __restrict__ Ch, float* __restrict__ Cf,
    int K, int N, const float* __restrict__ bias, const float* __restrict__ resid)
{
    extern __shared__ __half smh[];
    const uint32_t sbase = (uint32_t)__cvta_generic_to_shared(smh);

    const int tid = threadIdx.x;
    const int lane = tid & 31, warp = tid >> 5;
    const int wm = (warp >> 2) * 64;
    const int wn = (warp & 3) * 32;
    const int m0 = blockIdx.y * 128;
    const int n0 = blockIdx.x * 128;
    const int g = lane >> 2, t = lane & 3;

    // ldmatrix per-lane offsets
    const int a_row = lane & 15, a_col = (lane >> 4) * 8;           // A (x4)
    const int b_row = (lane & 7) + ((lane >> 3) & 1) * 8;           // B (x4 trans)
    const int b_col = ((lane >> 4) & 1) * 8;

    float acc[4][4][4];
    #pragma unroll
    for (int i = 0; i < 4; i++)
        #pragma unroll
        for (int j = 0; j < 4; j++)
            #pragma unroll
            for (int q = 0; q < 4; q++) acc[i][j][q] = 0.f;

    auto load_tile = [&](int kt, int buf) {
        int k0 = kt * 64;
        __half* As = smh + buf * GSTG;
        __half* Bs = smh + buf * GSTG + GS_A;
        #pragma unroll
        for (int i = 0; i < 4; i++) {
            int id = tid + i * 256;
            int ar = id >> 3, ac = (id & 7) * 8;
            cp16g(&As[ar * 72 + ac], &A[(size_t)(m0 + ar) * K + k0 + ac]);
            int br = id >> 4, bc = (id & 15) * 8;
            cp16g(&Bs[br * 136 + bc], &W[(size_t)(k0 + br) * N + n0 + bc]);
        }
    };

    const int ntiles = K / 64;
    load_tile(0, 0); cp_commit();
    load_tile(1, 1); cp_commit();
    cp_wait1();
    __syncthreads();

    for (int kt = 0; kt < ntiles; kt++) {
        const int cur = kt % 3;
        if (kt + 2 < ntiles) load_tile(kt + 2, (kt + 2) % 3);
        cp_commit();

        const uint32_t abase = sbase + (uint32_t)(cur * GSTG) * 2;
        const uint32_t bbase = abase + (uint32_t)GS_A * 2;

        #pragma unroll
        for (int ks = 0; ks < 4; ks++) {
            uint32_t af[4][4];
            #pragma unroll
            for (int mt = 0; mt < 4; mt++) {
                uint32_t addr = abase +
                    (uint32_t)(((wm + mt * 16 + a_row) * 72 + ks * 16 + a_col) << 1);
                ldsm4(af[mt][0], af[mt][1], af[mt][2], af[mt][3], addr);
            }
            uint32_t bf[8];
            #pragma unroll
            for (int n2 = 0; n2 < 2; n2++) {
                uint32_t addr = bbase +
                    (uint32_t)(((ks * 16 + b_row) * 136 + wn + n2 * 16 + b_col) << 1);
                ldsm4t(bf[n2*4], bf[n2*4+1], bf[n2*4+2], bf[n2*4+3], addr);
            }
            #pragma unroll
            for (int mt = 0; mt < 4; mt++)
                #pragma unroll
                for (int nt = 0; nt < 4; nt++)
                    mma16(acc[mt][nt], af[mt][0], af[mt][1], af[mt][2], af[mt][3],
                          bf[nt*2], bf[nt*2+1]);
        }

        cp_wait1();
        __syncthreads();
    }

    if (Ch) {
        #pragma unroll
        for (int mt = 0; mt < 4; mt++) {
            int row = m0 + wm + mt * 16 + g;
            #pragma unroll
            for (int nt = 0; nt < 4; nt++) {
                int col = n0 + wn + nt * 8 + 2 * t;
                *(__half2*)&Ch[(size_t)row * N + col] =
                    __floats2half2_rn(acc[mt][nt][0], acc[mt][nt][1]);
                *(__half2*)&Ch[(size_t)(row + 8) * N + col] =
                    __floats2half2_rn(acc[mt][nt][2], acc[mt][nt][3]);
            }
        }
    } else {
        #pragma unroll
        for (int mt = 0; mt < 4; mt++) {
            int row = m0 + wm + mt * 16 + g;
            #pragma unroll
            for (int nt = 0; nt < 4; nt++) {
                int col = n0 + wn + nt * 8 + 2 * t;
                float2 r01 = { acc[mt][nt][0], acc[mt][nt][1] };
                float2 r23 = { acc[mt][nt][2], acc[mt][nt][3] };
                if (bias) {
                    float2 bb = *(const float2*)&bias[col];
                    r01.x += bb.x; r01.y += bb.y;
                    r23.x += bb.x; r23.y += bb.y;
                }
                if (resid) {
                    float2 e0 = *(const float2*)&resid[(size_t)row * N + col];
                    float2 e1 = *(const float2*)&resid[(size_t)(row + 8) * N + col];
                    r01.x += e0.x; r01.y += e0.y;
                    r23.x += e1.x; r23.y += e1.y;
                }
                *(float2*)&Cf[(size_t)row * N + col]       = r01;
                *(float2*)&Cf[(size_t)(row + 8) * N + col] = r23;
            }
        }
    }
}

// ---------------------------------------------------------------------------
// fp16 flash attention: 128 q-rows/CTA, 8 warps x 16 rows, 64-key chunks,
// double-buffered cp.async K/V, m16n8k16 MMAs, ldsm.trans for V. 2 CTAs/SM.
// ---------------------------------------------------------------------------
#define KVSTG 4608                       // 64*72 halves per buffer
#define ATTN_SMEM ((4*KVSTG + 128*72) * 2)   // 55296 bytes

__global__ __launch_bounds__(256, 2) void attn_h(
    const __half* __restrict__ Qg, const __half* __restrict__ Kg,
    const __half* __restrict__ Vg, __half* __restrict__ Og)
{
    extern __shared__ __half smh[];
    __half* KsB = smh;                  // [2][64][72]
    __half* VsB = smh + 2 * KVSTG;      // [2][64][72]
    __half* Ps  = smh + 4 * KVSTG;      // [128][72] (Q staging, then P)
    const uint32_t ksbase = (uint32_t)__cvta_generic_to_shared(KsB);
    const uint32_t vsbase = (uint32_t)__cvta_generic_to_shared(VsB);
    const uint32_t psbase = (uint32_t)__cvta_generic_to_shared(Ps);

    const int tid  = threadIdx.x;
    const int lane = tid & 31, warp = tid >> 5;
    const int g = lane >> 2, t = lane & 3;
    const int Rr = warp * 16;
    const int it = blockIdx.x, h = blockIdx.y, b = blockIdx.z;

    const __half* qb = Qg + ((size_t)b * NN + it * 128) * INNER + h * DH;
    const __half* kb = Kg + (size_t)b * MM * INNER + h * DH;
    const __half* vb = Vg + (size_t)b * MM * INNER + h * DH;

    // ldmatrix per-lane offsets
    const int a_row = lane & 15, a_col = (lane >> 4) * 8;              // Q/P (x4)
    const int k_row = (lane & 7) + ((lane >> 4) & 1) * 8;              // K (x4, [n][k])
    const int k_col = ((lane >> 3) & 1) * 8;
    const int v_row = (lane & 7) + ((lane >> 3) & 1) * 8;              // V (x4 trans)
    const int v_col = ((lane >> 4) & 1) * 8;

    auto load_chunk = [&](int buf, int j0) {
        __half* Ks = KsB + buf * KVSTG;
        __half* Vs = VsB + buf * KVSTG;
        #pragma unroll
        for (int i = 0; i < 2; i++) {
            int id = tid + i * 256;
            int r = id >> 3, c = (id & 7) * 8;
            cp16g(&Ks[r * 72 + c], &kb[(size_t)(j0 + r) * INNER + c]);
            cp16g(&Vs[r * 72 + c], &vb[(size_t)(j0 + r) * INNER + c]);
        }
    };

    // stage Q into Ps
    #pragma unroll
    for (int i = 0; i < 4; i++) {
        int id = tid + i * 256;
        int r = id >> 3, c = (id & 7) * 8;
        cp16g(&Ps[r * 72 + c], &qb[(size_t)r * INNER + c]);
    }
    cp_commit();
    load_chunk(0, 0);
    cp_commit();
    cp_wait1();          // Q group done
    __syncthreads();

    uint32_t qf[4][4];
    #pragma unroll
    for (int ks = 0; ks < 4; ks++) {
        uint32_t addr = psbase + (uint32_t)(((Rr + a_row) * 72 + ks * 16 + a_col) << 1);
        ldsm4(qf[ks][0], qf[ks][1], qf[ks][2], qf[ks][3], addr);
    }

    float of[8][4];
    #pragma unroll
    for (int i = 0; i < 8; i++)
        #pragma unroll
        for (int q = 0; q < 4; q++) of[i][q] = 0.f;
    float m0r = -INFINITY, m1r = -INFINITY, l0 = 0.f, l1 = 0.f;
    const float scale = 0.125f;

    const int nch = MM / 64;
    for (int ch = 0; ch < nch; ch++) {
        const int cur = ch & 1;
        __syncthreads();
        if (ch + 1 < nch) load_chunk(cur ^ 1, (ch + 1) * 64);
        cp_commit();
        cp_wait1();
        __syncthreads();

        // S = Q K^T
        float sacc[8][4];
        #pragma unroll
        for (int i = 0; i < 8; i++)
            #pragma unroll
            for (int q = 0; q < 4; q++) sacc[i][q] = 0.f;
        const uint32_t kbase = ksbase + (uint32_t)(cur * KVSTG) * 2;
        #pragma unroll
        for (int ks = 0; ks < 4; ks++) {
            #pragma unroll
            for (int n2 = 0; n2 < 4; n2++) {
                uint32_t kf0, kf1, kf2, kf3;
                uint32_t addr = kbase +
                    (uint32_t)(((n2 * 16 + k_row) * 72 + ks * 16 + k_col) << 1);
                ldsm4(kf0, kf1, kf2, kf3, addr);
                mma16(sacc[n2*2],   qf[ks][0], qf[ks][1], qf[ks][2], qf[ks][3], kf0, kf1);
                mma16(sacc[n2*2+1], qf[ks][0], qf[ks][1], qf[ks][2], qf[ks][3], kf2, kf3);
            }
        }

        // online softmax
        float rmax0 = -INFINITY, rmax1 = -INFINITY;
        #pragma unroll
        for (int nt = 0; nt < 8; nt++) {
            sacc[nt][0] *= scale; sacc[nt][1] *= scale;
            sacc[nt][2] *= scale; sacc[nt][3] *= scale;
            rmax0 = fmaxf(rmax0, fmaxf(sacc[nt][0], sacc[nt][1]));
            rmax1 = fmaxf(rmax1, fmaxf(sacc[nt][2], sacc[nt][3]));
        }
        rmax0 = fmaxf(rmax0, __shfl_xor_sync(0xffffffffu, rmax0, 1));
        rmax0 = fmaxf(rmax0, __shfl_xor_sync(0xffffffffu, rmax0, 2));
        rmax1 = fmaxf(rmax1, __shfl_xor_sync(0xffffffffu, rmax1, 1));
        rmax1 = fmaxf(rmax1, __shfl_xor_sync(0xffffffffu, rmax1, 2));
        float mn0 = fmaxf(m0r, rmax0), mn1 = fmaxf(m1r, rmax1);
        float c0 = __expf(m0r - mn0), c1 = __expf(m1r - mn1);
        m0r = mn0; m1r = mn1;

        float rs0 = 0.f, rs1 = 0.f;
        #pragma unroll
        for (int nt = 0; nt < 8; nt++) {
            float p0 = __expf(sacc[nt][0] - mn0);
            float p1 = __expf(sacc[nt][1] - mn0);
            float p2 = __expf(sacc[nt][2] - mn1);
            float p3 = __expf(sacc[nt][3] - mn1);
            rs0 += p0 + p1; rs1 += p2 + p3;
            *(__half2*)&Ps[(Rr + g) * 72 + nt * 8 + 2 * t]     = __floats2half2_rn(p0, p1);
            *(__half2*)&Ps[(Rr + 8 + g) * 72 + nt * 8 + 2 * t] = __floats2half2_rn(p2, p3);
        }
        rs0 += __shfl_xor_sync(0xffffffffu, rs0, 1);
        rs0 += __shfl_xor_sync(0xffffffffu, rs0, 2);
        rs1 += __shfl_xor_sync(0xffffffffu, rs1, 1);
        rs1 += __shfl_xor_sync(0xffffffffu, rs1, 2);
        l0 = l0 * c0 + rs0;
        l1 = l1 * c1 + rs1;
        #pragma unroll
        for (int nt = 0; nt < 8; nt++) {
            of[nt][0] *= c0; of[nt][1] *= c0;
            of[nt][2] *= c1; of[nt][3] *= c1;
        }
        __syncwarp();

        // O += P @ V
        const uint32_t vbase = vsbase + (uint32_t)(cur * KVSTG) * 2;
        #pragma unroll
        for (int ks = 0; ks < 4; ks++) {
            uint32_t pf0, pf1, pf2, pf3;
            uint32_t paddr = psbase + (uint32_t)(((Rr + a_row) * 72 + ks * 16 + a_col) << 1);
            ldsm4(pf0, pf1, pf2, pf3, paddr);
            #pragma unroll
            for (int n2 = 0; n2 < 4; n2++) {
                uint32_t vf0, vf1, vf2, vf3;
                uint32_t addr = vbase +
                    (uint32_t)(((ks * 16 + v_row) * 72 + n2 * 16 + v_col) << 1);
                ldsm4t(vf0, vf1, vf2, vf3, addr);
                mma16(of[n2*2],   pf0, pf1, pf2, pf3, vf0, vf1);
                mma16(of[n2*2+1], pf0, pf1, pf2, pf3, vf2, vf3);
            }
        }
    }

    float inv0 = 1.f / l0, inv1 = 1.f / l1;
    int row0 = it * 128 + Rr + g, row1 = row0 + 8;
    #pragma unroll
    for (int nt = 0; nt < 8; nt++) {
        *(__half2*)&Og[((size_t)b * NN + row0) * INNER + h * DH + nt * 8 + 2 * t] =
            __floats2half2_rn(of[nt][0] * inv0, of[nt][1] * inv0);
        *(__half2*)&Og[((size_t)b * NN + row1) * INNER + h * DH + nt * 8 + 2 * t] =
            __floats2half2_rn(of[nt][2] * inv1, of[nt][3] * inv1);
    }
}

// ---------------------------------------------------------------------------
// Launch
// ---------------------------------------------------------------------------
extern "C" void kernel_launch(void* const* d_in, const int* in_sizes, int n_in,
                              void* d_out, int out_size)
{
    (void)in_sizes; (void)n_in; (void)out_size;
    const float* x     = (const float*)d_in[0];
    const float* cond  = (const float*)d_in[1];
    const float* lnx_g = (const float*)d_in[2];
    const float* lnx_b = (const float*)d_in[3];
    const float* lnc_g = (const float*)d_in[4];
    const float* lnc_b = (const float*)d_in[5];
    const float* Wq    = (const float*)d_in[6];
    const float* Wk    = (const float*)d_in[7];
    const float* Wv    = (const float*)d_in[8];
    const float* Wo    = (const float*)d_in[9];
    const float* bo    = (const float*)d_in[10];
    const float* lnf_g = (const float*)d_in[11];
    const float* lnf_b = (const float*)d_in[12];
    float* out = (float*)d_out;

    __half *xn, *cn, *q, *k, *v, *ao, *wq, *wk, *wv, *wo;
    float *y;
    cudaGetSymbolAddress((void**)&xn, g_xn);
    cudaGetSymbolAddress((void**)&cn, g_cn);
    cudaGetSymbolAddress((void**)&q,  g_q);
    cudaGetSymbolAddress((void**)&k,  g_k);
    cudaGetSymbolAddress((void**)&v,  g_v);
    cudaGetSymbolAddress((void**)&ao, g_ao);
    cudaGetSymbolAddress((void**)&y,  g_y);
    cudaGetSymbolAddress((void**)&wq, g_wq);
    cudaGetSymbolAddress((void**)&wk, g_wk);
    cudaGetSymbolAddress((void**)&wv, g_wv);
    cudaGetSymbolAddress((void**)&wo, g_wo);

    cudaFuncSetAttribute(gemm_h, cudaFuncAttributeMaxDynamicSharedMemorySize, GEMM_SMEM);
    cudaFuncSetAttribute(attn_h, cudaFuncAttributeMaxDynamicSharedMemorySize, ATTN_SMEM);

    // weights -> fp16
    f2h_kernel<<<(DQ*INNER/4 + 255)/256, 256>>>((const float4*)Wq, (__half2*)wq, DQ*INNER/4);
    f2h_kernel<<<(DC*INNER/4 + 255)/256, 256>>>((const float4*)Wk, (__half2*)wk, DC*INNER/4);
    f2h_kernel<<<(DC*INNER/4 + 255)/256, 256>>>((const float4*)Wv, (__half2*)wv, DC*INNER/4);
    f2h_kernel<<<(INNER*DQ/4 + 255)/256, 256>>>((const float4*)Wo, (__half2*)wo, INNER*DQ/4);

    ln_kernel<DQ, true><<<BB * NN, 128>>>(x, lnx_g, lnx_b, xn);
    ln_kernel<DC, true><<<BB * MM, 128>>>(cond, lnc_g, lnc_b, cn);

    dim3 gthr(256);
    dim3 gp(INNER / 128, (BB * NN) / 128);
    gemm_h<<<gp, gthr, GEMM_SMEM>>>(xn, wq, q, nullptr, DQ, INNER, nullptr, nullptr);
    gemm_h<<<gp, gthr, GEMM_SMEM>>>(cn, wk, k, nullptr, DC, INNER, nullptr, nullptr);
    gemm_h<<<gp, gthr, GEMM_SMEM>>>(cn, wv, v, nullptr, DC, INNER, nullptr, nullptr);

    dim3 ga(NN / 128, HH, BB);
    attn_h<<<ga, gthr, ATTN_SMEM>>>(q, k, v, ao);

    dim3 go(DQ / 128, (BB * NN) / 128);
    gemm_h<<<go, gthr, GEMM_SMEM>>>(ao, wo, nullptr, y, INNER, DQ, bo, x);

    ln_kernel<DQ, false><<<BB * NN, 128>>>(y, lnf_g, lnf_b, out);
}

// round 7
// speedup vs baseline: 6.2825x; 1.0365x over previous
#include <cuda_runtime.h>
#include <cuda_fp16.h>
#include <math.h>
#include <stdint.h>

#define BB 4
#define NN 2048
#define MM 2048
#define DQ 512
#define DC 768
#define HH 8
#define DH 64
#define INNER 512

// ---------------------------------------------------------------------------
// Scratch (device globals -- no allocation allowed)
// ---------------------------------------------------------------------------
__device__ __half g_xn[BB*NN*DQ];
__device__ __half g_cn[BB*MM*DC];
__device__ __half g_q [BB*NN*INNER];
__device__ __half g_k [BB*MM*INNER];
__device__ __half g_v [BB*MM*INNER];
__device__ __half g_ao[BB*NN*INNER];
__device__ float  g_y [BB*NN*DQ];
__device__ __half g_wq[DQ*INNER];
__device__ __half g_wk[DC*INNER];
__device__ __half g_wv[DC*INNER];
__device__ __half g_wo[INNER*DQ];

// ---------------------------------------------------------------------------
// PTX helpers
// ---------------------------------------------------------------------------
__device__ __forceinline__ void cp16g(void* dst_smem, const void* src) {
    uint32_t d = (uint32_t)__cvta_generic_to_shared(dst_smem);
    asm volatile("cp.async.cg.shared.global [%0], [%1], 16;" :: "r"(d), "l"(src));
}
__device__ __forceinline__ void cp_commit() {
    asm volatile("cp.async.commit_group;" ::: "memory");
}
__device__ __forceinline__ void cp_wait1() {
    asm volatile("cp.async.wait_group 1;" ::: "memory");
}
__device__ __forceinline__ void ldsm4(uint32_t& r0, uint32_t& r1, uint32_t& r2, uint32_t& r3, uint32_t a) {
    asm volatile("ldmatrix.sync.aligned.m8n8.x4.shared.b16 {%0,%1,%2,%3}, [%4];"
                 : "=r"(r0), "=r"(r1), "=r"(r2), "=r"(r3) : "r"(a));
}
__device__ __forceinline__ void ldsm4t(uint32_t& r0, uint32_t& r1, uint32_t& r2, uint32_t& r3, uint32_t a) {
    asm volatile("ldmatrix.sync.aligned.m8n8.x4.trans.shared.b16 {%0,%1,%2,%3}, [%4];"
                 : "=r"(r0), "=r"(r1), "=r"(r2), "=r"(r3) : "r"(a));
}
__device__ __forceinline__ void mma16(float* c, uint32_t a0, uint32_t a1, uint32_t a2, uint32_t a3,
                                      uint32_t b0, uint32_t b1) {
    asm volatile(
        "mma.sync.aligned.m16n8k16.row.col.f32.f16.f16.f32 "
        "{%0,%1,%2,%3},{%4,%5,%6,%7},{%8,%9},{%0,%1,%2,%3};"
        : "+f"(c[0]), "+f"(c[1]), "+f"(c[2]), "+f"(c[3])
        : "r"(a0), "r"(a1), "r"(a2), "r"(a3), "r"(b0), "r"(b1));
}

// ---------------------------------------------------------------------------
// fp32 -> fp16: all four weight matrices in one launch
// ---------------------------------------------------------------------------
#define N4_WQ (DQ*INNER/4)
#define N4_WK (DC*INNER/4)
#define N4_WV (DC*INNER/4)
#define N4_WO (INNER*DQ/4)
#define N4_TOT (N4_WQ + N4_WK + N4_WV + N4_WO)

__global__ void f2h_all_kernel(const float4* __restrict__ wq, const float4* __restrict__ wk,
                               const float4* __restrict__ wv, const float4* __restrict__ wo)
{
    int i = blockIdx.x * blockDim.x + threadIdx.x;
    if (i >= N4_TOT) return;
    const float4* src;
    __half2* dst;
    int j = i;
    if (j < N4_WQ)                { src = wq; dst = (__half2*)g_wq; }
    else if ((j -= N4_WQ) < N4_WK) { src = wk; dst = (__half2*)g_wk; }
    else if ((j -= N4_WK) < N4_WV) { src = wv; dst = (__half2*)g_wv; }
    else { j -= N4_WV;              src = wo; dst = (__half2*)g_wo; }
    float4 v = src[j];
    dst[2*j]   = __floats2half2_rn(v.x, v.y);
    dst[2*j+1] = __floats2half2_rn(v.z, v.w);
}

// ---------------------------------------------------------------------------
// LayerNorm (fp32 in; fp16 or fp32 out)
// ---------------------------------------------------------------------------
template<int D, bool HALF>
__global__ void ln_kernel(const float* __restrict__ in,
                          const float* __restrict__ gw,
                          const float* __restrict__ bw,
                          void* __restrict__ outp)
{
    const int row = blockIdx.x;
    const float4* x4 = (const float4*)(in + (size_t)row * D);

    float s = 0.f, sq = 0.f;
    for (int i = threadIdx.x; i < D / 4; i += blockDim.x) {
        float4 v = x4[i];
        s  += v.x + v.y + v.z + v.w;
        sq += v.x * v.x + v.y * v.y + v.z * v.z + v.w * v.w;
    }
    __shared__ float red0[8], red1[8];
    #pragma unroll
    for (int off = 16; off; off >>= 1) {
        s  += __shfl_xor_sync(0xffffffffu, s,  off);
        sq += __shfl_xor_sync(0xffffffffu, sq, off);
    }
    int wid = threadIdx.x >> 5, lid = threadIdx.x & 31;
    if (lid == 0) { red0[wid] = s; red1[wid] = sq; }
    __syncthreads();
    int nw = blockDim.x >> 5;
    if (wid == 0) {
        s  = (lid < nw) ? red0[lid] : 0.f;
        sq = (lid < nw) ? red1[lid] : 0.f;
        #pragma unroll
        for (int off = 4; off; off >>= 1) {
            s  += __shfl_xor_sync(0xffffffffu, s,  off);
            sq += __shfl_xor_sync(0xffffffffu, sq, off);
        }
        if (lid == 0) { red0[0] = s; red1[0] = sq; }
    }
    __syncthreads();
    const float mu   = red0[0] * (1.0f / D);
    const float var  = red1[0] * (1.0f / D) - mu * mu;
    const float rstd = rsqrtf(var + 1e-5f);
    const float4* g4 = (const float4*)gw;
    const float4* b4 = (const float4*)bw;
    for (int i = threadIdx.x; i < D / 4; i += blockDim.x) {
        float4 v = x4[i], g = g4[i], b = b4[i], r;
        r.x = (v.x - mu) * rstd * g.x + b.x;
        r.y = (v.y - mu) * rstd * g.y + b.y;
        r.z = (v.z - mu) * rstd * g.z + b.z;
        r.w = (v.w - mu) * rstd * g.w + b.w;
        if (HALF) {
            __half2* o2 = (__half2*)outp + (size_t)row * (D / 2);
            o2[2*i]   = __floats2half2_rn(r.x, r.y);
            o2[2*i+1] = __floats2half2_rn(r.z, r.w);
        } else {
            float4* o4 = (float4*)outp + (size_t)row * (D / 4);
            o4[i] = r;
        }
    }
}

// ---------------------------------------------------------------------------
// fp16 tensor-core GEMM, 3-stage cp.async pipeline, BK=64.
// CTA 128x128, 8 warps, warp 64x32. Half output scaled by oscale
// (attention 1/sqrt(dh) folded into Q projection). fp32 path: +bias+resid.
// ---------------------------------------------------------------------------
#define GS_A 9216                      // 128*72 halves
#define GS_B 8704                      // 64*136 halves
#define GSTG (GS_A + GS_B)             // 17920 halves / stage
#define GEMM_SMEM (3 * GSTG * 2)       // 107520 bytes

__global__ __launch_bounds__(256, 2) void gemm_h(
    const __half* __restrict__ A, const __half* __restrict__ W,
    __half* __restrict__ Ch, float* __restrict__ Cf,
    int K, int N, float oscale,
    const float* __restrict__ bias, const float* __restrict__ resid)
{
    extern __shared__ __half smh[];
    const uint32_t sbase = (uint32_t)__cvta_generic_to_shared(smh);

    const int tid = threadIdx.x;
    const int lane = tid & 31, warp = tid >> 5;
    const int wm = (warp >> 2) * 64;
    const int wn = (warp & 3) * 32;
    const int m0 = blockIdx.y * 128;
    const int n0 = blockIdx.x * 128;
    const int g = lane >> 2, t = lane & 3;

    const int a_row = lane & 15, a_col = (lane >> 4) * 8;
    const int b_row = (lane & 7) + ((lane >> 3) & 1) * 8;
    const int b_col = ((lane >> 4) & 1) * 8;

    float acc[4][4][4];
    #pragma unroll
    for (int i = 0; i < 4; i++)
        #pragma unroll
        for (int j = 0; j < 4; j++)
            #pragma unroll
            for (int q = 0; q < 4; q++) acc[i][j][q] = 0.f;

    auto load_tile = [&](int kt, int buf) {
        int k0 = kt * 64;
        __half* As = smh + buf * GSTG;
        __half* Bs = smh + buf * GSTG + GS_A;
        #pragma unroll
        for (int i = 0; i < 4; i++) {
            int id = tid + i * 256;
            int ar = id >> 3, ac = (id & 7) * 8;
            cp16g(&As[ar * 72 + ac], &A[(size_t)(m0 + ar) * K + k0 + ac]);
            int br = id >> 4, bc = (id & 15) * 8;
            cp16g(&Bs[br * 136 + bc], &W[(size_t)(k0 + br) * N + n0 + bc]);
        }
    };

    const int ntiles = K / 64;
    load_tile(0, 0); cp_commit();
    load_tile(1, 1); cp_commit();
    cp_wait1();
    __syncthreads();

    for (int kt = 0; kt < ntiles; kt++) {
        const int cur = kt % 3;
        if (kt + 2 < ntiles) load_tile(kt + 2, (kt + 2) % 3);
        cp_commit();

        const uint32_t abase = sbase + (uint32_t)(cur * GSTG) * 2;
        const uint32_t bbase = abase + (uint32_t)GS_A * 2;

        #pragma unroll
        for (int ks = 0; ks < 4; ks++) {
            uint32_t af[4][4];
            #pragma unroll
            for (int mt = 0; mt < 4; mt++) {
                uint32_t addr = abase +
                    (uint32_t)(((wm + mt * 16 + a_row) * 72 + ks * 16 + a_col) << 1);
                ldsm4(af[mt][0], af[mt][1], af[mt][2], af[mt][3], addr);
            }
            uint32_t bf[8];
            #pragma unroll
            for (int n2 = 0; n2 < 2; n2++) {
                uint32_t addr = bbase +
                    (uint32_t)(((ks * 16 + b_row) * 136 + wn + n2 * 16 + b_col) << 1);
                ldsm4t(bf[n2*4], bf[n2*4+1], bf[n2*4+2], bf[n2*4+3], addr);
            }
            #pragma unroll
            for (int mt = 0; mt < 4; mt++)
                #pragma unroll
                for (int nt = 0; nt < 4; nt++)
                    mma16(acc[mt][nt], af[mt][0], af[mt][1], af[mt][2], af[mt][3],
                          bf[nt*2], bf[nt*2+1]);
        }

        cp_wait1();
        __syncthreads();
    }

    if (Ch) {
        #pragma unroll
        for (int mt = 0; mt < 4; mt++) {
            int row = m0 + wm + mt * 16 + g;
            #pragma unroll
            for (int nt = 0; nt < 4; nt++) {
                int col = n0 + wn + nt * 8 + 2 * t;
                *(__half2*)&Ch[(size_t)row * N + col] =
                    __floats2half2_rn(acc[mt][nt][0] * oscale, acc[mt][nt][1] * oscale);
                *(__half2*)&Ch[(size_t)(row + 8) * N + col] =
                    __floats2half2_rn(acc[mt][nt][2] * oscale, acc[mt][nt][3] * oscale);
            }
        }
    } else {
        #pragma unroll
        for (int mt = 0; mt < 4; mt++) {
            int row = m0 + wm + mt * 16 + g;
            #pragma unroll
            for (int nt = 0; nt < 4; nt++) {
                int col = n0 + wn + nt * 8 + 2 * t;
                float2 r01 = { acc[mt][nt][0], acc[mt][nt][1] };
                float2 r23 = { acc[mt][nt][2], acc[mt][nt][3] };
                if (bias) {
                    float2 bb = *(const float2*)&bias[col];
                    r01.x += bb.x; r01.y += bb.y;
                    r23.x += bb.x; r23.y += bb.y;
                }
                if (resid) {
                    float2 e0 = *(const float2*)&resid[(size_t)row * N + col];
                    float2 e1 = *(const float2*)&resid[(size_t)(row + 8) * N + col];
                    r01.x += e0.x; r01.y += e0.y;
                    r23.x += e1.x; r23.y += e1.y;
                }
                *(float2*)&Cf[(size_t)row * N + col]       = r01;
                *(float2*)&Cf[(size_t)(row + 8) * N + col] = r23;
            }
        }
    }
}

// ---------------------------------------------------------------------------
// fp16 flash attention: 128 q-rows/CTA, 8 warps x 16 rows, 64-key chunks,
// 3-stage cp.async K/V pipeline (single sync per chunk). Q pre-scaled.
// ---------------------------------------------------------------------------
#define KVSTG 4608                           // 64*72 halves per buffer
#define ATTN_SMEM ((6*KVSTG + 128*72) * 2)   // 73728 bytes

__global__ __launch_bounds__(256, 2) void attn_h(
    const __half* __restrict__ Qg, const __half* __restrict__ Kg,
    const __half* __restrict__ Vg, __half* __restrict__ Og)
{
    extern __shared__ __half smh[];
    __half* KsB = smh;                  // [3][64][72]
    __half* VsB = smh + 3 * KVSTG;      // [3][64][72]
    __half* Ps  = smh + 6 * KVSTG;      // [128][72] (Q staging, then P)
    const uint32_t ksbase = (uint32_t)__cvta_generic_to_shared(KsB);
    const uint32_t vsbase = (uint32_t)__cvta_generic_to_shared(VsB);
    const uint32_t psbase = (uint32_t)__cvta_generic_to_shared(Ps);

    const int tid  = threadIdx.x;
    const int lane = tid & 31, warp = tid >> 5;
    const int g = lane >> 2, t = lane & 3;
    const int Rr = warp * 16;
    const int it = blockIdx.x, h = blockIdx.y, b = blockIdx.z;

    const __half* qb = Qg + ((size_t)b * NN + it * 128) * INNER + h * DH;
    const __half* kb = Kg + (size_t)b * MM * INNER + h * DH;
    const __half* vb = Vg + (size_t)b * MM * INNER + h * DH;

    const int a_row = lane & 15, a_col = (lane >> 4) * 8;
    const int k_row = (lane & 7) + ((lane >> 4) & 1) * 8;
    const int k_col = ((lane >> 3) & 1) * 8;
    const int v_row = (lane & 7) + ((lane >> 3) & 1) * 8;
    const int v_col = ((lane >> 4) & 1) * 8;

    auto load_chunk = [&](int buf, int j0) {
        __half* Ks = KsB + buf * KVSTG;
        __half* Vs = VsB + buf * KVSTG;
        #pragma unroll
        for (int i = 0; i < 2; i++) {
            int id = tid + i * 256;
            int r = id >> 3, c = (id & 7) * 8;
            cp16g(&Ks[r * 72 + c], &kb[(size_t)(j0 + r) * INNER + c]);
            cp16g(&Vs[r * 72 + c], &vb[(size_t)(j0 + r) * INNER + c]);
        }
    };

    // stage Q + prologue chunks
    #pragma unroll
    for (int i = 0; i < 4; i++) {
        int id = tid + i * 256;
        int r = id >> 3, c = (id & 7) * 8;
        cp16g(&Ps[r * 72 + c], &qb[(size_t)r * INNER + c]);
    }
    load_chunk(0, 0);
    cp_commit();                 // group A: Q + chunk0
    load_chunk(1, 64);
    cp_commit();                 // group B: chunk1
    cp_wait1();                  // group A done
    __syncthreads();

    uint32_t qf[4][4];
    #pragma unroll
    for (int ks = 0; ks < 4; ks++) {
        uint32_t addr = psbase + (uint32_t)(((Rr + a_row) * 72 + ks * 16 + a_col) << 1);
        ldsm4(qf[ks][0], qf[ks][1], qf[ks][2], qf[ks][3], addr);
    }
    __syncthreads();             // all warps have Q frags before Ps reuse

    float of[8][4];
    #pragma unroll
    for (int i = 0; i < 8; i++)
        #pragma unroll
        for (int q = 0; q < 4; q++) of[i][q] = 0.f;
    float m0r = -INFINITY, m1r = -INFINITY, l0 = 0.f, l1 = 0.f;

    const int nch = MM / 64;
    for (int ch = 0; ch < nch; ch++) {
        const int cur = ch % 3;
        if (ch + 2 < nch) load_chunk((ch + 2) % 3, (ch + 2) * 64);
        cp_commit();

        // S = Q K^T  (Q pre-scaled by 1/sqrt(dh))
        float sacc[8][4];
        #pragma unroll
        for (int i = 0; i < 8; i++)
            #pragma unroll
            for (int q = 0; q < 4; q++) sacc[i][q] = 0.f;
        const uint32_t kbase = ksbase + (uint32_t)(cur * KVSTG) * 2;
        #pragma unroll
        for (int ks = 0; ks < 4; ks++) {
            #pragma unroll
            for (int n2 = 0; n2 < 4; n2++) {
                uint32_t kf0, kf1, kf2, kf3;
                uint32_t addr = kbase +
                    (uint32_t)(((n2 * 16 + k_row) * 72 + ks * 16 + k_col) << 1);
                ldsm4(kf0, kf1, kf2, kf3, addr);
                mma16(sacc[n2*2],   qf[ks][0], qf[ks][1], qf[ks][2], qf[ks][3], kf0, kf1);
                mma16(sacc[n2*2+1], qf[ks][0], qf[ks][1], qf[ks][2], qf[ks][3], kf2, kf3);
            }
        }

        // online softmax
        float rmax0 = -INFINITY, rmax1 = -INFINITY;
        #pragma unroll
        for (int nt = 0; nt < 8; nt++) {
            rmax0 = fmaxf(rmax0, fmaxf(sacc[nt][0], sacc[nt][1]));
            rmax1 = fmaxf(rmax1, fmaxf(sacc[nt][2], sacc[nt][3]));
        }
        rmax0 = fmaxf(rmax0, __shfl_xor_sync(0xffffffffu, rmax0, 1));
        rmax0 = fmaxf(rmax0, __shfl_xor_sync(0xffffffffu, rmax0, 2));
        rmax1 = fmaxf(rmax1, __shfl_xor_sync(0xffffffffu, rmax1, 1));
        rmax1 = fmaxf(rmax1, __shfl_xor_sync(0xffffffffu, rmax1, 2));
        float mn0 = fmaxf(m0r, rmax0), mn1 = fmaxf(m1r, rmax1);
        float c0 = __expf(m0r - mn0), c1 = __expf(m1r - mn1);
        m0r = mn0; m1r = mn1;

        float rs0 = 0.f, rs1 = 0.f;
        #pragma unroll
        for (int nt = 0; nt < 8; nt++) {
            float p0 = __expf(sacc[nt][0] - mn0);
            float p1 = __expf(sacc[nt][1] - mn0);
            float p2 = __expf(sacc[nt][2] - mn1);
            float p3 = __expf(sacc[nt][3] - mn1);
            rs0 += p0 + p1; rs1 += p2 + p3;
            *(__half2*)&Ps[(Rr + g) * 72 + nt * 8 + 2 * t]     = __floats2half2_rn(p0, p1);
            *(__half2*)&Ps[(Rr + 8 + g) * 72 + nt * 8 + 2 * t] = __floats2half2_rn(p2, p3);
        }
        rs0 += __shfl_xor_sync(0xffffffffu, rs0, 1);
        rs0 += __shfl_xor_sync(0xffffffffu, rs0, 2);
        rs1 += __shfl_xor_sync(0xffffffffu, rs1, 1);
        rs1 += __shfl_xor_sync(0xffffffffu, rs1, 2);
        l0 = l0 * c0 + rs0;
        l1 = l1 * c1 + rs1;
        #pragma unroll
        for (int nt = 0; nt < 8; nt++) {
            of[nt][0] *= c0; of[nt][1] *= c0;
            of[nt][2] *= c1; of[nt][3] *= c1;
        }
        __syncwarp();

        // O += P @ V
        const uint32_t vbase = vsbase + (uint32_t)(cur * KVSTG) * 2;
        #pragma unroll
        for (int ks = 0; ks < 4; ks++) {
            uint32_t pf0, pf1, pf2, pf3;
            uint32_t paddr = psbase + (uint32_t)(((Rr + a_row) * 72 + ks * 16 + a_col) << 1);
            ldsm4(pf0, pf1, pf2, pf3, paddr);
            #pragma unroll
            for (int n2 = 0; n2 < 4; n2++) {
                uint32_t vf0, vf1, vf2, vf3;
                uint32_t addr = vbase +
                    (uint32_t)(((ks * 16 + v_row) * 72 + n2 * 16 + v_col) << 1);
                ldsm4t(vf0, vf1, vf2, vf3, addr);
                mma16(of[n2*2],   pf0, pf1, pf2, pf3, vf0, vf1);
                mma16(of[n2*2+1], pf0, pf1, pf2, pf3, vf2, vf3);
            }
        }

        cp_wait1();            // chunk ch+1 resident
        __syncthreads();
    }

    float inv0 = 1.f / l0, inv1 = 1.f / l1;
    int row0 = it * 128 + Rr + g, row1 = row0 + 8;
    #pragma unroll
    for (int nt = 0; nt < 8; nt++) {
        *(__half2*)&Og[((size_t)b * NN + row0) * INNER + h * DH + nt * 8 + 2 * t] =
            __floats2half2_rn(of[nt][0] * inv0, of[nt][1] * inv0);
        *(__half2*)&Og[((size_t)b * NN + row1) * INNER + h * DH + nt * 8 + 2 * t] =
            __floats2half2_rn(of[nt][2] * inv1, of[nt][3] * inv1);
    }
}

// ---------------------------------------------------------------------------
// Launch
// ---------------------------------------------------------------------------
extern "C" void kernel_launch(void* const* d_in, const int* in_sizes, int n_in,
                              void* d_out, int out_size)
{
    (void)in_sizes; (void)n_in; (void)out_size;
    const float* x     = (const float*)d_in[0];
    const float* cond  = (const float*)d_in[1];
    const float* lnx_g = (const float*)d_in[2];
    const float* lnx_b = (const float*)d_in[3];
    const float* lnc_g = (const float*)d_in[4];
    const float* lnc_b = (const float*)d_in[5];
    const float* Wq    = (const float*)d_in[6];
    const float* Wk    = (const float*)d_in[7];
    const float* Wv    = (const float*)d_in[8];
    const float* Wo    = (const float*)d_in[9];
    const float* bo    = (const float*)d_in[10];
    const float* lnf_g = (const float*)d_in[11];
    const float* lnf_b = (const float*)d_in[12];
    float* out = (float*)d_out;

    __half *xn, *cn, *q, *k, *v, *ao, *wq, *wk, *wv, *wo;
    float *y;
    cudaGetSymbolAddress((void**)&xn, g_xn);
    cudaGetSymbolAddress((void**)&cn, g_cn);
    cudaGetSymbolAddress((void**)&q,  g_q);
    cudaGetSymbolAddress((void**)&k,  g_k);
    cudaGetSymbolAddress((void**)&v,  g_v);
    cudaGetSymbolAddress((void**)&ao, g_ao);
    cudaGetSymbolAddress((void**)&y,  g_y);
    cudaGetSymbolAddress((void**)&wq, g_wq);
    cudaGetSymbolAddress((void**)&wk, g_wk);
    cudaGetSymbolAddress((void**)&wv, g_wv);
    cudaGetSymbolAddress((void**)&wo, g_wo);

    cudaFuncSetAttribute(gemm_h, cudaFuncAttributeMaxDynamicSharedMemorySize, GEMM_SMEM);
    cudaFuncSetAttribute(attn_h, cudaFuncAttributeMaxDynamicSharedMemorySize, ATTN_SMEM);

    f2h_all_kernel<<<(N4_TOT + 255)/256, 256>>>((const float4*)Wq, (const float4*)Wk,
                                                (const float4*)Wv, (const float4*)Wo);

    ln_kernel<DQ, true><<<BB * NN, 128>>>(x, lnx_g, lnx_b, xn);
    ln_kernel<DC, true><<<BB * MM, 128>>>(cond, lnc_g, lnc_b, cn);

    dim3 gthr(256);
    dim3 gp(INNER / 128, (BB * NN) / 128);
    gemm_h<<<gp, gthr, GEMM_SMEM>>>(xn, wq, q, nullptr, DQ, INNER, 0.125f, nullptr, nullptr);
    gemm_h<<<gp, gthr, GEMM_SMEM>>>(cn, wk, k, nullptr, DC, INNER, 1.0f, nullptr, nullptr);
    gemm_h<<<gp, gthr, GEMM_SMEM>>>(cn, wv, v, nullptr, DC, INNER, 1.0f, nullptr, nullptr);

    dim3 ga(NN / 128, HH, BB);
    attn_h<<<ga, gthr, ATTN_SMEM>>>(q, k, v, ao);

    dim3 go(DQ / 128, (BB * NN) / 128);
    gemm_h<<<go, gthr, GEMM_SMEM>>>(ao, wo, nullptr, y, INNER, DQ, 1.0f, bo, x);

    ln_kernel<DQ, false><<<BB * NN, 128>>>(y, lnf_g, lnf_b, out);
}

// round 9
// speedup vs baseline: 6.6015x; 1.0508x over previous
#include <cuda_runtime.h>
#include <cuda_fp16.h>
#include <math.h>
#include <stdint.h>

#define BB 4
#define NN 2048
#define MM 2048
#define DQ 512
#define DC 768
#define HH 8
#define DH 64
#define INNER 512

// ---------------------------------------------------------------------------
// Scratch (device globals -- no allocation allowed)
// ---------------------------------------------------------------------------
__device__ __half g_xn[BB*NN*DQ];
__device__ __half g_cn[BB*MM*DC];
__device__ __half g_q [BB*NN*INNER];
__device__ __half g_k [BB*MM*INNER];
__device__ __half g_v [BB*MM*INNER];
__device__ __half g_ao[BB*NN*INNER];
__device__ float  g_y [BB*NN*DQ];
__device__ __half g_wq[DQ*INNER];
__device__ __half g_wk[DC*INNER];
__device__ __half g_wv[DC*INNER];
__device__ __half g_wo[INNER*DQ];

// ---------------------------------------------------------------------------
// PTX helpers
// ---------------------------------------------------------------------------
__device__ __forceinline__ uint32_t h2_as_u32(__half2 h) {
    return *reinterpret_cast<uint32_t*>(&h);
}
__device__ __forceinline__ void cp16g(void* dst_smem, const void* src) {
    uint32_t d = (uint32_t)__cvta_generic_to_shared(dst_smem);
    asm volatile("cp.async.cg.shared.global [%0], [%1], 16;" :: "r"(d), "l"(src));
}
__device__ __forceinline__ void cp_commit() {
    asm volatile("cp.async.commit_group;" ::: "memory");
}
__device__ __forceinline__ void cp_wait1() {
    asm volatile("cp.async.wait_group 1;" ::: "memory");
}
__device__ __forceinline__ void ldsm4(uint32_t& r0, uint32_t& r1, uint32_t& r2, uint32_t& r3, uint32_t a) {
    asm volatile("ldmatrix.sync.aligned.m8n8.x4.shared.b16 {%0,%1,%2,%3}, [%4];"
                 : "=r"(r0), "=r"(r1), "=r"(r2), "=r"(r3) : "r"(a));
}
__device__ __forceinline__ void ldsm4t(uint32_t& r0, uint32_t& r1, uint32_t& r2, uint32_t& r3, uint32_t a) {
    asm volatile("ldmatrix.sync.aligned.m8n8.x4.trans.shared.b16 {%0,%1,%2,%3}, [%4];"
                 : "=r"(r0), "=r"(r1), "=r"(r2), "=r"(r3) : "r"(a));
}
__device__ __forceinline__ void mma16(float* c, uint32_t a0, uint32_t a1, uint32_t a2, uint32_t a3,
                                      uint32_t b0, uint32_t b1) {
    asm volatile(
        "mma.sync.aligned.m16n8k16.row.col.f32.f16.f16.f32 "
        "{%0,%1,%2,%3},{%4,%5,%6,%7},{%8,%9},{%0,%1,%2,%3};"
        : "+f"(c[0]), "+f"(c[1]), "+f"(c[2]), "+f"(c[3])
        : "r"(a0), "r"(a1), "r"(a2), "r"(a3), "r"(b0), "r"(b1));
}

// ---------------------------------------------------------------------------
// fp32 -> fp16: all four weight matrices in one launch
// ---------------------------------------------------------------------------
#define N4_WQ (DQ*INNER/4)
#define N4_WK (DC*INNER/4)
#define N4_WV (DC*INNER/4)
#define N4_WO (INNER*DQ/4)
#define N4_TOT (N4_WQ + N4_WK + N4_WV + N4_WO)

__global__ void f2h_all_kernel(const float4* __restrict__ wq, const float4* __restrict__ wk,
                               const float4* __restrict__ wv, const float4* __restrict__ wo)
{
    int i = blockIdx.x * blockDim.x + threadIdx.x;
    if (i >= N4_TOT) return;
    const float4* src;
    __half2* dst;
    int j = i;
    if (j < N4_WQ)                { src = wq; dst = (__half2*)g_wq; }
    else if ((j -= N4_WQ) < N4_WK) { src = wk; dst = (__half2*)g_wk; }
    else if ((j -= N4_WK) < N4_WV) { src = wv; dst = (__half2*)g_wv; }
    else { j -= N4_WV;              src = wo; dst = (__half2*)g_wo; }
    float4 v = src[j];
    dst[2*j]   = __floats2half2_rn(v.x, v.y);
    dst[2*j+1] = __floats2half2_rn(v.z, v.w);
}

// ---------------------------------------------------------------------------
// LayerNorm (fp32 in; fp16 or fp32 out)
// ---------------------------------------------------------------------------
template<int D, bool HALF>
__global__ void ln_kernel(const float* __restrict__ in,
                          const float* __restrict__ gw,
                          const float* __restrict__ bw,
                          void* __restrict__ outp)
{
    const int row = blockIdx.x;
    const float4* x4 = (const float4*)(in + (size_t)row * D);

    float s = 0.f, sq = 0.f;
    for (int i = threadIdx.x; i < D / 4; i += blockDim.x) {
        float4 v = x4[i];
        s  += v.x + v.y + v.z + v.w;
        sq += v.x * v.x + v.y * v.y + v.z * v.z + v.w * v.w;
    }
    __shared__ float red0[8], red1[8];
    #pragma unroll
    for (int off = 16; off; off >>= 1) {
        s  += __shfl_xor_sync(0xffffffffu, s,  off);
        sq += __shfl_xor_sync(0xffffffffu, sq, off);
    }
    int wid = threadIdx.x >> 5, lid = threadIdx.x & 31;
    if (lid == 0) { red0[wid] = s; red1[wid] = sq; }
    __syncthreads();
    int nw = blockDim.x >> 5;
    if (wid == 0) {
        s  = (lid < nw) ? red0[lid] : 0.f;
        sq = (lid < nw) ? red1[lid] : 0.f;
        #pragma unroll
        for (int off = 4; off; off >>= 1) {
            s  += __shfl_xor_sync(0xffffffffu, s,  off);
            sq += __shfl_xor_sync(0xffffffffu, sq, off);
        }
        if (lid == 0) { red0[0] = s; red1[0] = sq; }
    }
    __syncthreads();
    const float mu   = red0[0] * (1.0f / D);
    const float var  = red1[0] * (1.0f / D) - mu * mu;
    const float rstd = rsqrtf(var + 1e-5f);
    const float4* g4 = (const float4*)gw;
    const float4* b4 = (const float4*)bw;
    for (int i = threadIdx.x; i < D / 4; i += blockDim.x) {
        float4 v = x4[i], g = g4[i], b = b4[i], r;
        r.x = (v.x - mu) * rstd * g.x + b.x;
        r.y = (v.y - mu) * rstd * g.y + b.y;
        r.z = (v.z - mu) * rstd * g.z + b.z;
        r.w = (v.w - mu) * rstd * g.w + b.w;
        if (HALF) {
            __half2* o2 = (__half2*)outp + (size_t)row * (D / 2);
            o2[2*i]   = __floats2half2_rn(r.x, r.y);
            o2[2*i+1] = __floats2half2_rn(r.z, r.w);
        } else {
            float4* o4 = (float4*)outp + (size_t)row * (D / 4);
            o4[i] = r;
        }
    }
}

// ---------------------------------------------------------------------------
// fp16 tensor-core GEMM, 3-stage cp.async pipeline, BK=64.
// CTA 128x128, 8 warps, warp 64x32. Half output scaled by oscale.
// ---------------------------------------------------------------------------
#define GS_A 9216                      // 128*72 halves
#define GS_B 8704                      // 64*136 halves
#define GSTG (GS_A + GS_B)             // 17920 halves / stage
#define GEMM_SMEM (3 * GSTG * 2)       // 107520 bytes

__global__ __launch_bounds__(256, 2) void gemm_h(
    const __half* __restrict__ A, const __half* __restrict__ W,
    __half* __restrict__ Ch, float* __restrict__ Cf,
    int K, int N, float oscale,
    const float* __restrict__ bias, const float* __restrict__ resid)
{
    extern __shared__ __half smh[];
    const uint32_t sbase = (uint32_t)__cvta_generic_to_shared(smh);

    const int tid = threadIdx.x;
    const int lane = tid & 31, warp = tid >> 5;
    const int wm = (warp >> 2) * 64;
    const int wn = (warp & 3) * 32;
    const int m0 = blockIdx.y * 128;
    const int n0 = blockIdx.x * 128;
    const int g = lane >> 2, t = lane & 3;

    const int a_row = lane & 15, a_col = (lane >> 4) * 8;
    const int b_row = (lane & 7) + ((lane >> 3) & 1) * 8;
    const int b_col = ((lane >> 4) & 1) * 8;

    float acc[4][4][4];
    #pragma unroll
    for (int i = 0; i < 4; i++)
        #pragma unroll
        for (int j = 0; j < 4; j++)
            #pragma unroll
            for (int q = 0; q < 4; q++) acc[i][j][q] = 0.f;

    auto load_tile = [&](int kt, int buf) {
        int k0 = kt * 64;
        __half* As = smh + buf * GSTG;
        __half* Bs = smh + buf * GSTG + GS_A;
        #pragma unroll
        for (int i = 0; i < 4; i++) {
            int id = tid + i * 256;
            int ar = id >> 3, ac = (id & 7) * 8;
            cp16g(&As[ar * 72 + ac], &A[(size_t)(m0 + ar) * K + k0 + ac]);
            int br = id >> 4, bc = (id & 15) * 8;
            cp16g(&Bs[br * 136 + bc], &W[(size_t)(k0 + br) * N + n0 + bc]);
        }
    };

    const int ntiles = K / 64;
    load_tile(0, 0); cp_commit();
    load_tile(1, 1); cp_commit();
    cp_wait1();
    __syncthreads();

    for (int kt = 0; kt < ntiles; kt++) {
        const int cur = kt % 3;
        if (kt + 2 < ntiles) load_tile(kt + 2, (kt + 2) % 3);
        cp_commit();

        const uint32_t abase = sbase + (uint32_t)(cur * GSTG) * 2;
        const uint32_t bbase = abase + (uint32_t)GS_A * 2;

        #pragma unroll
        for (int ks = 0; ks < 4; ks++) {
            uint32_t af[4][4];
            #pragma unroll
            for (int mt = 0; mt < 4; mt++) {
                uint32_t addr = abase +
                    (uint32_t)(((wm + mt * 16 + a_row) * 72 + ks * 16 + a_col) << 1);
                ldsm4(af[mt][0], af[mt][1], af[mt][2], af[mt][3], addr);
            }
            uint32_t bf[8];
            #pragma unroll
            for (int n2 = 0; n2 < 2; n2++) {
                uint32_t addr = bbase +
                    (uint32_t)(((ks * 16 + b_row) * 136 + wn + n2 * 16 + b_col) << 1);
                ldsm4t(bf[n2*4], bf[n2*4+1], bf[n2*4+2], bf[n2*4+3], addr);
            }
            #pragma unroll
            for (int mt = 0; mt < 4; mt++)
                #pragma unroll
                for (int nt = 0; nt < 4; nt++)
                    mma16(acc[mt][nt], af[mt][0], af[mt][1], af[mt][2], af[mt][3],
                          bf[nt*2], bf[nt*2+1]);
        }

        cp_wait1();
        __syncthreads();
    }

    if (Ch) {
        #pragma unroll
        for (int mt = 0; mt < 4; mt++) {
            int row = m0 + wm + mt * 16 + g;
            #pragma unroll
            for (int nt = 0; nt < 4; nt++) {
                int col = n0 + wn + nt * 8 + 2 * t;
                *(__half2*)&Ch[(size_t)row * N + col] =
                    __floats2half2_rn(acc[mt][nt][0] * oscale, acc[mt][nt][1] * oscale);
                *(__half2*)&Ch[(size_t)(row + 8) * N + col] =
                    __floats2half2_rn(acc[mt][nt][2] * oscale, acc[mt][nt][3] * oscale);
            }
        }
    } else {
        #pragma unroll
        for (int mt = 0; mt < 4; mt++) {
            int row = m0 + wm + mt * 16 + g;
            #pragma unroll
            for (int nt = 0; nt < 4; nt++) {
                int col = n0 + wn + nt * 8 + 2 * t;
                float2 r01 = { acc[mt][nt][0], acc[mt][nt][1] };
                float2 r23 = { acc[mt][nt][2], acc[mt][nt][3] };
                if (bias) {
                    float2 bb = *(const float2*)&bias[col];
                    r01.x += bb.x; r01.y += bb.y;
                    r23.x += bb.x; r23.y += bb.y;
                }
                if (resid) {
                    float2 e0 = *(const float2*)&resid[(size_t)row * N + col];
                    float2 e1 = *(const float2*)&resid[(size_t)(row + 8) * N + col];
                    r01.x += e0.x; r01.y += e0.y;
                    r23.x += e1.x; r23.y += e1.y;
                }
                *(float2*)&Cf[(size_t)row * N + col]       = r01;
                *(float2*)&Cf[(size_t)(row + 8) * N + col] = r23;
            }
        }
    }
}

// ---------------------------------------------------------------------------
// fp16 flash attention, FA2 register-P path: S accumulator fragments are
// repacked directly into PV A-operand fragments (no P smem round-trip).
// 128 q-rows/CTA, 8 warps x 16 rows, 64-key chunks, 3-stage cp.async K/V.
// ---------------------------------------------------------------------------
#define KVSTG 4608                           // 64*72 halves per buffer
#define ATTN_SMEM ((6*KVSTG + 128*72) * 2)   // 73728 bytes

__global__ __launch_bounds__(256, 2) void attn_h(
    const __half* __restrict__ Qg, const __half* __restrict__ Kg,
    const __half* __restrict__ Vg, __half* __restrict__ Og)
{
    extern __shared__ __half smh[];
    __half* KsB = smh;                  // [3][64][72]
    __half* VsB = smh + 3 * KVSTG;      // [3][64][72]
    __half* Qs  = smh + 6 * KVSTG;      // [128][72] (Q staging only)
    const uint32_t ksbase = (uint32_t)__cvta_generic_to_shared(KsB);
    const uint32_t vsbase = (uint32_t)__cvta_generic_to_shared(VsB);
    const uint32_t qsbase = (uint32_t)__cvta_generic_to_shared(Qs);

    const int tid  = threadIdx.x;
    const int lane = tid & 31, warp = tid >> 5;
    const int g = lane >> 2, t = lane & 3;
    const int Rr = warp * 16;
    const int it = blockIdx.x, h = blockIdx.y, b = blockIdx.z;

    const __half* qb = Qg + ((size_t)b * NN + it * 128) * INNER + h * DH;
    const __half* kb = Kg + (size_t)b * MM * INNER + h * DH;
    const __half* vb = Vg + (size_t)b * MM * INNER + h * DH;

    const int a_row = lane & 15, a_col = (lane >> 4) * 8;
    const int k_row = (lane & 7) + ((lane >> 4) & 1) * 8;
    const int k_col = ((lane >> 3) & 1) * 8;
    const int v_row = (lane & 7) + ((lane >> 3) & 1) * 8;
    const int v_col = ((lane >> 4) & 1) * 8;

    auto load_chunk = [&](int buf, int j0) {
        __half* Ks = KsB + buf * KVSTG;
        __half* Vs = VsB + buf * KVSTG;
        #pragma unroll
        for (int i = 0; i < 2; i++) {
            int id = tid + i * 256;
            int r = id >> 3, c = (id & 7) * 8;
            cp16g(&Ks[r * 72 + c], &kb[(size_t)(j0 + r) * INNER + c]);
            cp16g(&Vs[r * 72 + c], &vb[(size_t)(j0 + r) * INNER + c]);
        }
    };

    // stage Q + prologue chunks
    #pragma unroll
    for (int i = 0; i < 4; i++) {
        int id = tid + i * 256;
        int r = id >> 3, c = (id & 7) * 8;
        cp16g(&Qs[r * 72 + c], &qb[(size_t)r * INNER + c]);
    }
    load_chunk(0, 0);
    cp_commit();                 // group A: Q + chunk0
    load_chunk(1, 64);
    cp_commit();                 // group B: chunk1
    cp_wait1();                  // group A done
    __syncthreads();

    uint32_t qf[4][4];
    #pragma unroll
    for (int ks = 0; ks < 4; ks++) {
        uint32_t addr = qsbase + (uint32_t)(((Rr + a_row) * 72 + ks * 16 + a_col) << 1);
        ldsm4(qf[ks][0], qf[ks][1], qf[ks][2], qf[ks][3], addr);
    }

    float of[8][4];
    #pragma unroll
    for (int i = 0; i < 8; i++)
        #pragma unroll
        for (int q = 0; q < 4; q++) of[i][q] = 0.f;
    float m0r = -INFINITY, m1r = -INFINITY, l0 = 0.f, l1 = 0.f;

    const int nch = MM / 64;
    for (int ch = 0; ch < nch; ch++) {
        const int cur = ch % 3;
        if (ch + 2 < nch) load_chunk((ch + 2) % 3, (ch + 2) * 64);
        cp_commit();

        // S = Q K^T  (Q pre-scaled by 1/sqrt(dh))
        float sacc[8][4];
        #pragma unroll
        for (int i = 0; i < 8; i++)
            #pragma unroll
            for (int q = 0; q < 4; q++) sacc[i][q] = 0.f;
        const uint32_t kbase = ksbase + (uint32_t)(cur * KVSTG) * 2;
        #pragma unroll
        for (int ks = 0; ks < 4; ks++) {
            #pragma unroll
            for (int n2 = 0; n2 < 4; n2++) {
                uint32_t kf0, kf1, kf2, kf3;
                uint32_t addr = kbase +
                    (uint32_t)(((n2 * 16 + k_row) * 72 + ks * 16 + k_col) << 1);
                ldsm4(kf0, kf1, kf2, kf3, addr);
                mma16(sacc[n2*2],   qf[ks][0], qf[ks][1], qf[ks][2], qf[ks][3], kf0, kf1);
                mma16(sacc[n2*2+1], qf[ks][0], qf[ks][1], qf[ks][2], qf[ks][3], kf2, kf3);
            }
        }

        // online softmax
        float rmax0 = -INFINITY, rmax1 = -INFINITY;
        #pragma unroll
        for (int nt = 0; nt < 8; nt++) {
            rmax0 = fmaxf(rmax0, fmaxf(sacc[nt][0], sacc[nt][1]));
            rmax1 = fmaxf(rmax1, fmaxf(sacc[nt][2], sacc[nt][3]));
        }
        rmax0 = fmaxf(rmax0, __shfl_xor_sync(0xffffffffu, rmax0, 1));
        rmax0 = fmaxf(rmax0, __shfl_xor_sync(0xffffffffu, rmax0, 2));
        rmax1 = fmaxf(rmax1, __shfl_xor_sync(0xffffffffu, rmax1, 1));
        rmax1 = fmaxf(rmax1, __shfl_xor_sync(0xffffffffu, rmax1, 2));
        float mn0 = fmaxf(m0r, rmax0), mn1 = fmaxf(m1r, rmax1);
        float c0 = __expf(m0r - mn0), c1 = __expf(m1r - mn1);
        m0r = mn0; m1r = mn1;

        // exponentiate + pack P directly into PV A-fragments (FA2 layout):
        // k-group ks covers keys 16ks..16ks+15 = n-tiles 2ks (a0,a1) and 2ks+1 (a2,a3)
        uint32_t pf[4][4];
        float rs0 = 0.f, rs1 = 0.f;
        #pragma unroll
        for (int ks = 0; ks < 4; ks++) {
            #pragma unroll
            for (int half = 0; half < 2; half++) {
                const int nt = 2 * ks + half;
                float p0 = __expf(sacc[nt][0] - mn0);
                float p1 = __expf(sacc[nt][1] - mn0);
                float p2 = __expf(sacc[nt][2] - mn1);
                float p3 = __expf(sacc[nt][3] - mn1);
                rs0 += p0 + p1; rs1 += p2 + p3;
                pf[ks][2*half]   = h2_as_u32(__floats2half2_rn(p0, p1)); // row g
                pf[ks][2*half+1] = h2_as_u32(__floats2half2_rn(p2, p3)); // row g+8
            }
        }
        rs0 += __shfl_xor_sync(0xffffffffu, rs0, 1);
        rs0 += __shfl_xor_sync(0xffffffffu, rs0, 2);
        rs1 += __shfl_xor_sync(0xffffffffu, rs1, 1);
        rs1 += __shfl_xor_sync(0xffffffffu, rs1, 2);
        l0 = l0 * c0 + rs0;
        l1 = l1 * c1 + rs1;
        #pragma unroll
        for (int nt = 0; nt < 8; nt++) {
            of[nt][0] *= c0; of[nt][1] *= c0;
            of[nt][2] *= c1; of[nt][3] *= c1;
        }

        // O += P @ V (P from registers)
        const uint32_t vbase = vsbase + (uint32_t)(cur * KVSTG) * 2;
        #pragma unroll
        for (int ks = 0; ks < 4; ks++) {
            #pragma unroll
            for (int n2 = 0; n2 < 4; n2++) {
                uint32_t vf0, vf1, vf2, vf3;
                uint32_t addr = vbase +
                    (uint32_t)(((ks * 16 + v_row) * 72 + n2 * 16 + v_col) << 1);
                ldsm4t(vf0, vf1, vf2, vf3, addr);
                mma16(of[n2*2],   pf[ks][0], pf[ks][1], pf[ks][2], pf[ks][3], vf0, vf1);
                mma16(of[n2*2+1], pf[ks][0], pf[ks][1], pf[ks][2], pf[ks][3], vf2, vf3);
            }
        }

        cp_wait1();            // chunk ch+1 resident
        __syncthreads();
    }

    float inv0 = 1.f / l0, inv1 = 1.f / l1;
    int row0 = it * 128 + Rr + g, row1 = row0 + 8;
    #pragma unroll
    for (int nt = 0; nt < 8; nt++) {
        *(__half2*)&Og[((size_t)b * NN + row0) * INNER + h * DH + nt * 8 + 2 * t] =
            __floats2half2_rn(of[nt][0] * inv0, of[nt][1] * inv0);
        *(__half2*)&Og[((size_t)b * NN + row1) * INNER + h * DH + nt * 8 + 2 * t] =
            __floats2half2_rn(of[nt][2] * inv1, of[nt][3] * inv1);
    }
}

// ---------------------------------------------------------------------------
// Launch
// ---------------------------------------------------------------------------
extern "C" void kernel_launch(void* const* d_in, const int* in_sizes, int n_in,
                              void* d_out, int out_size)
{
    (void)in_sizes; (void)n_in; (void)out_size;
    const float* x     = (const float*)d_in[0];
    const float* cond  = (const float*)d_in[1];
    const float* lnx_g = (const float*)d_in[2];
    const float* lnx_b = (const float*)d_in[3];
    const float* lnc_g = (const float*)d_in[4];
    const float* lnc_b = (const float*)d_in[5];
    const float* Wq    = (const float*)d_in[6];
    const float* Wk    = (const float*)d_in[7];
    const float* Wv    = (const float*)d_in[8];
    const float* Wo    = (const float*)d_in[9];
    const float* bo    = (const float*)d_in[10];
    const float* lnf_g = (const float*)d_in[11];
    const float* lnf_b = (const float*)d_in[12];
    float* out = (float*)d_out;

    __half *xn, *cn, *q, *k, *v, *ao, *wq, *wk, *wv, *wo;
    float *y;
    cudaGetSymbolAddress((void**)&xn, g_xn);
    cudaGetSymbolAddress((void**)&cn, g_cn);
    cudaGetSymbolAddress((void**)&q,  g_q);
    cudaGetSymbolAddress((void**)&k,  g_k);
    cudaGetSymbolAddress((void**)&v,  g_v);
    cudaGetSymbolAddress((void**)&ao, g_ao);
    cudaGetSymbolAddress((void**)&y,  g_y);
    cudaGetSymbolAddress((void**)&wq, g_wq);
    cudaGetSymbolAddress((void**)&wk, g_wk);
    cudaGetSymbolAddress((void**)&wv, g_wv);
    cudaGetSymbolAddress((void**)&wo, g_wo);

    cudaFuncSetAttribute(gemm_h, cudaFuncAttributeMaxDynamicSharedMemorySize, GEMM_SMEM);
    cudaFuncSetAttribute(attn_h, cudaFuncAttributeMaxDynamicSharedMemorySize, ATTN_SMEM);

    f2h_all_kernel<<<(N4_TOT + 255)/256, 256>>>((const float4*)Wq, (const float4*)Wk,
                                                (const float4*)Wv, (const float4*)Wo);

    ln_kernel<DQ, true><<<BB * NN, 128>>>(x, lnx_g, lnx_b, xn);
    ln_kernel<DC, true><<<BB * MM, 128>>>(cond, lnc_g, lnc_b, cn);

    dim3 gthr(256);
    dim3 gp(INNER / 128, (BB * NN) / 128);
    gemm_h<<<gp, gthr, GEMM_SMEM>>>(xn, wq, q, nullptr, DQ, INNER, 0.125f, nullptr, nullptr);
    gemm_h<<<gp, gthr, GEMM_SMEM>>>(cn, wk, k, nullptr, DC, INNER, 1.0f, nullptr, nullptr);
    gemm_h<<<gp, gthr, GEMM_SMEM>>>(cn, wv, v, nullptr, DC, INNER, 1.0f, nullptr, nullptr);

    dim3 ga(NN / 128, HH, BB);
    attn_h<<<ga, gthr, ATTN_SMEM>>>(q, k, v, ao);

    dim3 go(DQ / 128, (BB * NN) / 128);
    gemm_h<<<go, gthr, GEMM_SMEM>>>(ao, wo, nullptr, y, INNER, DQ, 1.0f, bo, x);

    ln_kernel<DQ, false><<<BB * NN, 128>>>(y, lnf_g, lnf_b, out);
}

// round 10
// speedup vs baseline: 6.6837x; 1.0124x over previous
#include <cuda_runtime.h>
#include <cuda_fp16.h>
#include <math.h>
#include <stdint.h>

#define BB 4
#define NN 2048
#define MM 2048
#define DQ 512
#define DC 768
#define HH 8
#define DH 64
#define INNER 512

// 0.125 * log2(e): folds both the attention scale and the base-2 exp domain
// into the Q projection output.
#define QSCALE 0.18033688011112042f

// ---------------------------------------------------------------------------
// Scratch (device globals -- no allocation allowed)
// ---------------------------------------------------------------------------
__device__ __half g_xn[BB*NN*DQ];
__device__ __half g_cn[BB*MM*DC];
__device__ __half g_q [BB*NN*INNER];
__device__ __half g_k [BB*MM*INNER];
__device__ __half g_v [BB*MM*INNER];
__device__ __half g_ao[BB*NN*INNER];
__device__ float  g_y [BB*NN*DQ];
__device__ __half g_wq[DQ*INNER];
__device__ __half g_wk[DC*INNER];
__device__ __half g_wv[DC*INNER];
__device__ __half g_wo[INNER*DQ];

// ---------------------------------------------------------------------------
// PTX helpers
// ---------------------------------------------------------------------------
__device__ __forceinline__ uint32_t h2_as_u32(__half2 h) {
    return *reinterpret_cast<uint32_t*>(&h);
}
__device__ __forceinline__ void cp16g(void* dst_smem, const void* src) {
    uint32_t d = (uint32_t)__cvta_generic_to_shared(dst_smem);
    asm volatile("cp.async.cg.shared.global [%0], [%1], 16;" :: "r"(d), "l"(src));
}
__device__ __forceinline__ void cp_commit() {
    asm volatile("cp.async.commit_group;" ::: "memory");
}
__device__ __forceinline__ void cp_wait1() {
    asm volatile("cp.async.wait_group 1;" ::: "memory");
}
__device__ __forceinline__ void ldsm4(uint32_t& r0, uint32_t& r1, uint32_t& r2, uint32_t& r3, uint32_t a) {
    asm volatile("ldmatrix.sync.aligned.m8n8.x4.shared.b16 {%0,%1,%2,%3}, [%4];"
                 : "=r"(r0), "=r"(r1), "=r"(r2), "=r"(r3) : "r"(a));
}
__device__ __forceinline__ void ldsm4t(uint32_t& r0, uint32_t& r1, uint32_t& r2, uint32_t& r3, uint32_t a) {
    asm volatile("ldmatrix.sync.aligned.m8n8.x4.trans.shared.b16 {%0,%1,%2,%3}, [%4];"
                 : "=r"(r0), "=r"(r1), "=r"(r2), "=r"(r3) : "r"(a));
}
__device__ __forceinline__ void mma16(float* c, uint32_t a0, uint32_t a1, uint32_t a2, uint32_t a3,
                                      uint32_t b0, uint32_t b1) {
    asm volatile(
        "mma.sync.aligned.m16n8k16.row.col.f32.f16.f16.f32 "
        "{%0,%1,%2,%3},{%4,%5,%6,%7},{%8,%9},{%0,%1,%2,%3};"
        : "+f"(c[0]), "+f"(c[1]), "+f"(c[2]), "+f"(c[3])
        : "r"(a0), "r"(a1), "r"(a2), "r"(a3), "r"(b0), "r"(b1));
}

// ---------------------------------------------------------------------------
// fp32 -> fp16: all four weight matrices in one launch
// ---------------------------------------------------------------------------
#define N4_WQ (DQ*INNER/4)
#define N4_WK (DC*INNER/4)
#define N4_WV (DC*INNER/4)
#define N4_WO (INNER*DQ/4)
#define N4_TOT (N4_WQ + N4_WK + N4_WV + N4_WO)

__global__ void f2h_all_kernel(const float4* __restrict__ wq, const float4* __restrict__ wk,
                               const float4* __restrict__ wv, const float4* __restrict__ wo)
{
    int i = blockIdx.x * blockDim.x + threadIdx.x;
    if (i >= N4_TOT) return;
    const float4* src;
    __half2* dst;
    int j = i;
    if (j < N4_WQ)                { src = wq; dst = (__half2*)g_wq; }
    else if ((j -= N4_WQ) < N4_WK) { src = wk; dst = (__half2*)g_wk; }
    else if ((j -= N4_WK) < N4_WV) { src = wv; dst = (__half2*)g_wv; }
    else { j -= N4_WV;              src = wo; dst = (__half2*)g_wo; }
    float4 v = src[j];
    dst[2*j]   = __floats2half2_rn(v.x, v.y);
    dst[2*j+1] = __floats2half2_rn(v.z, v.w);
}

// ---------------------------------------------------------------------------
// LayerNorm (fp32 in; fp16 or fp32 out)
// ---------------------------------------------------------------------------
template<int D, bool HALF>
__global__ void ln_kernel(const float* __restrict__ in,
                          const float* __restrict__ gw,
                          const float* __restrict__ bw,
                          void* __restrict__ outp)
{
    const int row = blockIdx.x;
    const float4* x4 = (const float4*)(in + (size_t)row * D);

    float s = 0.f, sq = 0.f;
    for (int i = threadIdx.x; i < D / 4; i += blockDim.x) {
        float4 v = x4[i];
        s  += v.x + v.y + v.z + v.w;
        sq += v.x * v.x + v.y * v.y + v.z * v.z + v.w * v.w;
    }
    __shared__ float red0[8], red1[8];
    #pragma unroll
    for (int off = 16; off; off >>= 1) {
        s  += __shfl_xor_sync(0xffffffffu, s,  off);
        sq += __shfl_xor_sync(0xffffffffu, sq, off);
    }
    int wid = threadIdx.x >> 5, lid = threadIdx.x & 31;
    if (lid == 0) { red0[wid] = s; red1[wid] = sq; }
    __syncthreads();
    int nw = blockDim.x >> 5;
    if (wid == 0) {
        s  = (lid < nw) ? red0[lid] : 0.f;
        sq = (lid < nw) ? red1[lid] : 0.f;
        #pragma unroll
        for (int off = 4; off; off >>= 1) {
            s  += __shfl_xor_sync(0xffffffffu, s,  off);
            sq += __shfl_xor_sync(0xffffffffu, sq, off);
        }
        if (lid == 0) { red0[0] = s; red1[0] = sq; }
    }
    __syncthreads();
    const float mu   = red0[0] * (1.0f / D);
    const float var  = red1[0] * (1.0f / D) - mu * mu;
    const float rstd = rsqrtf(var + 1e-5f);
    const float4* g4 = (const float4*)gw;
    const float4* b4 = (const float4*)bw;
    for (int i = threadIdx.x; i < D / 4; i += blockDim.x) {
        float4 v = x4[i], g = g4[i], b = b4[i], r;
        r.x = (v.x - mu) * rstd * g.x + b.x;
        r.y = (v.y - mu) * rstd * g.y + b.y;
        r.z = (v.z - mu) * rstd * g.z + b.z;
        r.w = (v.w - mu) * rstd * g.w + b.w;
        if (HALF) {
            __half2* o2 = (__half2*)outp + (size_t)row * (D / 2);
            o2[2*i]   = __floats2half2_rn(r.x, r.y);
            o2[2*i+1] = __floats2half2_rn(r.z, r.w);
        } else {
            float4* o4 = (float4*)outp + (size_t)row * (D / 4);
            o4[i] = r;
        }
    }
}

// ---------------------------------------------------------------------------
// GEMM tile config shared by both gemm kernels
// ---------------------------------------------------------------------------
#define GS_A 9216                      // 128*72 halves
#define GS_B 8704                      // 64*136 halves
#define GSTG (GS_A + GS_B)             // 17920 halves / stage
#define GEMM_SMEM (3 * GSTG * 2)       // 107520 bytes

// Shared mainloop body as a macro-free inline: implemented per-kernel to keep
// ptxas scheduling simple.

// ---------------------------------------------------------------------------
// Merged Q/K/V projection: one launch, grid.z selects {Q,K,V}.
// All operands are device globals; fp16 output scaled by per-z factor.
// ---------------------------------------------------------------------------
__global__ __launch_bounds__(256, 2) void qkv_gemm()
{
    extern __shared__ __half smh[];
    const uint32_t sbase = (uint32_t)__cvta_generic_to_shared(smh);

    const __half* A; const __half* W; __half* C; int K; float osc;
    if (blockIdx.z == 0)      { A = g_xn; W = g_wq; C = g_q; K = DQ; osc = QSCALE; }
    else if (blockIdx.z == 1) { A = g_cn; W = g_wk; C = g_k; K = DC; osc = 1.0f; }
    else                      { A = g_cn; W = g_wv; C = g_v; K = DC; osc = 1.0f; }

    const int tid = threadIdx.x;
    const int lane = tid & 31, warp = tid >> 5;
    const int wm = (warp >> 2) * 64;
    const int wn = (warp & 3) * 32;
    const int m0 = blockIdx.y * 128;
    const int n0 = blockIdx.x * 128;
    const int g = lane >> 2, t = lane & 3;

    const int a_row = lane & 15, a_col = (lane >> 4) * 8;
    const int b_row = (lane & 7) + ((lane >> 3) & 1) * 8;
    const int b_col = ((lane >> 4) & 1) * 8;

    float acc[4][4][4];
    #pragma unroll
    for (int i = 0; i < 4; i++)
        #pragma unroll
        for (int j = 0; j < 4; j++)
            #pragma unroll
            for (int q = 0; q < 4; q++) acc[i][j][q] = 0.f;

    auto load_tile = [&](int kt, int buf) {
        int k0 = kt * 64;
        __half* As = smh + buf * GSTG;
        __half* Bs = smh + buf * GSTG + GS_A;
        #pragma unroll
        for (int i = 0; i < 4; i++) {
            int id = tid + i * 256;
            int ar = id >> 3, ac = (id & 7) * 8;
            cp16g(&As[ar * 72 + ac], &A[(size_t)(m0 + ar) * K + k0 + ac]);
            int br = id >> 4, bc = (id & 15) * 8;
            cp16g(&Bs[br * 136 + bc], &W[(size_t)(k0 + br) * INNER + n0 + bc]);
        }
    };

    const int ntiles = K / 64;
    load_tile(0, 0); cp_commit();
    load_tile(1, 1); cp_commit();
    cp_wait1();
    __syncthreads();

    for (int kt = 0; kt < ntiles; kt++) {
        const int cur = kt % 3;
        if (kt + 2 < ntiles) load_tile(kt + 2, (kt + 2) % 3);
        cp_commit();

        const uint32_t abase = sbase + (uint32_t)(cur * GSTG) * 2;
        const uint32_t bbase = abase + (uint32_t)GS_A * 2;

        #pragma unroll
        for (int ks = 0; ks < 4; ks++) {
            uint32_t af[4][4];
            #pragma unroll
            for (int mt = 0; mt < 4; mt++) {
                uint32_t addr = abase +
                    (uint32_t)(((wm + mt * 16 + a_row) * 72 + ks * 16 + a_col) << 1);
                ldsm4(af[mt][0], af[mt][1], af[mt][2], af[mt][3], addr);
            }
            uint32_t bf[8];
            #pragma unroll
            for (int n2 = 0; n2 < 2; n2++) {
                uint32_t addr = bbase +
                    (uint32_t)(((ks * 16 + b_row) * 136 + wn + n2 * 16 + b_col) << 1);
                ldsm4t(bf[n2*4], bf[n2*4+1], bf[n2*4+2], bf[n2*4+3], addr);
            }
            #pragma unroll
            for (int mt = 0; mt < 4; mt++)
                #pragma unroll
                for (int nt = 0; nt < 4; nt++)
                    mma16(acc[mt][nt], af[mt][0], af[mt][1], af[mt][2], af[mt][3],
                          bf[nt*2], bf[nt*2+1]);
        }

        cp_wait1();
        __syncthreads();
    }

    #pragma unroll
    for (int mt = 0; mt < 4; mt++) {
        int row = m0 + wm + mt * 16 + g;
        #pragma unroll
        for (int nt = 0; nt < 4; nt++) {
            int col = n0 + wn + nt * 8 + 2 * t;
            *(__half2*)&C[(size_t)row * INNER + col] =
                __floats2half2_rn(acc[mt][nt][0] * osc, acc[mt][nt][1] * osc);
            *(__half2*)&C[(size_t)(row + 8) * INNER + col] =
                __floats2half2_rn(acc[mt][nt][2] * osc, acc[mt][nt][3] * osc);
        }
    }
}

// ---------------------------------------------------------------------------
// O-projection GEMM (fp32 out + bias + residual)
// ---------------------------------------------------------------------------
__global__ __launch_bounds__(256, 2) void gemm_o(
    const float* __restrict__ bias, const float* __restrict__ resid)
{
    extern __shared__ __half smh[];
    const uint32_t sbase = (uint32_t)__cvta_generic_to_shared(smh);
    const __half* A = g_ao;
    const __half* W = g_wo;
    float* Cf = g_y;
    const int K = INNER, N = DQ;

    const int tid = threadIdx.x;
    const int lane = tid & 31, warp = tid >> 5;
    const int wm = (warp >> 2) * 64;
    const int wn = (warp & 3) * 32;
    const int m0 = blockIdx.y * 128;
    const int n0 = blockIdx.x * 128;
    const int g = lane >> 2, t = lane & 3;

    const int a_row = lane & 15, a_col = (lane >> 4) * 8;
    const int b_row = (lane & 7) + ((lane >> 3) & 1) * 8;
    const int b_col = ((lane >> 4) & 1) * 8;

    float acc[4][4][4];
    #pragma unroll
    for (int i = 0; i < 4; i++)
        #pragma unroll
        for (int j = 0; j < 4; j++)
            #pragma unroll
            for (int q = 0; q < 4; q++) acc[i][j][q] = 0.f;

    auto load_tile = [&](int kt, int buf) {
        int k0 = kt * 64;
        __half* As = smh + buf * GSTG;
        __half* Bs = smh + buf * GSTG + GS_A;
        #pragma unroll
        for (int i = 0; i < 4; i++) {
            int id = tid + i * 256;
            int ar = id >> 3, ac = (id & 7) * 8;
            cp16g(&As[ar * 72 + ac], &A[(size_t)(m0 + ar) * K + k0 + ac]);
            int br = id >> 4, bc = (id & 15) * 8;
            cp16g(&Bs[br * 136 + bc], &W[(size_t)(k0 + br) * N + n0 + bc]);
        }
    };

    const int ntiles = K / 64;
    load_tile(0, 0); cp_commit();
    load_tile(1, 1); cp_commit();
    cp_wait1();
    __syncthreads();

    for (int kt = 0; kt < ntiles; kt++) {
        const int cur = kt % 3;
        if (kt + 2 < ntiles) load_tile(kt + 2, (kt + 2) % 3);
        cp_commit();

        const uint32_t abase = sbase + (uint32_t)(cur * GSTG) * 2;
        const uint32_t bbase = abase + (uint32_t)GS_A * 2;

        #pragma unroll
        for (int ks = 0; ks < 4; ks++) {
            uint32_t af[4][4];
            #pragma unroll
            for (int mt = 0; mt < 4; mt++) {
                uint32_t addr = abase +
                    (uint32_t)(((wm + mt * 16 + a_row) * 72 + ks * 16 + a_col) << 1);
                ldsm4(af[mt][0], af[mt][1], af[mt][2], af[mt][3], addr);
            }
            uint32_t bf[8];
            #pragma unroll
            for (int n2 = 0; n2 < 2; n2++) {
                uint32_t addr = bbase +
                    (uint32_t)(((ks * 16 + b_row) * 136 + wn + n2 * 16 + b_col) << 1);
                ldsm4t(bf[n2*4], bf[n2*4+1], bf[n2*4+2], bf[n2*4+3], addr);
            }
            #pragma unroll
            for (int mt = 0; mt < 4; mt++)
                #pragma unroll
                for (int nt = 0; nt < 4; nt++)
                    mma16(acc[mt][nt], af[mt][0], af[mt][1], af[mt][2], af[mt][3],
                          bf[nt*2], bf[nt*2+1]);
        }

        cp_wait1();
        __syncthreads();
    }

    #pragma unroll
    for (int mt = 0; mt < 4; mt++) {
        int row = m0 + wm + mt * 16 + g;
        #pragma unroll
        for (int nt = 0; nt < 4; nt++) {
            int col = n0 + wn + nt * 8 + 2 * t;
            float2 r01 = { acc[mt][nt][0], acc[mt][nt][1] };
            float2 r23 = { acc[mt][nt][2], acc[mt][nt][3] };
            float2 bb = *(const float2*)&bias[col];
            r01.x += bb.x; r01.y += bb.y;
            r23.x += bb.x; r23.y += bb.y;
            float2 e0 = *(const float2*)&resid[(size_t)row * N + col];
            float2 e1 = *(const float2*)&resid[(size_t)(row + 8) * N + col];
            r01.x += e0.x; r01.y += e0.y;
            r23.x += e1.x; r23.y += e1.y;
            *(float2*)&Cf[(size_t)row * N + col]       = r01;
            *(float2*)&Cf[(size_t)(row + 8) * N + col] = r23;
        }
    }
}

// ---------------------------------------------------------------------------
// fp16 flash attention, FA2 register-P, base-2 softmax with h2exp2 (f16x2
// MUFU): Q arrives pre-scaled by 0.125*log2(e), so S is in log2 domain.
// ---------------------------------------------------------------------------
#define KVSTG 4608                           // 64*72 halves per buffer
#define ATTN_SMEM ((6*KVSTG + 128*72) * 2)   // 73728 bytes

__global__ __launch_bounds__(256, 2) void attn_h(
    const __half* __restrict__ Qg, const __half* __restrict__ Kg,
    const __half* __restrict__ Vg, __half* __restrict__ Og)
{
    extern __shared__ __half smh[];
    __half* KsB = smh;                  // [3][64][72]
    __half* VsB = smh + 3 * KVSTG;      // [3][64][72]
    __half* Qs  = smh + 6 * KVSTG;      // [128][72] (Q staging only)
    const uint32_t ksbase = (uint32_t)__cvta_generic_to_shared(KsB);
    const uint32_t vsbase = (uint32_t)__cvta_generic_to_shared(VsB);
    const uint32_t qsbase = (uint32_t)__cvta_generic_to_shared(Qs);

    const int tid  = threadIdx.x;
    const int lane = tid & 31, warp = tid >> 5;
    const int g = lane >> 2, t = lane & 3;
    const int Rr = warp * 16;
    const int it = blockIdx.x, h = blockIdx.y, b = blockIdx.z;

    const __half* qb = Qg + ((size_t)b * NN + it * 128) * INNER + h * DH;
    const __half* kb = Kg + (size_t)b * MM * INNER + h * DH;
    const __half* vb = Vg + (size_t)b * MM * INNER + h * DH;

    const int a_row = lane & 15, a_col = (lane >> 4) * 8;
    const int k_row = (lane & 7) + ((lane >> 4) & 1) * 8;
    const int k_col = ((lane >> 3) & 1) * 8;
    const int v_row = (lane & 7) + ((lane >> 3) & 1) * 8;
    const int v_col = ((lane >> 4) & 1) * 8;

    auto load_chunk = [&](int buf, int j0) {
        __half* Ks = KsB + buf * KVSTG;
        __half* Vs = VsB + buf * KVSTG;
        #pragma unroll
        for (int i = 0; i < 2; i++) {
            int id = tid + i * 256;
            int r = id >> 3, c = (id & 7) * 8;
            cp16g(&Ks[r * 72 + c], &kb[(size_t)(j0 + r) * INNER + c]);
            cp16g(&Vs[r * 72 + c], &vb[(size_t)(j0 + r) * INNER + c]);
        }
    };

    // stage Q + prologue chunks
    #pragma unroll
    for (int i = 0; i < 4; i++) {
        int id = tid + i * 256;
        int r = id >> 3, c = (id & 7) * 8;
        cp16g(&Qs[r * 72 + c], &qb[(size_t)r * INNER + c]);
    }
    load_chunk(0, 0);
    cp_commit();                 // group A: Q + chunk0
    load_chunk(1, 64);
    cp_commit();                 // group B: chunk1
    cp_wait1();                  // group A done
    __syncthreads();

    uint32_t qf[4][4];
    #pragma unroll
    for (int ks = 0; ks < 4; ks++) {
        uint32_t addr = qsbase + (uint32_t)(((Rr + a_row) * 72 + ks * 16 + a_col) << 1);
        ldsm4(qf[ks][0], qf[ks][1], qf[ks][2], qf[ks][3], addr);
    }

    float of[8][4];
    #pragma unroll
    for (int i = 0; i < 8; i++)
        #pragma unroll
        for (int q = 0; q < 4; q++) of[i][q] = 0.f;
    float m0r = -INFINITY, m1r = -INFINITY, l0 = 0.f, l1 = 0.f;

    const int nch = MM / 64;
    for (int ch = 0; ch < nch; ch++) {
        const int cur = ch % 3;
        if (ch + 2 < nch) load_chunk((ch + 2) % 3, (ch + 2) * 64);
        cp_commit();

        // S = Q K^T  (log2-domain: Q pre-scaled by 0.125*log2e)
        float sacc[8][4];
        #pragma unroll
        for (int i = 0; i < 8; i++)
            #pragma unroll
            for (int q = 0; q < 4; q++) sacc[i][q] = 0.f;
        const uint32_t kbase = ksbase + (uint32_t)(cur * KVSTG) * 2;
        #pragma unroll
        for (int ks = 0; ks < 4; ks++) {
            #pragma unroll
            for (int n2 = 0; n2 < 4; n2++) {
                uint32_t kf0, kf1, kf2, kf3;
                uint32_t addr = kbase +
                    (uint32_t)(((n2 * 16 + k_row) * 72 + ks * 16 + k_col) << 1);
                ldsm4(kf0, kf1, kf2, kf3, addr);
                mma16(sacc[n2*2],   qf[ks][0], qf[ks][1], qf[ks][2], qf[ks][3], kf0, kf1);
                mma16(sacc[n2*2+1], qf[ks][0], qf[ks][1], qf[ks][2], qf[ks][3], kf2, kf3);
            }
        }

        // online softmax (base-2)
        float rmax0 = -INFINITY, rmax1 = -INFINITY;
        #pragma unroll
        for (int nt = 0; nt < 8; nt++) {
            rmax0 = fmaxf(rmax0, fmaxf(sacc[nt][0], sacc[nt][1]));
            rmax1 = fmaxf(rmax1, fmaxf(sacc[nt][2], sacc[nt][3]));
        }
        rmax0 = fmaxf(rmax0, __shfl_xor_sync(0xffffffffu, rmax0, 1));
        rmax0 = fmaxf(rmax0, __shfl_xor_sync(0xffffffffu, rmax0, 2));
        rmax1 = fmaxf(rmax1, __shfl_xor_sync(0xffffffffu, rmax1, 1));
        rmax1 = fmaxf(rmax1, __shfl_xor_sync(0xffffffffu, rmax1, 2));
        float mn0 = fmaxf(m0r, rmax0), mn1 = fmaxf(m1r, rmax1);
        float c0 = exp2f(m0r - mn0), c1 = exp2f(m1r - mn1);
        m0r = mn0; m1r = mn1;

        // exp2 in f16x2 (one MUFU per pair) -> directly the PV A-fragments
        uint32_t pf[4][4];
        float rs0 = 0.f, rs1 = 0.f;
        #pragma unroll
        for (int ks = 0; ks < 4; ks++) {
            #pragma unroll
            for (int half = 0; half < 2; half++) {
                const int nt = 2 * ks + half;
                __half2 e01 = h2exp2(__floats2half2_rn(sacc[nt][0] - mn0, sacc[nt][1] - mn0));
                __half2 e23 = h2exp2(__floats2half2_rn(sacc[nt][2] - mn1, sacc[nt][3] - mn1));
                pf[ks][2*half]   = h2_as_u32(e01);   // row g
                pf[ks][2*half+1] = h2_as_u32(e23);   // row g+8
                float2 f01 = __half22float2(e01);
                float2 f23 = __half22float2(e23);
                rs0 += f01.x + f01.y;
                rs1 += f23.x + f23.y;
            }
        }
        rs0 += __shfl_xor_sync(0xffffffffu, rs0, 1);
        rs0 += __shfl_xor_sync(0xffffffffu, rs0, 2);
        rs1 += __shfl_xor_sync(0xffffffffu, rs1, 1);
        rs1 += __shfl_xor_sync(0xffffffffu, rs1, 2);
        l0 = l0 * c0 + rs0;
        l1 = l1 * c1 + rs1;
        #pragma unroll
        for (int nt = 0; nt < 8; nt++) {
            of[nt][0] *= c0; of[nt][1] *= c0;
            of[nt][2] *= c1; of[nt][3] *= c1;
        }

        // O += P @ V (P from registers)
        const uint32_t vbase = vsbase + (uint32_t)(cur * KVSTG) * 2;
        #pragma unroll
        for (int ks = 0; ks < 4; ks++) {
            #pragma unroll
            for (int n2 = 0; n2 < 4; n2++) {
                uint32_t vf0, vf1, vf2, vf3;
                uint32_t addr = vbase +
                    (uint32_t)(((ks * 16 + v_row) * 72 + n2 * 16 + v_col) << 1);
                ldsm4t(vf0, vf1, vf2, vf3, addr);
                mma16(of[n2*2],   pf[ks][0], pf[ks][1], pf[ks][2], pf[ks][3], vf0, vf1);
                mma16(of[n2*2+1], pf[ks][0], pf[ks][1], pf[ks][2], pf[ks][3], vf2, vf3);
            }
        }

        cp_wait1();            // chunk ch+1 resident
        __syncthreads();
    }

    float inv0 = 1.f / l0, inv1 = 1.f / l1;
    int row0 = it * 128 + Rr + g, row1 = row0 + 8;
    #pragma unroll
    for (int nt = 0; nt < 8; nt++) {
        *(__half2*)&Og[((size_t)b * NN + row0) * INNER + h * DH + nt * 8 + 2 * t] =
            __floats2half2_rn(of[nt][0] * inv0, of[nt][1] * inv0);
        *(__half2*)&Og[((size_t)b * NN + row1) * INNER + h * DH + nt * 8 + 2 * t] =
            __floats2half2_rn(of[nt][2] * inv1, of[nt][3] * inv1);
    }
}

// ---------------------------------------------------------------------------
// Launch
// ---------------------------------------------------------------------------
extern "C" void kernel_launch(void* const* d_in, const int* in_sizes, int n_in,
                              void* d_out, int out_size)
{
    (void)in_sizes; (void)n_in; (void)out_size;
    const float* x     = (const float*)d_in[0];
    const float* cond  = (const float*)d_in[1];
    const float* lnx_g = (const float*)d_in[2];
    const float* lnx_b = (const float*)d_in[3];
    const float* lnc_g = (const float*)d_in[4];
    const float* lnc_b = (const float*)d_in[5];
    const float* Wq    = (const float*)d_in[6];
    const float* Wk    = (const float*)d_in[7];
    const float* Wv    = (const float*)d_in[8];
    const float* Wo    = (const float*)d_in[9];
    const float* bo    = (const float*)d_in[10];
    const float* lnf_g = (const float*)d_in[11];
    const float* lnf_b = (const float*)d_in[12];
    float* out = (float*)d_out;

    __half *xn, *cn, *q, *k, *v, *ao;
    float *y;
    cudaGetSymbolAddress((void**)&xn, g_xn);
    cudaGetSymbolAddress((void**)&cn, g_cn);
    cudaGetSymbolAddress((void**)&q,  g_q);
    cudaGetSymbolAddress((void**)&k,  g_k);
    cudaGetSymbolAddress((void**)&v,  g_v);
    cudaGetSymbolAddress((void**)&ao, g_ao);
    cudaGetSymbolAddress((void**)&y,  g_y);

    cudaFuncSetAttribute(qkv_gemm, cudaFuncAttributeMaxDynamicSharedMemorySize, GEMM_SMEM);
    cudaFuncSetAttribute(gemm_o,  cudaFuncAttributeMaxDynamicSharedMemorySize, GEMM_SMEM);
    cudaFuncSetAttribute(attn_h,  cudaFuncAttributeMaxDynamicSharedMemorySize, ATTN_SMEM);

    f2h_all_kernel<<<(N4_TOT + 255)/256, 256>>>((const float4*)Wq, (const float4*)Wk,
                                                (const float4*)Wv, (const float4*)Wo);

    ln_kernel<DQ, true><<<BB * NN, 128>>>(x, lnx_g, lnx_b, xn);
    ln_kernel<DC, true><<<BB * MM, 128>>>(cond, lnc_g, lnc_b, cn);

    dim3 gthr(256);
    qkv_gemm<<<dim3(INNER / 128, (BB * NN) / 128, 3), gthr, GEMM_SMEM>>>();

    dim3 ga(NN / 128, HH, BB);
    attn_h<<<ga, gthr, ATTN_SMEM>>>(q, k, v, ao);

    gemm_o<<<dim3(DQ / 128, (BB * NN) / 128), gthr, GEMM_SMEM>>>(bo, x);

    ln_kernel<DQ, false><<<BB * NN, 128>>>(y, lnf_g, lnf_b, out);
}

// round 11
// speedup vs baseline: 6.7374x; 1.0080x over previous
#include <cuda_runtime.h>
#include <cuda_fp16.h>
#include <math.h>
#include <stdint.h>

#define BB 4
#define NN 2048
#define MM 2048
#define DQ 512
#define DC 768
#define HH 8
#define DH 64
#define INNER 512

// 0.125 * log2(e): folds attention scale + base-2 exp domain into Q projection.
#define QSCALE 0.18033688011112042f

// ---------------------------------------------------------------------------
// Scratch (device globals -- no allocation allowed)
// ---------------------------------------------------------------------------
__device__ __half g_xn[BB*NN*DQ];
__device__ __half g_cn[BB*MM*DC];
__device__ __half g_q [BB*NN*INNER];
__device__ __half g_k [BB*MM*INNER];
__device__ __half g_v [BB*MM*INNER];
__device__ __half g_ao[BB*NN*INNER];
__device__ float  g_y [BB*NN*DQ];
__device__ __half g_wq[DQ*INNER];
__device__ __half g_wk[DC*INNER];
__device__ __half g_wv[DC*INNER];
__device__ __half g_wo[INNER*DQ];

// ---------------------------------------------------------------------------
// PTX helpers
// ---------------------------------------------------------------------------
__device__ __forceinline__ uint32_t h2_as_u32(__half2 h) {
    return *reinterpret_cast<uint32_t*>(&h);
}
__device__ __forceinline__ void cp16g(void* dst_smem, const void* src) {
    uint32_t d = (uint32_t)__cvta_generic_to_shared(dst_smem);
    asm volatile("cp.async.cg.shared.global [%0], [%1], 16;" :: "r"(d), "l"(src));
}
__device__ __forceinline__ void cp_commit() {
    asm volatile("cp.async.commit_group;" ::: "memory");
}
__device__ __forceinline__ void cp_wait1() {
    asm volatile("cp.async.wait_group 1;" ::: "memory");
}
__device__ __forceinline__ void cp_wait2() {
    asm volatile("cp.async.wait_group 2;" ::: "memory");
}
__device__ __forceinline__ void ldsm4(uint32_t& r0, uint32_t& r1, uint32_t& r2, uint32_t& r3, uint32_t a) {
    asm volatile("ldmatrix.sync.aligned.m8n8.x4.shared.b16 {%0,%1,%2,%3}, [%4];"
                 : "=r"(r0), "=r"(r1), "=r"(r2), "=r"(r3) : "r"(a));
}
__device__ __forceinline__ void ldsm4t(uint32_t& r0, uint32_t& r1, uint32_t& r2, uint32_t& r3, uint32_t a) {
    asm volatile("ldmatrix.sync.aligned.m8n8.x4.trans.shared.b16 {%0,%1,%2,%3}, [%4];"
                 : "=r"(r0), "=r"(r1), "=r"(r2), "=r"(r3) : "r"(a));
}
__device__ __forceinline__ void mma16(float* c, uint32_t a0, uint32_t a1, uint32_t a2, uint32_t a3,
                                      uint32_t b0, uint32_t b1) {
    asm volatile(
        "mma.sync.aligned.m16n8k16.row.col.f32.f16.f16.f32 "
        "{%0,%1,%2,%3},{%4,%5,%6,%7},{%8,%9},{%0,%1,%2,%3};"
        : "+f"(c[0]), "+f"(c[1]), "+f"(c[2]), "+f"(c[3])
        : "r"(a0), "r"(a1), "r"(a2), "r"(a3), "r"(b0), "r"(b1));
}

// ---------------------------------------------------------------------------
// fp32 -> fp16: all four weight matrices in one launch
// ---------------------------------------------------------------------------
#define N4_WQ (DQ*INNER/4)
#define N4_WK (DC*INNER/4)
#define N4_WV (DC*INNER/4)
#define N4_WO (INNER*DQ/4)
#define N4_TOT (N4_WQ + N4_WK + N4_WV + N4_WO)

__global__ void f2h_all_kernel(const float4* __restrict__ wq, const float4* __restrict__ wk,
                               const float4* __restrict__ wv, const float4* __restrict__ wo)
{
    int i = blockIdx.x * blockDim.x + threadIdx.x;
    if (i >= N4_TOT) return;
    const float4* src;
    __half2* dst;
    int j = i;
    if (j < N4_WQ)                { src = wq; dst = (__half2*)g_wq; }
    else if ((j -= N4_WQ) < N4_WK) { src = wk; dst = (__half2*)g_wk; }
    else if ((j -= N4_WK) < N4_WV) { src = wv; dst = (__half2*)g_wv; }
    else { j -= N4_WV;              src = wo; dst = (__half2*)g_wo; }
    float4 v = src[j];
    dst[2*j]   = __floats2half2_rn(v.x, v.y);
    dst[2*j+1] = __floats2half2_rn(v.z, v.w);
}

// ---------------------------------------------------------------------------
// LayerNorm (fp32 in; fp16 or fp32 out)
// ---------------------------------------------------------------------------
template<int D, bool HALF>
__global__ void ln_kernel(const float* __restrict__ in,
                          const float* __restrict__ gw,
                          const float* __restrict__ bw,
                          void* __restrict__ outp)
{
    const int row = blockIdx.x;
    const float4* x4 = (const float4*)(in + (size_t)row * D);

    float s = 0.f, sq = 0.f;
    for (int i = threadIdx.x; i < D / 4; i += blockDim.x) {
        float4 v = x4[i];
        s  += v.x + v.y + v.z + v.w;
        sq += v.x * v.x + v.y * v.y + v.z * v.z + v.w * v.w;
    }
    __shared__ float red0[8], red1[8];
    #pragma unroll
    for (int off = 16; off; off >>= 1) {
        s  += __shfl_xor_sync(0xffffffffu, s,  off);
        sq += __shfl_xor_sync(0xffffffffu, sq, off);
    }
    int wid = threadIdx.x >> 5, lid = threadIdx.x & 31;
    if (lid == 0) { red0[wid] = s; red1[wid] = sq; }
    __syncthreads();
    int nw = blockDim.x >> 5;
    if (wid == 0) {
        s  = (lid < nw) ? red0[lid] : 0.f;
        sq = (lid < nw) ? red1[lid] : 0.f;
        #pragma unroll
        for (int off = 4; off; off >>= 1) {
            s  += __shfl_xor_sync(0xffffffffu, s,  off);
            sq += __shfl_xor_sync(0xffffffffu, sq, off);
        }
        if (lid == 0) { red0[0] = s; red1[0] = sq; }
    }
    __syncthreads();
    const float mu   = red0[0] * (1.0f / D);
    const float var  = red1[0] * (1.0f / D) - mu * mu;
    const float rstd = rsqrtf(var + 1e-5f);
    const float4* g4 = (const float4*)gw;
    const float4* b4 = (const float4*)bw;
    for (int i = threadIdx.x; i < D / 4; i += blockDim.x) {
        float4 v = x4[i], g = g4[i], b = b4[i], r;
        r.x = (v.x - mu) * rstd * g.x + b.x;
        r.y = (v.y - mu) * rstd * g.y + b.y;
        r.z = (v.z - mu) * rstd * g.z + b.z;
        r.w = (v.w - mu) * rstd * g.w + b.w;
        if (HALF) {
            __half2* o2 = (__half2*)outp + (size_t)row * (D / 2);
            o2[2*i]   = __floats2half2_rn(r.x, r.y);
            o2[2*i+1] = __floats2half2_rn(r.z, r.w);
        } else {
            float4* o4 = (float4*)outp + (size_t)row * (D / 4);
            o4[i] = r;
        }
    }
}

// ---------------------------------------------------------------------------
// GEMM tile config
// ---------------------------------------------------------------------------
#define GS_A 9216                      // 128*72 halves
#define GS_B 8704                      // 64*136 halves
#define GSTG (GS_A + GS_B)             // 17920 halves / stage
#define GEMM_SMEM (3 * GSTG * 2)       // 107520 bytes

// ---------------------------------------------------------------------------
// Merged Q/K/V projection: one launch, grid.z selects {Q,K,V}.
// ---------------------------------------------------------------------------
__global__ __launch_bounds__(256, 2) void qkv_gemm()
{
    extern __shared__ __half smh[];
    const uint32_t sbase = (uint32_t)__cvta_generic_to_shared(smh);

    const __half* A; const __half* W; __half* C; int K; float osc;
    if (blockIdx.z == 0)      { A = g_xn; W = g_wq; C = g_q; K = DQ; osc = QSCALE; }
    else if (blockIdx.z == 1) { A = g_cn; W = g_wk; C = g_k; K = DC; osc = 1.0f; }
    else                      { A = g_cn; W = g_wv; C = g_v; K = DC; osc = 1.0f; }

    const int tid = threadIdx.x;
    const int lane = tid & 31, warp = tid >> 5;
    const int wm = (warp >> 2) * 64;
    const int wn = (warp & 3) * 32;
    const int m0 = blockIdx.y * 128;
    const int n0 = blockIdx.x * 128;
    const int g = lane >> 2, t = lane & 3;

    const int a_row = lane & 15, a_col = (lane >> 4) * 8;
    const int b_row = (lane & 7) + ((lane >> 3) & 1) * 8;
    const int b_col = ((lane >> 4) & 1) * 8;

    float acc[4][4][4];
    #pragma unroll
    for (int i = 0; i < 4; i++)
        #pragma unroll
        for (int j = 0; j < 4; j++)
            #pragma unroll
            for (int q = 0; q < 4; q++) acc[i][j][q] = 0.f;

    auto load_tile = [&](int kt, int buf) {
        int k0 = kt * 64;
        __half* As = smh + buf * GSTG;
        __half* Bs = smh + buf * GSTG + GS_A;
        #pragma unroll
        for (int i = 0; i < 4; i++) {
            int id = tid + i * 256;
            int ar = id >> 3, ac = (id & 7) * 8;
            cp16g(&As[ar * 72 + ac], &A[(size_t)(m0 + ar) * K + k0 + ac]);
            int br = id >> 4, bc = (id & 15) * 8;
            cp16g(&Bs[br * 136 + bc], &W[(size_t)(k0 + br) * INNER + n0 + bc]);
        }
    };

    const int ntiles = K / 64;
    load_tile(0, 0); cp_commit();
    load_tile(1, 1); cp_commit();
    cp_wait1();
    __syncthreads();

    for (int kt = 0; kt < ntiles; kt++) {
        const int cur = kt % 3;
        if (kt + 2 < ntiles) load_tile(kt + 2, (kt + 2) % 3);
        cp_commit();

        const uint32_t abase = sbase + (uint32_t)(cur * GSTG) * 2;
        const uint32_t bbase = abase + (uint32_t)GS_A * 2;

        #pragma unroll
        for (int ks = 0; ks < 4; ks++) {
            uint32_t af[4][4];
            #pragma unroll
            for (int mt = 0; mt < 4; mt++) {
                uint32_t addr = abase +
                    (uint32_t)(((wm + mt * 16 + a_row) * 72 + ks * 16 + a_col) << 1);
                ldsm4(af[mt][0], af[mt][1], af[mt][2], af[mt][3], addr);
            }
            uint32_t bf[8];
            #pragma unroll
            for (int n2 = 0; n2 < 2; n2++) {
                uint32_t addr = bbase +
                    (uint32_t)(((ks * 16 + b_row) * 136 + wn + n2 * 16 + b_col) << 1);
                ldsm4t(bf[n2*4], bf[n2*4+1], bf[n2*4+2], bf[n2*4+3], addr);
            }
            #pragma unroll
            for (int mt = 0; mt < 4; mt++)
                #pragma unroll
                for (int nt = 0; nt < 4; nt++)
                    mma16(acc[mt][nt], af[mt][0], af[mt][1], af[mt][2], af[mt][3],
                          bf[nt*2], bf[nt*2+1]);
        }

        cp_wait1();
        __syncthreads();
    }

    #pragma unroll
    for (int mt = 0; mt < 4; mt++) {
        int row = m0 + wm + mt * 16 + g;
        #pragma unroll
        for (int nt = 0; nt < 4; nt++) {
            int col = n0 + wn + nt * 8 + 2 * t;
            *(__half2*)&C[(size_t)row * INNER + col] =
                __floats2half2_rn(acc[mt][nt][0] * osc, acc[mt][nt][1] * osc);
            *(__half2*)&C[(size_t)(row + 8) * INNER + col] =
                __floats2half2_rn(acc[mt][nt][2] * osc, acc[mt][nt][3] * osc);
        }
    }
}

// ---------------------------------------------------------------------------
// O-projection GEMM (fp32 out + bias + residual)
// ---------------------------------------------------------------------------
__global__ __launch_bounds__(256, 2) void gemm_o(
    const float* __restrict__ bias, const float* __restrict__ resid)
{
    extern __shared__ __half smh[];
    const uint32_t sbase = (uint32_t)__cvta_generic_to_shared(smh);
    const __half* A = g_ao;
    const __half* W = g_wo;
    float* Cf = g_y;
    const int K = INNER, N = DQ;

    const int tid = threadIdx.x;
    const int lane = tid & 31, warp = tid >> 5;
    const int wm = (warp >> 2) * 64;
    const int wn = (warp & 3) * 32;
    const int m0 = blockIdx.y * 128;
    const int n0 = blockIdx.x * 128;
    const int g = lane >> 2, t = lane & 3;

    const int a_row = lane & 15, a_col = (lane >> 4) * 8;
    const int b_row = (lane & 7) + ((lane >> 3) & 1) * 8;
    const int b_col = ((lane >> 4) & 1) * 8;

    float acc[4][4][4];
    #pragma unroll
    for (int i = 0; i < 4; i++)
        #pragma unroll
        for (int j = 0; j < 4; j++)
            #pragma unroll
            for (int q = 0; q < 4; q++) acc[i][j][q] = 0.f;

    auto load_tile = [&](int kt, int buf) {
        int k0 = kt * 64;
        __half* As = smh + buf * GSTG;
        __half* Bs = smh + buf * GSTG + GS_A;
        #pragma unroll
        for (int i = 0; i < 4; i++) {
            int id = tid + i * 256;
            int ar = id >> 3, ac = (id & 7) * 8;
            cp16g(&As[ar * 72 + ac], &A[(size_t)(m0 + ar) * K + k0 + ac]);
            int br = id >> 4, bc = (id & 15) * 8;
            cp16g(&Bs[br * 136 + bc], &W[(size_t)(k0 + br) * N + n0 + bc]);
        }
    };

    const int ntiles = K / 64;
    load_tile(0, 0); cp_commit();
    load_tile(1, 1); cp_commit();
    cp_wait1();
    __syncthreads();

    for (int kt = 0; kt < ntiles; kt++) {
        const int cur = kt % 3;
        if (kt + 2 < ntiles) load_tile(kt + 2, (kt + 2) % 3);
        cp_commit();

        const uint32_t abase = sbase + (uint32_t)(cur * GSTG) * 2;
        const uint32_t bbase = abase + (uint32_t)GS_A * 2;

        #pragma unroll
        for (int ks = 0; ks < 4; ks++) {
            uint32_t af[4][4];
            #pragma unroll
            for (int mt = 0; mt < 4; mt++) {
                uint32_t addr = abase +
                    (uint32_t)(((wm + mt * 16 + a_row) * 72 + ks * 16 + a_col) << 1);
                ldsm4(af[mt][0], af[mt][1], af[mt][2], af[mt][3], addr);
            }
            uint32_t bf[8];
            #pragma unroll
            for (int n2 = 0; n2 < 2; n2++) {
                uint32_t addr = bbase +
                    (uint32_t)(((ks * 16 + b_row) * 136 + wn + n2 * 16 + b_col) << 1);
                ldsm4t(bf[n2*4], bf[n2*4+1], bf[n2*4+2], bf[n2*4+3], addr);
            }
            #pragma unroll
            for (int mt = 0; mt < 4; mt++)
                #pragma unroll
                for (int nt = 0; nt < 4; nt++)
                    mma16(acc[mt][nt], af[mt][0], af[mt][1], af[mt][2], af[mt][3],
                          bf[nt*2], bf[nt*2+1]);
        }

        cp_wait1();
        __syncthreads();
    }

    #pragma unroll
    for (int mt = 0; mt < 4; mt++) {
        int row = m0 + wm + mt * 16 + g;
        #pragma unroll
        for (int nt = 0; nt < 4; nt++) {
            int col = n0 + wn + nt * 8 + 2 * t;
            float2 r01 = { acc[mt][nt][0], acc[mt][nt][1] };
            float2 r23 = { acc[mt][nt][2], acc[mt][nt][3] };
            float2 bb = *(const float2*)&bias[col];
            r01.x += bb.x; r01.y += bb.y;
            r23.x += bb.x; r23.y += bb.y;
            float2 e0 = *(const float2*)&resid[(size_t)row * N + col];
            float2 e1 = *(const float2*)&resid[(size_t)(row + 8) * N + col];
            r01.x += e0.x; r01.y += e0.y;
            r23.x += e1.x; r23.y += e1.y;
            *(float2*)&Cf[(size_t)row * N + col]       = r01;
            *(float2*)&Cf[(size_t)(row + 8) * N + col] = r23;
        }
    }
}

// ---------------------------------------------------------------------------
// fp16 flash attention, FA2 register-P, base-2 f16x2 softmax.
// 128-key chunks (two 64-key sub-blocks), 3-stage cp.async pipeline with ONE
// wait+barrier per 128 keys. Q staged in stage-2's smem (consumed pre-loop).
// ---------------------------------------------------------------------------
#define KVROWS 128
#define KSTG (KVROWS * 72)                       // 9216 halves (K per stage)
#define STG2 (2 * KSTG)                          // K+V per stage, halves
#define ATTN_SMEM (3 * STG2 * 2)                 // 110592 bytes

__global__ __launch_bounds__(256, 2) void attn_h(
    const __half* __restrict__ Qg, const __half* __restrict__ Kg,
    const __half* __restrict__ Vg, __half* __restrict__ Og)
{
    extern __shared__ __half smh[];
    // stage s: K at smh + s*STG2, V at smh + s*STG2 + KSTG
    __half* Qs = smh + 2 * STG2;    // overlaps stage 2 (safe: consumed pre-loop)
    const uint32_t sbase  = (uint32_t)__cvta_generic_to_shared(smh);
    const uint32_t qsbase = (uint32_t)__cvta_generic_to_shared(Qs);

    const int tid  = threadIdx.x;
    const int lane = tid & 31, warp = tid >> 5;
    const int g = lane >> 2, t = lane & 3;
    const int Rr = warp * 16;
    const int it = blockIdx.x, h = blockIdx.y, b = blockIdx.z;

    const __half* qb = Qg + ((size_t)b * NN + it * 128) * INNER + h * DH;
    const __half* kb = Kg + (size_t)b * MM * INNER + h * DH;
    const __half* vb = Vg + (size_t)b * MM * INNER + h * DH;

    const int a_row = lane & 15, a_col = (lane >> 4) * 8;
    const int k_row = (lane & 7) + ((lane >> 4) & 1) * 8;
    const int k_col = ((lane >> 3) & 1) * 8;
    const int v_row = (lane & 7) + ((lane >> 3) & 1) * 8;
    const int v_col = ((lane >> 4) & 1) * 8;

    // load one 128-key chunk (K and V) into stage buf
    auto load_chunk = [&](int buf, int j0) {
        __half* Ks = smh + buf * STG2;
        __half* Vs = Ks + KSTG;
        #pragma unroll
        for (int i = 0; i < 4; i++) {
            int id = tid + i * 256;
            int r = id >> 3, c = (id & 7) * 8;
            cp16g(&Ks[r * 72 + c], &kb[(size_t)(j0 + r) * INNER + c]);
            cp16g(&Vs[r * 72 + c], &vb[(size_t)(j0 + r) * INNER + c]);
        }
    };

    // prologue: Q into stage-2 space, then chunks 0 and 1
    #pragma unroll
    for (int i = 0; i < 4; i++) {
        int id = tid + i * 256;
        int r = id >> 3, c = (id & 7) * 8;
        cp16g(&Qs[r * 72 + c], &qb[(size_t)r * INNER + c]);
    }
    cp_commit();                 // group: Q
    load_chunk(0, 0);
    cp_commit();                 // group: chunk0
    load_chunk(1, KVROWS);
    cp_commit();                 // group: chunk1
    cp_wait2();                  // Q resident (chunk0, chunk1 may be pending)
    __syncthreads();

    uint32_t qf[4][4];
    #pragma unroll
    for (int ks = 0; ks < 4; ks++) {
        uint32_t addr = qsbase + (uint32_t)(((Rr + a_row) * 72 + ks * 16 + a_col) << 1);
        ldsm4(qf[ks][0], qf[ks][1], qf[ks][2], qf[ks][3], addr);
    }
    __syncthreads();             // all Q reads done before stage-2 is reloaded

    float of[8][4];
    #pragma unroll
    for (int i = 0; i < 8; i++)
        #pragma unroll
        for (int q = 0; q < 4; q++) of[i][q] = 0.f;
    float m0r = -INFINITY, m1r = -INFINITY, l0 = 0.f, l1 = 0.f;

    const int nch = MM / KVROWS;   // 16
    for (int ch = 0; ch < nch; ch++) {
        const int cur = ch % 3;
        if (ch + 2 < nch) load_chunk((ch + 2) % 3, (ch + 2) * KVROWS);
        cp_commit();

        const uint32_t kbase = sbase + (uint32_t)(cur * STG2) * 2;
        const uint32_t vbase = kbase + (uint32_t)KSTG * 2;

        #pragma unroll
        for (int sub = 0; sub < 2; sub++) {
            const int roff = sub * 64;   // key-row offset within stage

            // S = Q K^T (log2 domain)
            float sacc[8][4];
            #pragma unroll
            for (int i = 0; i < 8; i++)
                #pragma unroll
                for (int q = 0; q < 4; q++) sacc[i][q] = 0.f;
            #pragma unroll
            for (int ks = 0; ks < 4; ks++) {
                #pragma unroll
                for (int n2 = 0; n2 < 4; n2++) {
                    uint32_t kf0, kf1, kf2, kf3;
                    uint32_t addr = kbase +
                        (uint32_t)(((roff + n2 * 16 + k_row) * 72 + ks * 16 + k_col) << 1);
                    ldsm4(kf0, kf1, kf2, kf3, addr);
                    mma16(sacc[n2*2],   qf[ks][0], qf[ks][1], qf[ks][2], qf[ks][3], kf0, kf1);
                    mma16(sacc[n2*2+1], qf[ks][0], qf[ks][1], qf[ks][2], qf[ks][3], kf2, kf3);
                }
            }

            // online softmax (base-2)
            float rmax0 = -INFINITY, rmax1 = -INFINITY;
            #pragma unroll
            for (int nt = 0; nt < 8; nt++) {
                rmax0 = fmaxf(rmax0, fmaxf(sacc[nt][0], sacc[nt][1]));
                rmax1 = fmaxf(rmax1, fmaxf(sacc[nt][2], sacc[nt][3]));
            }
            rmax0 = fmaxf(rmax0, __shfl_xor_sync(0xffffffffu, rmax0, 1));
            rmax0 = fmaxf(rmax0, __shfl_xor_sync(0xffffffffu, rmax0, 2));
            rmax1 = fmaxf(rmax1, __shfl_xor_sync(0xffffffffu, rmax1, 1));
            rmax1 = fmaxf(rmax1, __shfl_xor_sync(0xffffffffu, rmax1, 2));
            float mn0 = fmaxf(m0r, rmax0), mn1 = fmaxf(m1r, rmax1);
            float c0 = exp2f(m0r - mn0), c1 = exp2f(m1r - mn1);
            m0r = mn0; m1r = mn1;

            uint32_t pf[4][4];
            float rs0 = 0.f, rs1 = 0.f;
            #pragma unroll
            for (int ks = 0; ks < 4; ks++) {
                #pragma unroll
                for (int half = 0; half < 2; half++) {
                    const int nt = 2 * ks + half;
                    __half2 e01 = h2exp2(__floats2half2_rn(sacc[nt][0] - mn0, sacc[nt][1] - mn0));
                    __half2 e23 = h2exp2(__floats2half2_rn(sacc[nt][2] - mn1, sacc[nt][3] - mn1));
                    pf[ks][2*half]   = h2_as_u32(e01);
                    pf[ks][2*half+1] = h2_as_u32(e23);
                    float2 f01 = __half22float2(e01);
                    float2 f23 = __half22float2(e23);
                    rs0 += f01.x + f01.y;
                    rs1 += f23.x + f23.y;
                }
            }
            rs0 += __shfl_xor_sync(0xffffffffu, rs0, 1);
            rs0 += __shfl_xor_sync(0xffffffffu, rs0, 2);
            rs1 += __shfl_xor_sync(0xffffffffu, rs1, 1);
            rs1 += __shfl_xor_sync(0xffffffffu, rs1, 2);
            l0 = l0 * c0 + rs0;
            l1 = l1 * c1 + rs1;
            #pragma unroll
            for (int nt = 0; nt < 8; nt++) {
                of[nt][0] *= c0; of[nt][1] *= c0;
                of[nt][2] *= c1; of[nt][3] *= c1;
            }

            // O += P @ V
            #pragma unroll
            for (int ks = 0; ks < 4; ks++) {
                #pragma unroll
                for (int n2 = 0; n2 < 4; n2++) {
                    uint32_t vf0, vf1, vf2, vf3;
                    uint32_t addr = vbase +
                        (uint32_t)(((roff + ks * 16 + v_row) * 72 + n2 * 16 + v_col) << 1);
                    ldsm4t(vf0, vf1, vf2, vf3, addr);
                    mma16(of[n2*2],   pf[ks][0], pf[ks][1], pf[ks][2], pf[ks][3], vf0, vf1);
                    mma16(of[n2*2+1], pf[ks][0], pf[ks][1], pf[ks][2], pf[ks][3], vf2, vf3);
                }
            }
        }

        cp_wait1();            // chunk ch+1 resident
        __syncthreads();
    }

    float inv0 = 1.f / l0, inv1 = 1.f / l1;
    int row0 = it * 128 + Rr + g, row1 = row0 + 8;
    #pragma unroll
    for (int nt = 0; nt < 8; nt++) {
        *(__half2*)&Og[((size_t)b * NN + row0) * INNER + h * DH + nt * 8 + 2 * t] =
            __floats2half2_rn(of[nt][0] * inv0, of[nt][1] * inv0);
        *(__half2*)&Og[((size_t)b * NN + row1) * INNER + h * DH + nt * 8 + 2 * t] =
            __floats2half2_rn(of[nt][2] * inv1, of[nt][3] * inv1);
    }
}

// ---------------------------------------------------------------------------
// Launch
// ---------------------------------------------------------------------------
extern "C" void kernel_launch(void* const* d_in, const int* in_sizes, int n_in,
                              void* d_out, int out_size)
{
    (void)in_sizes; (void)n_in; (void)out_size;
    const float* x     = (const float*)d_in[0];
    const float* cond  = (const float*)d_in[1];
    const float* lnx_g = (const float*)d_in[2];
    const float* lnx_b = (const float*)d_in[3];
    const float* lnc_g = (const float*)d_in[4];
    const float* lnc_b = (const float*)d_in[5];
    const float* Wq    = (const float*)d_in[6];
    const float* Wk    = (const float*)d_in[7];
    const float* Wv    = (const float*)d_in[8];
    const float* Wo    = (const float*)d_in[9];
    const float* bo    = (const float*)d_in[10];
    const float* lnf_g = (const float*)d_in[11];
    const float* lnf_b = (const float*)d_in[12];
    float* out = (float*)d_out;

    __half *xn, *cn, *q, *k, *v, *ao;
    float *y;
    cudaGetSymbolAddress((void**)&xn, g_xn);
    cudaGetSymbolAddress((void**)&cn, g_cn);
    cudaGetSymbolAddress((void**)&q,  g_q);
    cudaGetSymbolAddress((void**)&k,  g_k);
    cudaGetSymbolAddress((void**)&v,  g_v);
    cudaGetSymbolAddress((void**)&ao, g_ao);
    cudaGetSymbolAddress((void**)&y,  g_y);

    cudaFuncSetAttribute(qkv_gemm, cudaFuncAttributeMaxDynamicSharedMemorySize, GEMM_SMEM);
    cudaFuncSetAttribute(gemm_o,  cudaFuncAttributeMaxDynamicSharedMemorySize, GEMM_SMEM);
    cudaFuncSetAttribute(attn_h,  cudaFuncAttributeMaxDynamicSharedMemorySize, ATTN_SMEM);

    f2h_all_kernel<<<(N4_TOT + 255)/256, 256>>>((const float4*)Wq, (const float4*)Wk,
                                                (const float4*)Wv, (const float4*)Wo);

    ln_kernel<DQ, true><<<BB * NN, 128>>>(x, lnx_g, lnx_b, xn);
    ln_kernel<DC, true><<<BB * MM, 128>>>(cond, lnc_g, lnc_b, cn);

    dim3 gthr(256);
    qkv_gemm<<<dim3(INNER / 128, (BB * NN) / 128, 3), gthr, GEMM_SMEM>>>();

    dim3 ga(NN / 128, HH, BB);
    attn_h<<<ga, gthr, ATTN_SMEM>>>(q, k, v, ao);

    gemm_o<<<dim3(DQ / 128, (BB * NN) / 128), gthr, GEMM_SMEM>>>(bo, x);

    ln_kernel<DQ, false><<<BB * NN, 128>>>(y, lnf_g, lnf_b, out);
}

// round 12
// speedup vs baseline: 6.9206x; 1.0272x over previous
#include <cuda_runtime.h>
#include <cuda_fp16.h>
#include <math.h>
#include <stdint.h>

#define BB 4
#define NN 2048
#define MM 2048
#define DQ 512
#define DC 768
#define HH 8
#define DH 64
#define INNER 512

// 0.125 * log2(e): folds attention scale + base-2 exp domain into Q projection.
#define QSCALE 0.18033688011112042f

// ---------------------------------------------------------------------------
// Scratch (device globals -- no allocation allowed)
// ---------------------------------------------------------------------------
__device__ __half g_xn[BB*NN*DQ];
__device__ __half g_cn[BB*MM*DC];
__device__ __half g_q [BB*NN*INNER];
__device__ __half g_k [BB*MM*INNER];
__device__ __half g_v [BB*MM*INNER];
__device__ __half g_ao[BB*NN*INNER];
__device__ float  g_y [BB*NN*DQ];
__device__ __half g_wq[DQ*INNER];
__device__ __half g_wk[DC*INNER];
__device__ __half g_wv[DC*INNER];
__device__ __half g_wo[INNER*DQ];

// ---------------------------------------------------------------------------
// PTX helpers
// ---------------------------------------------------------------------------
__device__ __forceinline__ uint32_t h2_as_u32(__half2 h) {
    return *reinterpret_cast<uint32_t*>(&h);
}
__device__ __forceinline__ void cp16g(void* dst_smem, const void* src) {
    uint32_t d = (uint32_t)__cvta_generic_to_shared(dst_smem);
    asm volatile("cp.async.cg.shared.global [%0], [%1], 16;" :: "r"(d), "l"(src));
}
__device__ __forceinline__ void cp_commit() {
    asm volatile("cp.async.commit_group;" ::: "memory");
}
__device__ __forceinline__ void cp_wait1() {
    asm volatile("cp.async.wait_group 1;" ::: "memory");
}
__device__ __forceinline__ void cp_wait2() {
    asm volatile("cp.async.wait_group 2;" ::: "memory");
}
__device__ __forceinline__ void ldsm4(uint32_t& r0, uint32_t& r1, uint32_t& r2, uint32_t& r3, uint32_t a) {
    asm volatile("ldmatrix.sync.aligned.m8n8.x4.shared.b16 {%0,%1,%2,%3}, [%4];"
                 : "=r"(r0), "=r"(r1), "=r"(r2), "=r"(r3) : "r"(a));
}
__device__ __forceinline__ void ldsm4t(uint32_t& r0, uint32_t& r1, uint32_t& r2, uint32_t& r3, uint32_t a) {
    asm volatile("ldmatrix.sync.aligned.m8n8.x4.trans.shared.b16 {%0,%1,%2,%3}, [%4];"
                 : "=r"(r0), "=r"(r1), "=r"(r2), "=r"(r3) : "r"(a));
}
__device__ __forceinline__ void mma16(float* c, uint32_t a0, uint32_t a1, uint32_t a2, uint32_t a3,
                                      uint32_t b0, uint32_t b1) {
    asm volatile(
        "mma.sync.aligned.m16n8k16.row.col.f32.f16.f16.f32 "
        "{%0,%1,%2,%3},{%4,%5,%6,%7},{%8,%9},{%0,%1,%2,%3};"
        : "+f"(c[0]), "+f"(c[1]), "+f"(c[2]), "+f"(c[3])
        : "r"(a0), "r"(a1), "r"(a2), "r"(a3), "r"(b0), "r"(b1));
}

// ---------------------------------------------------------------------------
// fp32 -> fp16: all four weight matrices in one launch
// ---------------------------------------------------------------------------
#define N4_WQ (DQ*INNER/4)
#define N4_WK (DC*INNER/4)
#define N4_WV (DC*INNER/4)
#define N4_WO (INNER*DQ/4)
#define N4_TOT (N4_WQ + N4_WK + N4_WV + N4_WO)

__global__ void f2h_all_kernel(const float4* __restrict__ wq, const float4* __restrict__ wk,
                               const float4* __restrict__ wv, const float4* __restrict__ wo)
{
    int i = blockIdx.x * blockDim.x + threadIdx.x;
    if (i >= N4_TOT) return;
    const float4* src;
    __half2* dst;
    int j = i;
    if (j < N4_WQ)                { src = wq; dst = (__half2*)g_wq; }
    else if ((j -= N4_WQ) < N4_WK) { src = wk; dst = (__half2*)g_wk; }
    else if ((j -= N4_WK) < N4_WV) { src = wv; dst = (__half2*)g_wv; }
    else { j -= N4_WV;              src = wo; dst = (__half2*)g_wo; }
    float4 v = src[j];
    dst[2*j]   = __floats2half2_rn(v.x, v.y);
    dst[2*j+1] = __floats2half2_rn(v.z, v.w);
}

// ---------------------------------------------------------------------------
// Warp-per-row LayerNorm, input side (both LNs in one launch, fp16 out).
// Row data held in registers across the stats pass: single gmem read.
// ---------------------------------------------------------------------------
__global__ __launch_bounds__(256) void ln_in_dual(
    const float* __restrict__ x,    const float* __restrict__ xg, const float* __restrict__ xb,
    const float* __restrict__ cnd,  const float* __restrict__ cg, const float* __restrict__ cb)
{
    const int warp = threadIdx.x >> 5, lane = threadIdx.x & 31;
    int row = blockIdx.x * 8 + warp;

    const float* in; const float* gw; const float* bw; __half* out; int D;
    if (row < BB * NN) { in = x; gw = xg; bw = xb; out = g_xn; D = DQ; }
    else { row -= BB * NN; in = cnd; gw = cg; bw = cb; out = g_cn; D = DC; }
    const int nv = D / 128;   // float4s per lane (4 or 6)

    const float4* x4 = (const float4*)(in + (size_t)row * D);
    float4 v[6];
    float s = 0.f, sq = 0.f;
    #pragma unroll 6
    for (int i = 0; i < nv; i++) {
        v[i] = x4[lane + 32 * i];
        s  += v[i].x + v[i].y + v[i].z + v[i].w;
        sq += v[i].x * v[i].x + v[i].y * v[i].y + v[i].z * v[i].z + v[i].w * v[i].w;
    }
    #pragma unroll
    for (int off = 16; off; off >>= 1) {
        s  += __shfl_xor_sync(0xffffffffu, s,  off);
        sq += __shfl_xor_sync(0xffffffffu, sq, off);
    }
    const float mu   = s * (1.0f / D);
    const float var  = sq * (1.0f / D) - mu * mu;
    const float rstd = rsqrtf(var + 1e-5f);

    const float4* g4 = (const float4*)gw;
    const float4* b4 = (const float4*)bw;
    __half2* o2 = (__half2*)out + (size_t)row * (D / 2);
    #pragma unroll 6
    for (int i = 0; i < nv; i++) {
        float4 g = g4[lane + 32 * i], b = b4[lane + 32 * i];
        float rx = (v[i].x - mu) * rstd * g.x + b.x;
        float ry = (v[i].y - mu) * rstd * g.y + b.y;
        float rz = (v[i].z - mu) * rstd * g.z + b.z;
        float rw = (v[i].w - mu) * rstd * g.w + b.w;
        o2[(lane + 32 * i) * 2]     = __floats2half2_rn(rx, ry);
        o2[(lane + 32 * i) * 2 + 1] = __floats2half2_rn(rz, rw);
    }
}

// Warp-per-row final LayerNorm (fp32 in/out, D=512)
__global__ __launch_bounds__(256) void ln_out(
    const float* __restrict__ in, const float* __restrict__ gw,
    const float* __restrict__ bw, float* __restrict__ outp)
{
    const int warp = threadIdx.x >> 5, lane = threadIdx.x & 31;
    const int row = blockIdx.x * 8 + warp;

    const float4* x4 = (const float4*)(in + (size_t)row * DQ);
    float4 v[4];
    float s = 0.f, sq = 0.f;
    #pragma unroll
    for (int i = 0; i < 4; i++) {
        v[i] = x4[lane + 32 * i];
        s  += v[i].x + v[i].y + v[i].z + v[i].w;
        sq += v[i].x * v[i].x + v[i].y * v[i].y + v[i].z * v[i].z + v[i].w * v[i].w;
    }
    #pragma unroll
    for (int off = 16; off; off >>= 1) {
        s  += __shfl_xor_sync(0xffffffffu, s,  off);
        sq += __shfl_xor_sync(0xffffffffu, sq, off);
    }
    const float mu   = s * (1.0f / DQ);
    const float var  = sq * (1.0f / DQ) - mu * mu;
    const float rstd = rsqrtf(var + 1e-5f);

    const float4* g4 = (const float4*)gw;
    const float4* b4 = (const float4*)bw;
    float4* o4 = (float4*)(outp + (size_t)row * DQ);
    #pragma unroll
    for (int i = 0; i < 4; i++) {
        float4 g = g4[lane + 32 * i], b = b4[lane + 32 * i], r;
        r.x = (v[i].x - mu) * rstd * g.x + b.x;
        r.y = (v[i].y - mu) * rstd * g.y + b.y;
        r.z = (v[i].z - mu) * rstd * g.z + b.z;
        r.w = (v[i].w - mu) * rstd * g.w + b.w;
        o4[lane + 32 * i] = r;
    }
}

// ---------------------------------------------------------------------------
// GEMM tile config
// ---------------------------------------------------------------------------
#define GS_A 9216                      // 128*72 halves
#define GS_B 8704                      // 64*136 halves
#define GSTG (GS_A + GS_B)             // 17920 halves / stage
#define GEMM_SMEM (3 * GSTG * 2)       // 107520 bytes

// ---------------------------------------------------------------------------
// Merged Q/K/V projection: one launch, grid.z selects {Q,K,V}.
// ---------------------------------------------------------------------------
__global__ __launch_bounds__(256, 2) void qkv_gemm()
{
    extern __shared__ __half smh[];
    const uint32_t sbase = (uint32_t)__cvta_generic_to_shared(smh);

    const __half* A; const __half* W; __half* C; int K; float osc;
    if (blockIdx.z == 0)      { A = g_xn; W = g_wq; C = g_q; K = DQ; osc = QSCALE; }
    else if (blockIdx.z == 1) { A = g_cn; W = g_wk; C = g_k; K = DC; osc = 1.0f; }
    else                      { A = g_cn; W = g_wv; C = g_v; K = DC; osc = 1.0f; }

    const int tid = threadIdx.x;
    const int lane = tid & 31, warp = tid >> 5;
    const int wm = (warp >> 2) * 64;
    const int wn = (warp & 3) * 32;
    const int m0 = blockIdx.y * 128;
    const int n0 = blockIdx.x * 128;
    const int g = lane >> 2, t = lane & 3;

    const int a_row = lane & 15, a_col = (lane >> 4) * 8;
    const int b_row = (lane & 7) + ((lane >> 3) & 1) * 8;
    const int b_col = ((lane >> 4) & 1) * 8;

    float acc[4][4][4];
    #pragma unroll
    for (int i = 0; i < 4; i++)
        #pragma unroll
        for (int j = 0; j < 4; j++)
            #pragma unroll
            for (int q = 0; q < 4; q++) acc[i][j][q] = 0.f;

    auto load_tile = [&](int kt, int buf) {
        int k0 = kt * 64;
        __half* As = smh + buf * GSTG;
        __half* Bs = smh + buf * GSTG + GS_A;
        #pragma unroll
        for (int i = 0; i < 4; i++) {
            int id = tid + i * 256;
            int ar = id >> 3, ac = (id & 7) * 8;
            cp16g(&As[ar * 72 + ac], &A[(size_t)(m0 + ar) * K + k0 + ac]);
            int br = id >> 4, bc = (id & 15) * 8;
            cp16g(&Bs[br * 136 + bc], &W[(size_t)(k0 + br) * INNER + n0 + bc]);
        }
    };

    const int ntiles = K / 64;
    load_tile(0, 0); cp_commit();
    load_tile(1, 1); cp_commit();
    cp_wait1();
    __syncthreads();

    for (int kt = 0; kt < ntiles; kt++) {
        const int cur = kt % 3;
        if (kt + 2 < ntiles) load_tile(kt + 2, (kt + 2) % 3);
        cp_commit();

        const uint32_t abase = sbase + (uint32_t)(cur * GSTG) * 2;
        const uint32_t bbase = abase + (uint32_t)GS_A * 2;

        #pragma unroll
        for (int ks = 0; ks < 4; ks++) {
            uint32_t af[4][4];
            #pragma unroll
            for (int mt = 0; mt < 4; mt++) {
                uint32_t addr = abase +
                    (uint32_t)(((wm + mt * 16 + a_row) * 72 + ks * 16 + a_col) << 1);
                ldsm4(af[mt][0], af[mt][1], af[mt][2], af[mt][3], addr);
            }
            uint32_t bf[8];
            #pragma unroll
            for (int n2 = 0; n2 < 2; n2++) {
                uint32_t addr = bbase +
                    (uint32_t)(((ks * 16 + b_row) * 136 + wn + n2 * 16 + b_col) << 1);
                ldsm4t(bf[n2*4], bf[n2*4+1], bf[n2*4+2], bf[n2*4+3], addr);
            }
            #pragma unroll
            for (int mt = 0; mt < 4; mt++)
                #pragma unroll
                for (int nt = 0; nt < 4; nt++)
                    mma16(acc[mt][nt], af[mt][0], af[mt][1], af[mt][2], af[mt][3],
                          bf[nt*2], bf[nt*2+1]);
        }

        cp_wait1();
        __syncthreads();
    }

    #pragma unroll
    for (int mt = 0; mt < 4; mt++) {
        int row = m0 + wm + mt * 16 + g;
        #pragma unroll
        for (int nt = 0; nt < 4; nt++) {
            int col = n0 + wn + nt * 8 + 2 * t;
            *(__half2*)&C[(size_t)row * INNER + col] =
                __floats2half2_rn(acc[mt][nt][0] * osc, acc[mt][nt][1] * osc);
            *(__half2*)&C[(size_t)(row + 8) * INNER + col] =
                __floats2half2_rn(acc[mt][nt][2] * osc, acc[mt][nt][3] * osc);
        }
    }
}

// ---------------------------------------------------------------------------
// O-projection GEMM (fp32 out + bias + residual)
// ---------------------------------------------------------------------------
__global__ __launch_bounds__(256, 2) void gemm_o(
    const float* __restrict__ bias, const float* __restrict__ resid)
{
    extern __shared__ __half smh[];
    const uint32_t sbase = (uint32_t)__cvta_generic_to_shared(smh);
    const __half* A = g_ao;
    const __half* W = g_wo;
    float* Cf = g_y;
    const int K = INNER, N = DQ;

    const int tid = threadIdx.x;
    const int lane = tid & 31, warp = tid >> 5;
    const int wm = (warp >> 2) * 64;
    const int wn = (warp & 3) * 32;
    const int m0 = blockIdx.y * 128;
    const int n0 = blockIdx.x * 128;
    const int g = lane >> 2, t = lane & 3;

    const int a_row = lane & 15, a_col = (lane >> 4) * 8;
    const int b_row = (lane & 7) + ((lane >> 3) & 1) * 8;
    const int b_col = ((lane >> 4) & 1) * 8;

    float acc[4][4][4];
    #pragma unroll
    for (int i = 0; i < 4; i++)
        #pragma unroll
        for (int j = 0; j < 4; j++)
            #pragma unroll
            for (int q = 0; q < 4; q++) acc[i][j][q] = 0.f;

    auto load_tile = [&](int kt, int buf) {
        int k0 = kt * 64;
        __half* As = smh + buf * GSTG;
        __half* Bs = smh + buf * GSTG + GS_A;
        #pragma unroll
        for (int i = 0; i < 4; i++) {
            int id = tid + i * 256;
            int ar = id >> 3, ac = (id & 7) * 8;
            cp16g(&As[ar * 72 + ac], &A[(size_t)(m0 + ar) * K + k0 + ac]);
            int br = id >> 4, bc = (id & 15) * 8;
            cp16g(&Bs[br * 136 + bc], &W[(size_t)(k0 + br) * N + n0 + bc]);
        }
    };

    const int ntiles = K / 64;
    load_tile(0, 0); cp_commit();
    load_tile(1, 1); cp_commit();
    cp_wait1();
    __syncthreads();

    for (int kt = 0; kt < ntiles; kt++) {
        const int cur = kt % 3;
        if (kt + 2 < ntiles) load_tile(kt + 2, (kt + 2) % 3);
        cp_commit();

        const uint32_t abase = sbase + (uint32_t)(cur * GSTG) * 2;
        const uint32_t bbase = abase + (uint32_t)GS_A * 2;

        #pragma unroll
        for (int ks = 0; ks < 4; ks++) {
            uint32_t af[4][4];
            #pragma unroll
            for (int mt = 0; mt < 4; mt++) {
                uint32_t addr = abase +
                    (uint32_t)(((wm + mt * 16 + a_row) * 72 + ks * 16 + a_col) << 1);
                ldsm4(af[mt][0], af[mt][1], af[mt][2], af[mt][3], addr);
            }
            uint32_t bf[8];
            #pragma unroll
            for (int n2 = 0; n2 < 2; n2++) {
                uint32_t addr = bbase +
                    (uint32_t)(((ks * 16 + b_row) * 136 + wn + n2 * 16 + b_col) << 1);
                ldsm4t(bf[n2*4], bf[n2*4+1], bf[n2*4+2], bf[n2*4+3], addr);
            }
            #pragma unroll
            for (int mt = 0; mt < 4; mt++)
                #pragma unroll
                for (int nt = 0; nt < 4; nt++)
                    mma16(acc[mt][nt], af[mt][0], af[mt][1], af[mt][2], af[mt][3],
                          bf[nt*2], bf[nt*2+1]);
        }

        cp_wait1();
        __syncthreads();
    }

    #pragma unroll
    for (int mt = 0; mt < 4; mt++) {
        int row = m0 + wm + mt * 16 + g;
        #pragma unroll
        for (int nt = 0; nt < 4; nt++) {
            int col = n0 + wn + nt * 8 + 2 * t;
            float2 r01 = { acc[mt][nt][0], acc[mt][nt][1] };
            float2 r23 = { acc[mt][nt][2], acc[mt][nt][3] };
            float2 bb = *(const float2*)&bias[col];
            r01.x += bb.x; r01.y += bb.y;
            r23.x += bb.x; r23.y += bb.y;
            float2 e0 = *(const float2*)&resid[(size_t)row * N + col];
            float2 e1 = *(const float2*)&resid[(size_t)(row + 8) * N + col];
            r01.x += e0.x; r01.y += e0.y;
            r23.x += e1.x; r23.y += e1.y;
            *(float2*)&Cf[(size_t)row * N + col]       = r01;
            *(float2*)&Cf[(size_t)(row + 8) * N + col] = r23;
        }
    }
}

// ---------------------------------------------------------------------------
// fp16 flash attention, FA2 register-P, base-2 f16x2 softmax, vote-skipped
// of[] rescale. 128-key chunks (two 64-key sub-blocks), 3-stage pipeline.
// ---------------------------------------------------------------------------
#define KVROWS 128
#define KSTG (KVROWS * 72)                       // 9216 halves (K per stage)
#define STG2 (2 * KSTG)                          // K+V per stage, halves
#define ATTN_SMEM (3 * STG2 * 2)                 // 110592 bytes

__global__ __launch_bounds__(256, 2) void attn_h(
    const __half* __restrict__ Qg, const __half* __restrict__ Kg,
    const __half* __restrict__ Vg, __half* __restrict__ Og)
{
    extern __shared__ __half smh[];
    __half* Qs = smh + 2 * STG2;    // overlaps stage 2 (consumed pre-loop)
    const uint32_t sbase  = (uint32_t)__cvta_generic_to_shared(smh);
    const uint32_t qsbase = (uint32_t)__cvta_generic_to_shared(Qs);

    const int tid  = threadIdx.x;
    const int lane = tid & 31, warp = tid >> 5;
    const int g = lane >> 2, t = lane & 3;
    const int Rr = warp * 16;
    const int it = blockIdx.x, h = blockIdx.y, b = blockIdx.z;

    const __half* qb = Qg + ((size_t)b * NN + it * 128) * INNER + h * DH;
    const __half* kb = Kg + (size_t)b * MM * INNER + h * DH;
    const __half* vb = Vg + (size_t)b * MM * INNER + h * DH;

    const int a_row = lane & 15, a_col = (lane >> 4) * 8;
    const int k_row = (lane & 7) + ((lane >> 4) & 1) * 8;
    const int k_col = ((lane >> 3) & 1) * 8;
    const int v_row = (lane & 7) + ((lane >> 3) & 1) * 8;
    const int v_col = ((lane >> 4) & 1) * 8;

    auto load_chunk = [&](int buf, int j0) {
        __half* Ks = smh + buf * STG2;
        __half* Vs = Ks + KSTG;
        #pragma unroll
        for (int i = 0; i < 4; i++) {
            int id = tid + i * 256;
            int r = id >> 3, c = (id & 7) * 8;
            cp16g(&Ks[r * 72 + c], &kb[(size_t)(j0 + r) * INNER + c]);
            cp16g(&Vs[r * 72 + c], &vb[(size_t)(j0 + r) * INNER + c]);
        }
    };

    #pragma unroll
    for (int i = 0; i < 4; i++) {
        int id = tid + i * 256;
        int r = id >> 3, c = (id & 7) * 8;
        cp16g(&Qs[r * 72 + c], &qb[(size_t)r * INNER + c]);
    }
    cp_commit();                 // group: Q
    load_chunk(0, 0);
    cp_commit();                 // group: chunk0
    load_chunk(1, KVROWS);
    cp_commit();                 // group: chunk1
    cp_wait2();                  // Q resident
    __syncthreads();

    uint32_t qf[4][4];
    #pragma unroll
    for (int ks = 0; ks < 4; ks++) {
        uint32_t addr = qsbase + (uint32_t)(((Rr + a_row) * 72 + ks * 16 + a_col) << 1);
        ldsm4(qf[ks][0], qf[ks][1], qf[ks][2], qf[ks][3], addr);
    }
    __syncthreads();             // Q reads done before stage-2 reload

    float of[8][4];
    #pragma unroll
    for (int i = 0; i < 8; i++)
        #pragma unroll
        for (int q = 0; q < 4; q++) of[i][q] = 0.f;
    float m0r = -INFINITY, m1r = -INFINITY, l0 = 0.f, l1 = 0.f;

    const int nch = MM / KVROWS;   // 16
    for (int ch = 0; ch < nch; ch++) {
        const int cur = ch % 3;
        if (ch + 2 < nch) load_chunk((ch + 2) % 3, (ch + 2) * KVROWS);
        cp_commit();

        const uint32_t kbase = sbase + (uint32_t)(cur * STG2) * 2;
        const uint32_t vbase = kbase + (uint32_t)KSTG * 2;

        #pragma unroll
        for (int sub = 0; sub < 2; sub++) {
            const int roff = sub * 64;

            // S = Q K^T (log2 domain)
            float sacc[8][4];
            #pragma unroll
            for (int i = 0; i < 8; i++)
                #pragma unroll
                for (int q = 0; q < 4; q++) sacc[i][q] = 0.f;
            #pragma unroll
            for (int ks = 0; ks < 4; ks++) {
                #pragma unroll
                for (int n2 = 0; n2 < 4; n2++) {
                    uint32_t kf0, kf1, kf2, kf3;
                    uint32_t addr = kbase +
                        (uint32_t)(((roff + n2 * 16 + k_row) * 72 + ks * 16 + k_col) << 1);
                    ldsm4(kf0, kf1, kf2, kf3, addr);
                    mma16(sacc[n2*2],   qf[ks][0], qf[ks][1], qf[ks][2], qf[ks][3], kf0, kf1);
                    mma16(sacc[n2*2+1], qf[ks][0], qf[ks][1], qf[ks][2], qf[ks][3], kf2, kf3);
                }
            }

            // online softmax (base-2)
            float rmax0 = -INFINITY, rmax1 = -INFINITY;
            #pragma unroll
            for (int nt = 0; nt < 8; nt++) {
                rmax0 = fmaxf(rmax0, fmaxf(sacc[nt][0], sacc[nt][1]));
                rmax1 = fmaxf(rmax1, fmaxf(sacc[nt][2], sacc[nt][3]));
            }
            rmax0 = fmaxf(rmax0, __shfl_xor_sync(0xffffffffu, rmax0, 1));
            rmax0 = fmaxf(rmax0, __shfl_xor_sync(0xffffffffu, rmax0, 2));
            rmax1 = fmaxf(rmax1, __shfl_xor_sync(0xffffffffu, rmax1, 1));
            rmax1 = fmaxf(rmax1, __shfl_xor_sync(0xffffffffu, rmax1, 2));
            float mn0 = fmaxf(m0r, rmax0), mn1 = fmaxf(m1r, rmax1);
            float c0 = exp2f(m0r - mn0), c1 = exp2f(m1r - mn1);
            m0r = mn0; m1r = mn1;

            uint32_t pf[4][4];
            float rs0 = 0.f, rs1 = 0.f;
            #pragma unroll
            for (int ks = 0; ks < 4; ks++) {
                #pragma unroll
                for (int half = 0; half < 2; half++) {
                    const int nt = 2 * ks + half;
                    __half2 e01 = h2exp2(__floats2half2_rn(sacc[nt][0] - mn0, sacc[nt][1] - mn0));
                    __half2 e23 = h2exp2(__floats2half2_rn(sacc[nt][2] - mn1, sacc[nt][3] - mn1));
                    pf[ks][2*half]   = h2_as_u32(e01);
                    pf[ks][2*half+1] = h2_as_u32(e23);
                    float2 f01 = __half22float2(e01);
                    float2 f23 = __half22float2(e23);
                    rs0 += f01.x + f01.y;
                    rs1 += f23.x + f23.y;
                }
            }
            rs0 += __shfl_xor_sync(0xffffffffu, rs0, 1);
            rs0 += __shfl_xor_sync(0xffffffffu, rs0, 2);
            rs1 += __shfl_xor_sync(0xffffffffu, rs1, 1);
            rs1 += __shfl_xor_sync(0xffffffffu, rs1, 2);
            l0 = l0 * c0 + rs0;
            l1 = l1 * c1 + rs1;

            // vote-skip the of[] rescale: exact (skip only when all c==1)
            if (__any_sync(0xffffffffu, (c0 != 1.0f) || (c1 != 1.0f))) {
                #pragma unroll
                for (int nt = 0; nt < 8; nt++) {
                    of[nt][0] *= c0; of[nt][1] *= c0;
                    of[nt][2] *= c1; of[nt][3] *= c1;
                }
            }

            // O += P @ V
            #pragma unroll
            for (int ks = 0; ks < 4; ks++) {
                #pragma unroll
                for (int n2 = 0; n2 < 4; n2++) {
                    uint32_t vf0, vf1, vf2, vf3;
                    uint32_t addr = vbase +
                        (uint32_t)(((roff + ks * 16 + v_row) * 72 + n2 * 16 + v_col) << 1);
                    ldsm4t(vf0, vf1, vf2, vf3, addr);
                    mma16(of[n2*2],   pf[ks][0], pf[ks][1], pf[ks][2], pf[ks][3], vf0, vf1);
                    mma16(of[n2*2+1], pf[ks][0], pf[ks][1], pf[ks][2], pf[ks][3], vf2, vf3);
                }
            }
        }

        cp_wait1();
        __syncthreads();
    }

    float inv0 = 1.f / l0, inv1 = 1.f / l1;
    int row0 = it * 128 + Rr + g, row1 = row0 + 8;
    #pragma unroll
    for (int nt = 0; nt < 8; nt++) {
        *(__half2*)&Og[((size_t)b * NN + row0) * INNER + h * DH + nt * 8 + 2 * t] =
            __floats2half2_rn(of[nt][0] * inv0, of[nt][1] * inv0);
        *(__half2*)&Og[((size_t)b * NN + row1) * INNER + h * DH + nt * 8 + 2 * t] =
            __floats2half2_rn(of[nt][2] * inv1, of[nt][3] * inv1);
    }
}

// ---------------------------------------------------------------------------
// Launch
// ---------------------------------------------------------------------------
extern "C" void kernel_launch(void* const* d_in, const int* in_sizes, int n_in,
                              void* d_out, int out_size)
{
    (void)in_sizes; (void)n_in; (void)out_size;
    const float* x     = (const float*)d_in[0];
    const float* cond  = (const float*)d_in[1];
    const float* lnx_g = (const float*)d_in[2];
    const float* lnx_b = (const float*)d_in[3];
    const float* lnc_g = (const float*)d_in[4];
    const float* lnc_b = (const float*)d_in[5];
    const float* Wq    = (const float*)d_in[6];
    const float* Wk    = (const float*)d_in[7];
    const float* Wv    = (const float*)d_in[8];
    const float* Wo    = (const float*)d_in[9];
    const float* bo    = (const float*)d_in[10];
    const float* lnf_g = (const float*)d_in[11];
    const float* lnf_b = (const float*)d_in[12];
    float* out = (float*)d_out;

    __half *q, *k, *v, *ao;
    float *y;
    cudaGetSymbolAddress((void**)&q,  g_q);
    cudaGetSymbolAddress((void**)&k,  g_k);
    cudaGetSymbolAddress((void**)&v,  g_v);
    cudaGetSymbolAddress((void**)&ao, g_ao);
    cudaGetSymbolAddress((void**)&y,  g_y);

    cudaFuncSetAttribute(qkv_gemm, cudaFuncAttributeMaxDynamicSharedMemorySize, GEMM_SMEM);
    cudaFuncSetAttribute(gemm_o,  cudaFuncAttributeMaxDynamicSharedMemorySize, GEMM_SMEM);
    cudaFuncSetAttribute(attn_h,  cudaFuncAttributeMaxDynamicSharedMemorySize, ATTN_SMEM);

    f2h_all_kernel<<<(N4_TOT + 255)/256, 256>>>((const float4*)Wq, (const float4*)Wk,
                                                (const float4*)Wv, (const float4*)Wo);

    ln_in_dual<<<(BB * NN + BB * MM) / 8, 256>>>(x, lnx_g, lnx_b, cond, lnc_g, lnc_b);

    dim3 gthr(256);
    qkv_gemm<<<dim3(INNER / 128, (BB * NN) / 128, 3), gthr, GEMM_SMEM>>>();

    dim3 ga(NN / 128, HH, BB);
    attn_h<<<ga, gthr, ATTN_SMEM>>>(q, k, v, ao);

    gemm_o<<<dim3(DQ / 128, (BB * NN) / 128), gthr, GEMM_SMEM>>>(bo, x);

    ln_out<<<(BB * NN) / 8, 256>>>(y, lnf_g, lnf_b, out);
}

// round 13
// speedup vs baseline: 7.2086x; 1.0416x over previous
#include <cuda_runtime.h>
#include <cuda_fp16.h>
#include <math.h>
#include <stdint.h>

#define BB 4
#define NN 2048
#define MM 2048
#define DQ 512
#define DC 768
#define HH 8
#define DH 64
#define INNER 512

// 0.125 * log2(e): folds attention scale + base-2 exp domain into Q projection.
#define QSCALE 0.18033688011112042f

// ---------------------------------------------------------------------------
// Scratch (device globals -- no allocation allowed)
// ---------------------------------------------------------------------------
__device__ __half g_xn[BB*NN*DQ];
__device__ __half g_cn[BB*MM*DC];
__device__ __half g_q [BB*NN*INNER];
__device__ __half g_k [BB*MM*INNER];
__device__ __half g_v [BB*MM*INNER];
__device__ __half g_ao[BB*NN*INNER];
__device__ float  g_y [BB*NN*DQ];
__device__ __half g_wq[DQ*INNER];
__device__ __half g_wk[DC*INNER];
__device__ __half g_wv[DC*INNER];
__device__ __half g_wo[INNER*DQ];

// ---------------------------------------------------------------------------
// PTX helpers
// ---------------------------------------------------------------------------
__device__ __forceinline__ uint32_t h2_as_u32(__half2 h) {
    return *reinterpret_cast<uint32_t*>(&h);
}
__device__ __forceinline__ void cp16g(void* dst_smem, const void* src) {
    uint32_t d = (uint32_t)__cvta_generic_to_shared(dst_smem);
    asm volatile("cp.async.cg.shared.global [%0], [%1], 16;" :: "r"(d), "l"(src));
}
__device__ __forceinline__ void cp_commit() {
    asm volatile("cp.async.commit_group;" ::: "memory");
}
__device__ __forceinline__ void cp_wait1() {
    asm volatile("cp.async.wait_group 1;" ::: "memory");
}
__device__ __forceinline__ void cp_wait2() {
    asm volatile("cp.async.wait_group 2;" ::: "memory");
}
__device__ __forceinline__ void ldsm4(uint32_t& r0, uint32_t& r1, uint32_t& r2, uint32_t& r3, uint32_t a) {
    asm volatile("ldmatrix.sync.aligned.m8n8.x4.shared.b16 {%0,%1,%2,%3}, [%4];"
                 : "=r"(r0), "=r"(r1), "=r"(r2), "=r"(r3) : "r"(a));
}
__device__ __forceinline__ void ldsm4t(uint32_t& r0, uint32_t& r1, uint32_t& r2, uint32_t& r3, uint32_t a) {
    asm volatile("ldmatrix.sync.aligned.m8n8.x4.trans.shared.b16 {%0,%1,%2,%3}, [%4];"
                 : "=r"(r0), "=r"(r1), "=r"(r2), "=r"(r3) : "r"(a));
}
__device__ __forceinline__ void mma16(float* c, uint32_t a0, uint32_t a1, uint32_t a2, uint32_t a3,
                                      uint32_t b0, uint32_t b1) {
    asm volatile(
        "mma.sync.aligned.m16n8k16.row.col.f32.f16.f16.f32 "
        "{%0,%1,%2,%3},{%4,%5,%6,%7},{%8,%9},{%0,%1,%2,%3};"
        : "+f"(c[0]), "+f"(c[1]), "+f"(c[2]), "+f"(c[3])
        : "r"(a0), "r"(a1), "r"(a2), "r"(a3), "r"(b0), "r"(b1));
}

// all-ones fp16x2 B fragment (1.0, 1.0)
#define H2_ONES 0x3C003C00u

// ---------------------------------------------------------------------------
// fp32 -> fp16: all four weight matrices in one launch
// ---------------------------------------------------------------------------
#define N4_WQ (DQ*INNER/4)
#define N4_WK (DC*INNER/4)
#define N4_WV (DC*INNER/4)
#define N4_WO (INNER*DQ/4)
#define N4_TOT (N4_WQ + N4_WK + N4_WV + N4_WO)

__global__ void f2h_all_kernel(const float4* __restrict__ wq, const float4* __restrict__ wk,
                               const float4* __restrict__ wv, const float4* __restrict__ wo)
{
    int i = blockIdx.x * blockDim.x + threadIdx.x;
    if (i >= N4_TOT) return;
    const float4* src;
    __half2* dst;
    int j = i;
    if (j < N4_WQ)                { src = wq; dst = (__half2*)g_wq; }
    else if ((j -= N4_WQ) < N4_WK) { src = wk; dst = (__half2*)g_wk; }
    else if ((j -= N4_WK) < N4_WV) { src = wv; dst = (__half2*)g_wv; }
    else { j -= N4_WV;              src = wo; dst = (__half2*)g_wo; }
    float4 v = src[j];
    dst[2*j]   = __floats2half2_rn(v.x, v.y);
    dst[2*j+1] = __floats2half2_rn(v.z, v.w);
}

// ---------------------------------------------------------------------------
// Warp-per-row LayerNorm, input side (both LNs in one launch, fp16 out).
// ---------------------------------------------------------------------------
__global__ __launch_bounds__(256) void ln_in_dual(
    const float* __restrict__ x,    const float* __restrict__ xg, const float* __restrict__ xb,
    const float* __restrict__ cnd,  const float* __restrict__ cg, const float* __restrict__ cb)
{
    const int warp = threadIdx.x >> 5, lane = threadIdx.x & 31;
    int row = blockIdx.x * 8 + warp;

    const float* in; const float* gw; const float* bw; __half* out; int D;
    if (row < BB * NN) { in = x; gw = xg; bw = xb; out = g_xn; D = DQ; }
    else { row -= BB * NN; in = cnd; gw = cg; bw = cb; out = g_cn; D = DC; }
    const int nv = D / 128;

    const float4* x4 = (const float4*)(in + (size_t)row * D);
    float4 v[6];
    float s = 0.f, sq = 0.f;
    #pragma unroll 6
    for (int i = 0; i < nv; i++) {
        v[i] = x4[lane + 32 * i];
        s  += v[i].x + v[i].y + v[i].z + v[i].w;
        sq += v[i].x * v[i].x + v[i].y * v[i].y + v[i].z * v[i].z + v[i].w * v[i].w;
    }
    #pragma unroll
    for (int off = 16; off; off >>= 1) {
        s  += __shfl_xor_sync(0xffffffffu, s,  off);
        sq += __shfl_xor_sync(0xffffffffu, sq, off);
    }
    const float mu   = s * (1.0f / D);
    const float var  = sq * (1.0f / D) - mu * mu;
    const float rstd = rsqrtf(var + 1e-5f);

    const float4* g4 = (const float4*)gw;
    const float4* b4 = (const float4*)bw;
    __half2* o2 = (__half2*)out + (size_t)row * (D / 2);
    #pragma unroll 6
    for (int i = 0; i < nv; i++) {
        float4 g = g4[lane + 32 * i], b = b4[lane + 32 * i];
        float rx = (v[i].x - mu) * rstd * g.x + b.x;
        float ry = (v[i].y - mu) * rstd * g.y + b.y;
        float rz = (v[i].z - mu) * rstd * g.z + b.z;
        float rw = (v[i].w - mu) * rstd * g.w + b.w;
        o2[(lane + 32 * i) * 2]     = __floats2half2_rn(rx, ry);
        o2[(lane + 32 * i) * 2 + 1] = __floats2half2_rn(rz, rw);
    }
}

// Warp-per-row final LayerNorm (fp32 in/out, D=512)
__global__ __launch_bounds__(256) void ln_out(
    const float* __restrict__ in, const float* __restrict__ gw,
    const float* __restrict__ bw, float* __restrict__ outp)
{
    const int warp = threadIdx.x >> 5, lane = threadIdx.x & 31;
    const int row = blockIdx.x * 8 + warp;

    const float4* x4 = (const float4*)(in + (size_t)row * DQ);
    float4 v[4];
    float s = 0.f, sq = 0.f;
    #pragma unroll
    for (int i = 0; i < 4; i++) {
        v[i] = x4[lane + 32 * i];
        s  += v[i].x + v[i].y + v[i].z + v[i].w;
        sq += v[i].x * v[i].x + v[i].y * v[i].y + v[i].z * v[i].z + v[i].w * v[i].w;
    }
    #pragma unroll
    for (int off = 16; off; off >>= 1) {
        s  += __shfl_xor_sync(0xffffffffu, s,  off);
        sq += __shfl_xor_sync(0xffffffffu, sq, off);
    }
    const float mu   = s * (1.0f / DQ);
    const float var  = sq * (1.0f / DQ) - mu * mu;
    const float rstd = rsqrtf(var + 1e-5f);

    const float4* g4 = (const float4*)gw;
    const float4* b4 = (const float4*)bw;
    float4* o4 = (float4*)(outp + (size_t)row * DQ);
    #pragma unroll
    for (int i = 0; i < 4; i++) {
        float4 g = g4[lane + 32 * i], b = b4[lane + 32 * i], r;
        r.x = (v[i].x - mu) * rstd * g.x + b.x;
        r.y = (v[i].y - mu) * rstd * g.y + b.y;
        r.z = (v[i].z - mu) * rstd * g.z + b.z;
        r.w = (v[i].w - mu) * rstd * g.w + b.w;
        o4[lane + 32 * i] = r;
    }
}

// ---------------------------------------------------------------------------
// GEMM tile config
// ---------------------------------------------------------------------------
#define GS_A 9216                      // 128*72 halves
#define GS_B 8704                      // 64*136 halves
#define GSTG (GS_A + GS_B)             // 17920 halves / stage
#define GEMM_SMEM (3 * GSTG * 2)       // 107520 bytes

// ---------------------------------------------------------------------------
// Merged Q/K/V projection: one launch, grid.z selects {Q,K,V}.
// ---------------------------------------------------------------------------
__global__ __launch_bounds__(256, 2) void qkv_gemm()
{
    extern __shared__ __half smh[];
    const uint32_t sbase = (uint32_t)__cvta_generic_to_shared(smh);

    const __half* A; const __half* W; __half* C; int K; float osc;
    if (blockIdx.z == 0)      { A = g_xn; W = g_wq; C = g_q; K = DQ; osc = QSCALE; }
    else if (blockIdx.z == 1) { A = g_cn; W = g_wk; C = g_k; K = DC; osc = 1.0f; }
    else                      { A = g_cn; W = g_wv; C = g_v; K = DC; osc = 1.0f; }

    const int tid = threadIdx.x;
    const int lane = tid & 31, warp = tid >> 5;
    const int wm = (warp >> 2) * 64;
    const int wn = (warp & 3) * 32;
    const int m0 = blockIdx.y * 128;
    const int n0 = blockIdx.x * 128;
    const int g = lane >> 2, t = lane & 3;

    const int a_row = lane & 15, a_col = (lane >> 4) * 8;
    const int b_row = (lane & 7) + ((lane >> 3) & 1) * 8;
    const int b_col = ((lane >> 4) & 1) * 8;

    float acc[4][4][4];
    #pragma unroll
    for (int i = 0; i < 4; i++)
        #pragma unroll
        for (int j = 0; j < 4; j++)
            #pragma unroll
            for (int q = 0; q < 4; q++) acc[i][j][q] = 0.f;

    auto load_tile = [&](int kt, int buf) {
        int k0 = kt * 64;
        __half* As = smh + buf * GSTG;
        __half* Bs = smh + buf * GSTG + GS_A;
        #pragma unroll
        for (int i = 0; i < 4; i++) {
            int id = tid + i * 256;
            int ar = id >> 3, ac = (id & 7) * 8;
            cp16g(&As[ar * 72 + ac], &A[(size_t)(m0 + ar) * K + k0 + ac]);
            int br = id >> 4, bc = (id & 15) * 8;
            cp16g(&Bs[br * 136 + bc], &W[(size_t)(k0 + br) * INNER + n0 + bc]);
        }
    };

    const int ntiles = K / 64;
    load_tile(0, 0); cp_commit();
    load_tile(1, 1); cp_commit();
    cp_wait1();
    __syncthreads();

    for (int kt = 0; kt < ntiles; kt++) {
        const int cur = kt % 3;
        if (kt + 2 < ntiles) load_tile(kt + 2, (kt + 2) % 3);
        cp_commit();

        const uint32_t abase = sbase + (uint32_t)(cur * GSTG) * 2;
        const uint32_t bbase = abase + (uint32_t)GS_A * 2;

        #pragma unroll
        for (int ks = 0; ks < 4; ks++) {
            uint32_t af[4][4];
            #pragma unroll
            for (int mt = 0; mt < 4; mt++) {
                uint32_t addr = abase +
                    (uint32_t)(((wm + mt * 16 + a_row) * 72 + ks * 16 + a_col) << 1);
                ldsm4(af[mt][0], af[mt][1], af[mt][2], af[mt][3], addr);
            }
            uint32_t bf[8];
            #pragma unroll
            for (int n2 = 0; n2 < 2; n2++) {
                uint32_t addr = bbase +
                    (uint32_t)(((ks * 16 + b_row) * 136 + wn + n2 * 16 + b_col) << 1);
                ldsm4t(bf[n2*4], bf[n2*4+1], bf[n2*4+2], bf[n2*4+3], addr);
            }
            #pragma unroll
            for (int mt = 0; mt < 4; mt++)
                #pragma unroll
                for (int nt = 0; nt < 4; nt++)
                    mma16(acc[mt][nt], af[mt][0], af[mt][1], af[mt][2], af[mt][3],
                          bf[nt*2], bf[nt*2+1]);
        }

        cp_wait1();
        __syncthreads();
    }

    #pragma unroll
    for (int mt = 0; mt < 4; mt++) {
        int row = m0 + wm + mt * 16 + g;
        #pragma unroll
        for (int nt = 0; nt < 4; nt++) {
            int col = n0 + wn + nt * 8 + 2 * t;
            *(__half2*)&C[(size_t)row * INNER + col] =
                __floats2half2_rn(acc[mt][nt][0] * osc, acc[mt][nt][1] * osc);
            *(__half2*)&C[(size_t)(row + 8) * INNER + col] =
                __floats2half2_rn(acc[mt][nt][2] * osc, acc[mt][nt][3] * osc);
        }
    }
}

// ---------------------------------------------------------------------------
// O-projection GEMM (fp32 out + bias + residual)
// ---------------------------------------------------------------------------
__global__ __launch_bounds__(256, 2) void gemm_o(
    const float* __restrict__ bias, const float* __restrict__ resid)
{
    extern __shared__ __half smh[];
    const uint32_t sbase = (uint32_t)__cvta_generic_to_shared(smh);
    const __half* A = g_ao;
    const __half* W = g_wo;
    float* Cf = g_y;
    const int K = INNER, N = DQ;

    const int tid = threadIdx.x;
    const int lane = tid & 31, warp = tid >> 5;
    const int wm = (warp >> 2) * 64;
    const int wn = (warp & 3) * 32;
    const int m0 = blockIdx.y * 128;
    const int n0 = blockIdx.x * 128;
    const int g = lane >> 2, t = lane & 3;

    const int a_row = lane & 15, a_col = (lane >> 4) * 8;
    const int b_row = (lane & 7) + ((lane >> 3) & 1) * 8;
    const int b_col = ((lane >> 4) & 1) * 8;

    float acc[4][4][4];
    #pragma unroll
    for (int i = 0; i < 4; i++)
        #pragma unroll
        for (int j = 0; j < 4; j++)
            #pragma unroll
            for (int q = 0; q < 4; q++) acc[i][j][q] = 0.f;

    auto load_tile = [&](int kt, int buf) {
        int k0 = kt * 64;
        __half* As = smh + buf * GSTG;
        __half* Bs = smh + buf * GSTG + GS_A;
        #pragma unroll
        for (int i = 0; i < 4; i++) {
            int id = tid + i * 256;
            int ar = id >> 3, ac = (id & 7) * 8;
            cp16g(&As[ar * 72 + ac], &A[(size_t)(m0 + ar) * K + k0 + ac]);
            int br = id >> 4, bc = (id & 15) * 8;
            cp16g(&Bs[br * 136 + bc], &W[(size_t)(k0 + br) * N + n0 + bc]);
        }
    };

    const int ntiles = K / 64;
    load_tile(0, 0); cp_commit();
    load_tile(1, 1); cp_commit();
    cp_wait1();
    __syncthreads();

    for (int kt = 0; kt < ntiles; kt++) {
        const int cur = kt % 3;
        if (kt + 2 < ntiles) load_tile(kt + 2, (kt + 2) % 3);
        cp_commit();

        const uint32_t abase = sbase + (uint32_t)(cur * GSTG) * 2;
        const uint32_t bbase = abase + (uint32_t)GS_A * 2;

        #pragma unroll
        for (int ks = 0; ks < 4; ks++) {
            uint32_t af[4][4];
            #pragma unroll
            for (int mt = 0; mt < 4; mt++) {
                uint32_t addr = abase +
                    (uint32_t)(((wm + mt * 16 + a_row) * 72 + ks * 16 + a_col) << 1);
                ldsm4(af[mt][0], af[mt][1], af[mt][2], af[mt][3], addr);
            }
            uint32_t bf[8];
            #pragma unroll
            for (int n2 = 0; n2 < 2; n2++) {
                uint32_t addr = bbase +
                    (uint32_t)(((ks * 16 + b_row) * 136 + wn + n2 * 16 + b_col) << 1);
                ldsm4t(bf[n2*4], bf[n2*4+1], bf[n2*4+2], bf[n2*4+3], addr);
            }
            #pragma unroll
            for (int mt = 0; mt < 4; mt++)
                #pragma unroll
                for (int nt = 0; nt < 4; nt++)
                    mma16(acc[mt][nt], af[mt][0], af[mt][1], af[mt][2], af[mt][3],
                          bf[nt*2], bf[nt*2+1]);
        }

        cp_wait1();
        __syncthreads();
    }

    #pragma unroll
    for (int mt = 0; mt < 4; mt++) {
        int row = m0 + wm + mt * 16 + g;
        #pragma unroll
        for (int nt = 0; nt < 4; nt++) {
            int col = n0 + wn + nt * 8 + 2 * t;
            float2 r01 = { acc[mt][nt][0], acc[mt][nt][1] };
            float2 r23 = { acc[mt][nt][2], acc[mt][nt][3] };
            float2 bb = *(const float2*)&bias[col];
            r01.x += bb.x; r01.y += bb.y;
            r23.x += bb.x; r23.y += bb.y;
            float2 e0 = *(const float2*)&resid[(size_t)row * N + col];
            float2 e1 = *(const float2*)&resid[(size_t)(row + 8) * N + col];
            r01.x += e0.x; r01.y += e0.y;
            r23.x += e1.x; r23.y += e1.y;
            *(float2*)&Cf[(size_t)row * N + col]       = r01;
            *(float2*)&Cf[(size_t)(row + 8) * N + col] = r23;
        }
    }
}

// ---------------------------------------------------------------------------
// fp16 flash attention, FA2 register-P, base-2 f16x2 softmax.
// Softmax denominator computed by the tensor core: one extra mma16 per
// k-group with a constant all-ones B fragment accumulates l in lacc
// (rows g / g+8) -- removes all rs conversions, adds, and shuffles.
// ---------------------------------------------------------------------------
#define KVROWS 128
#define KSTG (KVROWS * 72)                       // 9216 halves (K per stage)
#define STG2 (2 * KSTG)                          // K+V per stage, halves
#define ATTN_SMEM (3 * STG2 * 2)                 // 110592 bytes

__global__ __launch_bounds__(256, 2) void attn_h(
    const __half* __restrict__ Qg, const __half* __restrict__ Kg,
    const __half* __restrict__ Vg, __half* __restrict__ Og)
{
    extern __shared__ __half smh[];
    __half* Qs = smh + 2 * STG2;    // overlaps stage 2 (consumed pre-loop)
    const uint32_t sbase  = (uint32_t)__cvta_generic_to_shared(smh);
    const uint32_t qsbase = (uint32_t)__cvta_generic_to_shared(Qs);

    const int tid  = threadIdx.x;
    const int lane = tid & 31, warp = tid >> 5;
    const int g = lane >> 2, t = lane & 3;
    const int Rr = warp * 16;
    const int it = blockIdx.x, h = blockIdx.y, b = blockIdx.z;

    const __half* qb = Qg + ((size_t)b * NN + it * 128) * INNER + h * DH;
    const __half* kb = Kg + (size_t)b * MM * INNER + h * DH;
    const __half* vb = Vg + (size_t)b * MM * INNER + h * DH;

    const int a_row = lane & 15, a_col = (lane >> 4) * 8;
    const int k_row = (lane & 7) + ((lane >> 4) & 1) * 8;
    const int k_col = ((lane >> 3) & 1) * 8;
    const int v_row = (lane & 7) + ((lane >> 3) & 1) * 8;
    const int v_col = ((lane >> 4) & 1) * 8;

    auto load_chunk = [&](int buf, int j0) {
        __half* Ks = smh + buf * STG2;
        __half* Vs = Ks + KSTG;
        #pragma unroll
        for (int i = 0; i < 4; i++) {
            int id = tid + i * 256;
            int r = id >> 3, c = (id & 7) * 8;
            cp16g(&Ks[r * 72 + c], &kb[(size_t)(j0 + r) * INNER + c]);
            cp16g(&Vs[r * 72 + c], &vb[(size_t)(j0 + r) * INNER + c]);
        }
    };

    #pragma unroll
    for (int i = 0; i < 4; i++) {
        int id = tid + i * 256;
        int r = id >> 3, c = (id & 7) * 8;
        cp16g(&Qs[r * 72 + c], &qb[(size_t)r * INNER + c]);
    }
    cp_commit();                 // group: Q
    load_chunk(0, 0);
    cp_commit();                 // group: chunk0
    load_chunk(1, KVROWS);
    cp_commit();                 // group: chunk1
    cp_wait2();                  // Q resident
    __syncthreads();

    uint32_t qf[4][4];
    #pragma unroll
    for (int ks = 0; ks < 4; ks++) {
        uint32_t addr = qsbase + (uint32_t)(((Rr + a_row) * 72 + ks * 16 + a_col) << 1);
        ldsm4(qf[ks][0], qf[ks][1], qf[ks][2], qf[ks][3], addr);
    }
    __syncthreads();             // Q reads done before stage-2 reload

    float of[8][4];
    #pragma unroll
    for (int i = 0; i < 8; i++)
        #pragma unroll
        for (int q = 0; q < 4; q++) of[i][q] = 0.f;
    float lacc[4] = {0.f, 0.f, 0.f, 0.f};   // l via P @ ones (rows g, g+8)
    float m0r = -INFINITY, m1r = -INFINITY;

    const int nch = MM / KVROWS;   // 16
    for (int ch = 0; ch < nch; ch++) {
        const int cur = ch % 3;
        if (ch + 2 < nch) load_chunk((ch + 2) % 3, (ch + 2) * KVROWS);
        cp_commit();

        const uint32_t kbase = sbase + (uint32_t)(cur * STG2) * 2;
        const uint32_t vbase = kbase + (uint32_t)KSTG * 2;

        #pragma unroll
        for (int sub = 0; sub < 2; sub++) {
            const int roff = sub * 64;

            // S = Q K^T (log2 domain)
            float sacc[8][4];
            #pragma unroll
            for (int i = 0; i < 8; i++)
                #pragma unroll
                for (int q = 0; q < 4; q++) sacc[i][q] = 0.f;
            #pragma unroll
            for (int ks = 0; ks < 4; ks++) {
                #pragma unroll
                for (int n2 = 0; n2 < 4; n2++) {
                    uint32_t kf0, kf1, kf2, kf3;
                    uint32_t addr = kbase +
                        (uint32_t)(((roff + n2 * 16 + k_row) * 72 + ks * 16 + k_col) << 1);
                    ldsm4(kf0, kf1, kf2, kf3, addr);
                    mma16(sacc[n2*2],   qf[ks][0], qf[ks][1], qf[ks][2], qf[ks][3], kf0, kf1);
                    mma16(sacc[n2*2+1], qf[ks][0], qf[ks][1], qf[ks][2], qf[ks][3], kf2, kf3);
                }
            }

            // online softmax (base-2)
            float rmax0 = -INFINITY, rmax1 = -INFINITY;
            #pragma unroll
            for (int nt = 0; nt < 8; nt++) {
                rmax0 = fmaxf(rmax0, fmaxf(sacc[nt][0], sacc[nt][1]));
                rmax1 = fmaxf(rmax1, fmaxf(sacc[nt][2], sacc[nt][3]));
            }
            rmax0 = fmaxf(rmax0, __shfl_xor_sync(0xffffffffu, rmax0, 1));
            rmax0 = fmaxf(rmax0, __shfl_xor_sync(0xffffffffu, rmax0, 2));
            rmax1 = fmaxf(rmax1, __shfl_xor_sync(0xffffffffu, rmax1, 1));
            rmax1 = fmaxf(rmax1, __shfl_xor_sync(0xffffffffu, rmax1, 2));
            float mn0 = fmaxf(m0r, rmax0), mn1 = fmaxf(m1r, rmax1);
            float c0 = exp2f(m0r - mn0), c1 = exp2f(m1r - mn1);
            m0r = mn0; m1r = mn1;

            // exp2 -> fp16 PV A-fragments (no rs bookkeeping needed)
            uint32_t pf[4][4];
            #pragma unroll
            for (int ks = 0; ks < 4; ks++) {
                #pragma unroll
                for (int half = 0; half < 2; half++) {
                    const int nt = 2 * ks + half;
                    __half2 e01 = h2exp2(__floats2half2_rn(sacc[nt][0] - mn0, sacc[nt][1] - mn0));
                    __half2 e23 = h2exp2(__floats2half2_rn(sacc[nt][2] - mn1, sacc[nt][3] - mn1));
                    pf[ks][2*half]   = h2_as_u32(e01);
                    pf[ks][2*half+1] = h2_as_u32(e23);
                }
            }

            // vote-skip rescale of O and l accumulators
            if (__any_sync(0xffffffffu, (c0 != 1.0f) || (c1 != 1.0f))) {
                #pragma unroll
                for (int nt = 0; nt < 8; nt++) {
                    of[nt][0] *= c0; of[nt][1] *= c0;
                    of[nt][2] *= c1; of[nt][3] *= c1;
                }
                lacc[0] *= c0; lacc[1] *= c0;
                lacc[2] *= c1; lacc[3] *= c1;
            }

            // O += P @ V, and l += P @ ones (tensor-core row sums)
            #pragma unroll
            for (int ks = 0; ks < 4; ks++) {
                mma16(lacc, pf[ks][0], pf[ks][1], pf[ks][2], pf[ks][3],
                      H2_ONES, H2_ONES);
                #pragma unroll
                for (int n2 = 0; n2 < 4; n2++) {
                    uint32_t vf0, vf1, vf2, vf3;
                    uint32_t addr = vbase +
                        (uint32_t)(((roff + ks * 16 + v_row) * 72 + n2 * 16 + v_col) << 1);
                    ldsm4t(vf0, vf1, vf2, vf3, addr);
                    mma16(of[n2*2],   pf[ks][0], pf[ks][1], pf[ks][2], pf[ks][3], vf0, vf1);
                    mma16(of[n2*2+1], pf[ks][0], pf[ks][1], pf[ks][2], pf[ks][3], vf2, vf3);
                }
            }
        }

        cp_wait1();
        __syncthreads();
    }

    float inv0 = 1.f / lacc[0], inv1 = 1.f / lacc[2];
    int row0 = it * 128 + Rr + g, row1 = row0 + 8;
    #pragma unroll
    for (int nt = 0; nt < 8; nt++) {
        *(__half2*)&Og[((size_t)b * NN + row0) * INNER + h * DH + nt * 8 + 2 * t] =
            __floats2half2_rn(of[nt][0] * inv0, of[nt][1] * inv0);
        *(__half2*)&Og[((size_t)b * NN + row1) * INNER + h * DH + nt * 8 + 2 * t] =
            __floats2half2_rn(of[nt][2] * inv1, of[nt][3] * inv1);
    }
}

// ---------------------------------------------------------------------------
// Launch
// ---------------------------------------------------------------------------
extern "C" void kernel_launch(void* const* d_in, const int* in_sizes, int n_in,
                              void* d_out, int out_size)
{
    (void)in_sizes; (void)n_in; (void)out_size;
    const float* x     = (const float*)d_in[0];
    const float* cond  = (const float*)d_in[1];
    const float* lnx_g = (const float*)d_in[2];
    const float* lnx_b = (const float*)d_in[3];
    const float* lnc_g = (const float*)d_in[4];
    const float* lnc_b = (const float*)d_in[5];
    const float* Wq    = (const float*)d_in[6];
    const float* Wk    = (const float*)d_in[7];
    const float* Wv    = (const float*)d_in[8];
    const float* Wo    = (const float*)d_in[9];
    const float* bo    = (const float*)d_in[10];
    const float* lnf_g = (const float*)d_in[11];
    const float* lnf_b = (const float*)d_in[12];
    float* out = (float*)d_out;

    __half *q, *k, *v, *ao;
    float *y;
    cudaGetSymbolAddress((void**)&q,  g_q);
    cudaGetSymbolAddress((void**)&k,  g_k);
    cudaGetSymbolAddress((void**)&v,  g_v);
    cudaGetSymbolAddress((void**)&ao, g_ao);
    cudaGetSymbolAddress((void**)&y,  g_y);

    cudaFuncSetAttribute(qkv_gemm, cudaFuncAttributeMaxDynamicSharedMemorySize, GEMM_SMEM);
    cudaFuncSetAttribute(gemm_o,  cudaFuncAttributeMaxDynamicSharedMemorySize, GEMM_SMEM);
    cudaFuncSetAttribute(attn_h,  cudaFuncAttributeMaxDynamicSharedMemorySize, ATTN_SMEM);

    f2h_all_kernel<<<(N4_TOT + 255)/256, 256>>>((const float4*)Wq, (const float4*)Wk,
                                                (const float4*)Wv, (const float4*)Wo);

    ln_in_dual<<<(BB * NN + BB * MM) / 8, 256>>>(x, lnx_g, lnx_b, cond, lnc_g, lnc_b);

    dim3 gthr(256);
    qkv_gemm<<<dim3(INNER / 128, (BB * NN) / 128, 3), gthr, GEMM_SMEM>>>();

    dim3 ga(NN / 128, HH, BB);
    attn_h<<<ga, gthr, ATTN_SMEM>>>(q, k, v, ao);

    gemm_o<<<dim3(DQ / 128, (BB * NN) / 128), gthr, GEMM_SMEM>>>(bo, x);

    ln_out<<<(BB * NN) / 8, 256>>>(y, lnf_g, lnf_b, out);
}

// round 14
// speedup vs baseline: 7.2300x; 1.0030x over previous
#include <cuda_runtime.h>
#include <cuda_fp16.h>
#include <math.h>
#include <stdint.h>

#define BB 4
#define NN 2048
#define MM 2048
#define DQ 512
#define DC 768
#define HH 8
#define DH 64
#define INNER 512

// 0.125 * log2(e): folds attention scale + base-2 exp domain into Q projection.
#define QSCALE 0.18033688011112042f

// ---------------------------------------------------------------------------
// Scratch (device globals -- no allocation allowed)
// ---------------------------------------------------------------------------
__device__ __half g_xn[BB*NN*DQ];
__device__ __half g_cn[BB*MM*DC];
__device__ __half g_q [BB*NN*INNER];
__device__ __half g_k [BB*MM*INNER];
__device__ __half g_v [BB*MM*INNER];
__device__ __half g_ao[BB*NN*INNER];
__device__ float  g_y [BB*NN*DQ];
__device__ __half g_wq[DQ*INNER];
__device__ __half g_wk[DC*INNER];
__device__ __half g_wv[DC*INNER];
__device__ __half g_wo[INNER*DQ];

// ---------------------------------------------------------------------------
// PTX helpers
// ---------------------------------------------------------------------------
__device__ __forceinline__ uint32_t h2_as_u32(__half2 h) {
    return *reinterpret_cast<uint32_t*>(&h);
}
__device__ __forceinline__ void cp16g(void* dst_smem, const void* src) {
    uint32_t d = (uint32_t)__cvta_generic_to_shared(dst_smem);
    asm volatile("cp.async.cg.shared.global [%0], [%1], 16;" :: "r"(d), "l"(src));
}
__device__ __forceinline__ void cp_commit() {
    asm volatile("cp.async.commit_group;" ::: "memory");
}
__device__ __forceinline__ void cp_wait1() {
    asm volatile("cp.async.wait_group 1;" ::: "memory");
}
__device__ __forceinline__ void cp_wait2() {
    asm volatile("cp.async.wait_group 2;" ::: "memory");
}
__device__ __forceinline__ void ldsm4(uint32_t& r0, uint32_t& r1, uint32_t& r2, uint32_t& r3, uint32_t a) {
    asm volatile("ldmatrix.sync.aligned.m8n8.x4.shared.b16 {%0,%1,%2,%3}, [%4];"
                 : "=r"(r0), "=r"(r1), "=r"(r2), "=r"(r3) : "r"(a));
}
__device__ __forceinline__ void ldsm4t(uint32_t& r0, uint32_t& r1, uint32_t& r2, uint32_t& r3, uint32_t a) {
    asm volatile("ldmatrix.sync.aligned.m8n8.x4.trans.shared.b16 {%0,%1,%2,%3}, [%4];"
                 : "=r"(r0), "=r"(r1), "=r"(r2), "=r"(r3) : "r"(a));
}
__device__ __forceinline__ void mma16(float* c, uint32_t a0, uint32_t a1, uint32_t a2, uint32_t a3,
                                      uint32_t b0, uint32_t b1) {
    asm volatile(
        "mma.sync.aligned.m16n8k16.row.col.f32.f16.f16.f32 "
        "{%0,%1,%2,%3},{%4,%5,%6,%7},{%8,%9},{%0,%1,%2,%3};"
        : "+f"(c[0]), "+f"(c[1]), "+f"(c[2]), "+f"(c[3])
        : "r"(a0), "r"(a1), "r"(a2), "r"(a3), "r"(b0), "r"(b1));
}

// all-ones fp16x2 B fragment (1.0, 1.0)
#define H2_ONES 0x3C003C00u

// ---------------------------------------------------------------------------
// fp32 -> fp16: all four weight matrices in one launch
// ---------------------------------------------------------------------------
#define N4_WQ (DQ*INNER/4)
#define N4_WK (DC*INNER/4)
#define N4_WV (DC*INNER/4)
#define N4_WO (INNER*DQ/4)
#define N4_TOT (N4_WQ + N4_WK + N4_WV + N4_WO)

__global__ void f2h_all_kernel(const float4* __restrict__ wq, const float4* __restrict__ wk,
                               const float4* __restrict__ wv, const float4* __restrict__ wo)
{
    int i = blockIdx.x * blockDim.x + threadIdx.x;
    if (i >= N4_TOT) return;
    const float4* src;
    __half2* dst;
    int j = i;
    if (j < N4_WQ)                { src = wq; dst = (__half2*)g_wq; }
    else if ((j -= N4_WQ) < N4_WK) { src = wk; dst = (__half2*)g_wk; }
    else if ((j -= N4_WK) < N4_WV) { src = wv; dst = (__half2*)g_wv; }
    else { j -= N4_WV;              src = wo; dst = (__half2*)g_wo; }
    float4 v = src[j];
    dst[2*j]   = __floats2half2_rn(v.x, v.y);
    dst[2*j+1] = __floats2half2_rn(v.z, v.w);
}

// ---------------------------------------------------------------------------
// Warp-per-row LayerNorm, input side (both LNs in one launch, fp16 out).
// ---------------------------------------------------------------------------
__global__ __launch_bounds__(256) void ln_in_dual(
    const float* __restrict__ x,    const float* __restrict__ xg, const float* __restrict__ xb,
    const float* __restrict__ cnd,  const float* __restrict__ cg, const float* __restrict__ cb)
{
    const int warp = threadIdx.x >> 5, lane = threadIdx.x & 31;
    int row = blockIdx.x * 8 + warp;

    const float* in; const float* gw; const float* bw; __half* out; int D;
    if (row < BB * NN) { in = x; gw = xg; bw = xb; out = g_xn; D = DQ; }
    else { row -= BB * NN; in = cnd; gw = cg; bw = cb; out = g_cn; D = DC; }
    const int nv = D / 128;

    const float4* x4 = (const float4*)(in + (size_t)row * D);
    float4 v[6];
    float s = 0.f, sq = 0.f;
    #pragma unroll 6
    for (int i = 0; i < nv; i++) {
        v[i] = x4[lane + 32 * i];
        s  += v[i].x + v[i].y + v[i].z + v[i].w;
        sq += v[i].x * v[i].x + v[i].y * v[i].y + v[i].z * v[i].z + v[i].w * v[i].w;
    }
    #pragma unroll
    for (int off = 16; off; off >>= 1) {
        s  += __shfl_xor_sync(0xffffffffu, s,  off);
        sq += __shfl_xor_sync(0xffffffffu, sq, off);
    }
    const float mu   = s * (1.0f / D);
    const float var  = sq * (1.0f / D) - mu * mu;
    const float rstd = rsqrtf(var + 1e-5f);

    const float4* g4 = (const float4*)gw;
    const float4* b4 = (const float4*)bw;
    __half2* o2 = (__half2*)out + (size_t)row * (D / 2);
    #pragma unroll 6
    for (int i = 0; i < nv; i++) {
        float4 g = g4[lane + 32 * i], b = b4[lane + 32 * i];
        float rx = (v[i].x - mu) * rstd * g.x + b.x;
        float ry = (v[i].y - mu) * rstd * g.y + b.y;
        float rz = (v[i].z - mu) * rstd * g.z + b.z;
        float rw = (v[i].w - mu) * rstd * g.w + b.w;
        o2[(lane + 32 * i) * 2]     = __floats2half2_rn(rx, ry);
        o2[(lane + 32 * i) * 2 + 1] = __floats2half2_rn(rz, rw);
    }
}

// Warp-per-row final LayerNorm (fp32 in/out, D=512)
__global__ __launch_bounds__(256) void ln_out(
    const float* __restrict__ in, const float* __restrict__ gw,
    const float* __restrict__ bw, float* __restrict__ outp)
{
    const int warp = threadIdx.x >> 5, lane = threadIdx.x & 31;
    const int row = blockIdx.x * 8 + warp;

    const float4* x4 = (const float4*)(in + (size_t)row * DQ);
    float4 v[4];
    float s = 0.f, sq = 0.f;
    #pragma unroll
    for (int i = 0; i < 4; i++) {
        v[i] = x4[lane + 32 * i];
        s  += v[i].x + v[i].y + v[i].z + v[i].w;
        sq += v[i].x * v[i].x + v[i].y * v[i].y + v[i].z * v[i].z + v[i].w * v[i].w;
    }
    #pragma unroll
    for (int off = 16; off; off >>= 1) {
        s  += __shfl_xor_sync(0xffffffffu, s,  off);
        sq += __shfl_xor_sync(0xffffffffu, sq, off);
    }
    const float mu   = s * (1.0f / DQ);
    const float var  = sq * (1.0f / DQ) - mu * mu;
    const float rstd = rsqrtf(var + 1e-5f);

    const float4* g4 = (const float4*)gw;
    const float4* b4 = (const float4*)bw;
    float4* o4 = (float4*)(outp + (size_t)row * DQ);
    #pragma unroll
    for (int i = 0; i < 4; i++) {
        float4 g = g4[lane + 32 * i], b = b4[lane + 32 * i], r;
        r.x = (v[i].x - mu) * rstd * g.x + b.x;
        r.y = (v[i].y - mu) * rstd * g.y + b.y;
        r.z = (v[i].z - mu) * rstd * g.z + b.z;
        r.w = (v[i].w - mu) * rstd * g.w + b.w;
        o4[lane + 32 * i] = r;
    }
}

// ---------------------------------------------------------------------------
// GEMM tile config
// ---------------------------------------------------------------------------
#define GS_A 9216                      // 128*72 halves
#define GS_B 8704                      // 64*136 halves
#define GSTG (GS_A + GS_B)             // 17920 halves / stage
#define GEMM_SMEM (3 * GSTG * 2)       // 107520 bytes

// ---------------------------------------------------------------------------
// Merged Q/K/V projection: one launch, grid.z selects {Q,K,V}.
// ---------------------------------------------------------------------------
__global__ __launch_bounds__(256, 2) void qkv_gemm()
{
    extern __shared__ __half smh[];
    const uint32_t sbase = (uint32_t)__cvta_generic_to_shared(smh);

    const __half* A; const __half* W; __half* C; int K; float osc;
    if (blockIdx.z == 0)      { A = g_xn; W = g_wq; C = g_q; K = DQ; osc = QSCALE; }
    else if (blockIdx.z == 1) { A = g_cn; W = g_wk; C = g_k; K = DC; osc = 1.0f; }
    else                      { A = g_cn; W = g_wv; C = g_v; K = DC; osc = 1.0f; }

    const int tid = threadIdx.x;
    const int lane = tid & 31, warp = tid >> 5;
    const int wm = (warp >> 2) * 64;
    const int wn = (warp & 3) * 32;
    const int m0 = blockIdx.y * 128;
    const int n0 = blockIdx.x * 128;
    const int g = lane >> 2, t = lane & 3;

    const int a_row = lane & 15, a_col = (lane >> 4) * 8;
    const int b_row = (lane & 7) + ((lane >> 3) & 1) * 8;
    const int b_col = ((lane >> 4) & 1) * 8;

    float acc[4][4][4];
    #pragma unroll
    for (int i = 0; i < 4; i++)
        #pragma unroll
        for (int j = 0; j < 4; j++)
            #pragma unroll
            for (int q = 0; q < 4; q++) acc[i][j][q] = 0.f;

    auto load_tile = [&](int kt, int buf) {
        int k0 = kt * 64;
        __half* As = smh + buf * GSTG;
        __half* Bs = smh + buf * GSTG + GS_A;
        #pragma unroll
        for (int i = 0; i < 4; i++) {
            int id = tid + i * 256;
            int ar = id >> 3, ac = (id & 7) * 8;
            cp16g(&As[ar * 72 + ac], &A[(size_t)(m0 + ar) * K + k0 + ac]);
            int br = id >> 4, bc = (id & 15) * 8;
            cp16g(&Bs[br * 136 + bc], &W[(size_t)(k0 + br) * INNER + n0 + bc]);
        }
    };

    const int ntiles = K / 64;
    load_tile(0, 0); cp_commit();
    load_tile(1, 1); cp_commit();
    cp_wait1();
    __syncthreads();

    for (int kt = 0; kt < ntiles; kt++) {
        const int cur = kt % 3;
        if (kt + 2 < ntiles) load_tile(kt + 2, (kt + 2) % 3);
        cp_commit();

        const uint32_t abase = sbase + (uint32_t)(cur * GSTG) * 2;
        const uint32_t bbase = abase + (uint32_t)GS_A * 2;

        #pragma unroll
        for (int ks = 0; ks < 4; ks++) {
            uint32_t af[4][4];
            #pragma unroll
            for (int mt = 0; mt < 4; mt++) {
                uint32_t addr = abase +
                    (uint32_t)(((wm + mt * 16 + a_row) * 72 + ks * 16 + a_col) << 1);
                ldsm4(af[mt][0], af[mt][1], af[mt][2], af[mt][3], addr);
            }
            uint32_t bf[8];
            #pragma unroll
            for (int n2 = 0; n2 < 2; n2++) {
                uint32_t addr = bbase +
                    (uint32_t)(((ks * 16 + b_row) * 136 + wn + n2 * 16 + b_col) << 1);
                ldsm4t(bf[n2*4], bf[n2*4+1], bf[n2*4+2], bf[n2*4+3], addr);
            }
            #pragma unroll
            for (int mt = 0; mt < 4; mt++)
                #pragma unroll
                for (int nt = 0; nt < 4; nt++)
                    mma16(acc[mt][nt], af[mt][0], af[mt][1], af[mt][2], af[mt][3],
                          bf[nt*2], bf[nt*2+1]);
        }

        cp_wait1();
        __syncthreads();
    }

    #pragma unroll
    for (int mt = 0; mt < 4; mt++) {
        int row = m0 + wm + mt * 16 + g;
        #pragma unroll
        for (int nt = 0; nt < 4; nt++) {
            int col = n0 + wn + nt * 8 + 2 * t;
            *(__half2*)&C[(size_t)row * INNER + col] =
                __floats2half2_rn(acc[mt][nt][0] * osc, acc[mt][nt][1] * osc);
            *(__half2*)&C[(size_t)(row + 8) * INNER + col] =
                __floats2half2_rn(acc[mt][nt][2] * osc, acc[mt][nt][3] * osc);
        }
    }
}

// ---------------------------------------------------------------------------
// O-projection GEMM (fp32 out + bias + residual)
// ---------------------------------------------------------------------------
__global__ __launch_bounds__(256, 2) void gemm_o(
    const float* __restrict__ bias, const float* __restrict__ resid)
{
    extern __shared__ __half smh[];
    const uint32_t sbase = (uint32_t)__cvta_generic_to_shared(smh);
    const __half* A = g_ao;
    const __half* W = g_wo;
    float* Cf = g_y;
    const int K = INNER, N = DQ;

    const int tid = threadIdx.x;
    const int lane = tid & 31, warp = tid >> 5;
    const int wm = (warp >> 2) * 64;
    const int wn = (warp & 3) * 32;
    const int m0 = blockIdx.y * 128;
    const int n0 = blockIdx.x * 128;
    const int g = lane >> 2, t = lane & 3;

    const int a_row = lane & 15, a_col = (lane >> 4) * 8;
    const int b_row = (lane & 7) + ((lane >> 3) & 1) * 8;
    const int b_col = ((lane >> 4) & 1) * 8;

    float acc[4][4][4];
    #pragma unroll
    for (int i = 0; i < 4; i++)
        #pragma unroll
        for (int j = 0; j < 4; j++)
            #pragma unroll
            for (int q = 0; q < 4; q++) acc[i][j][q] = 0.f;

    auto load_tile = [&](int kt, int buf) {
        int k0 = kt * 64;
        __half* As = smh + buf * GSTG;
        __half* Bs = smh + buf * GSTG + GS_A;
        #pragma unroll
        for (int i = 0; i < 4; i++) {
            int id = tid + i * 256;
            int ar = id >> 3, ac = (id & 7) * 8;
            cp16g(&As[ar * 72 + ac], &A[(size_t)(m0 + ar) * K + k0 + ac]);
            int br = id >> 4, bc = (id & 15) * 8;
            cp16g(&Bs[br * 136 + bc], &W[(size_t)(k0 + br) * N + n0 + bc]);
        }
    };

    const int ntiles = K / 64;
    load_tile(0, 0); cp_commit();
    load_tile(1, 1); cp_commit();
    cp_wait1();
    __syncthreads();

    for (int kt = 0; kt < ntiles; kt++) {
        const int cur = kt % 3;
        if (kt + 2 < ntiles) load_tile(kt + 2, (kt + 2) % 3);
        cp_commit();

        const uint32_t abase = sbase + (uint32_t)(cur * GSTG) * 2;
        const uint32_t bbase = abase + (uint32_t)GS_A * 2;

        #pragma unroll
        for (int ks = 0; ks < 4; ks++) {
            uint32_t af[4][4];
            #pragma unroll
            for (int mt = 0; mt < 4; mt++) {
                uint32_t addr = abase +
                    (uint32_t)(((wm + mt * 16 + a_row) * 72 + ks * 16 + a_col) << 1);
                ldsm4(af[mt][0], af[mt][1], af[mt][2], af[mt][3], addr);
            }
            uint32_t bf[8];
            #pragma unroll
            for (int n2 = 0; n2 < 2; n2++) {
                uint32_t addr = bbase +
                    (uint32_t)(((ks * 16 + b_row) * 136 + wn + n2 * 16 + b_col) << 1);
                ldsm4t(bf[n2*4], bf[n2*4+1], bf[n2*4+2], bf[n2*4+3], addr);
            }
            #pragma unroll
            for (int mt = 0; mt < 4; mt++)
                #pragma unroll
                for (int nt = 0; nt < 4; nt++)
                    mma16(acc[mt][nt], af[mt][0], af[mt][1], af[mt][2], af[mt][3],
                          bf[nt*2], bf[nt*2+1]);
        }

        cp_wait1();
        __syncthreads();
    }

    #pragma unroll
    for (int mt = 0; mt < 4; mt++) {
        int row = m0 + wm + mt * 16 + g;
        #pragma unroll
        for (int nt = 0; nt < 4; nt++) {
            int col = n0 + wn + nt * 8 + 2 * t;
            float2 r01 = { acc[mt][nt][0], acc[mt][nt][1] };
            float2 r23 = { acc[mt][nt][2], acc[mt][nt][3] };
            float2 bb = *(const float2*)&bias[col];
            r01.x += bb.x; r01.y += bb.y;
            r23.x += bb.x; r23.y += bb.y;
            float2 e0 = *(const float2*)&resid[(size_t)row * N + col];
            float2 e1 = *(const float2*)&resid[(size_t)(row + 8) * N + col];
            r01.x += e0.x; r01.y += e0.y;
            r23.x += e1.x; r23.y += e1.y;
            *(float2*)&Cf[(size_t)row * N + col]       = r01;
            *(float2*)&Cf[(size_t)(row + 8) * N + col] = r23;
        }
    }
}

// ---------------------------------------------------------------------------
// fp16 flash attention, FA2 register-P, base-2 f16x2 softmax, tensor-core l.
// NEW: record-max vote -- when no lane's local max beats the running max,
// skip the shuffle chain, correction exp2s, and rescale entirely (exact).
// ---------------------------------------------------------------------------
#define KVROWS 128
#define KSTG (KVROWS * 72)                       // 9216 halves (K per stage)
#define STG2 (2 * KSTG)                          // K+V per stage, halves
#define ATTN_SMEM (3 * STG2 * 2)                 // 110592 bytes

__global__ __launch_bounds__(256, 2) void attn_h(
    const __half* __restrict__ Qg, const __half* __restrict__ Kg,
    const __half* __restrict__ Vg, __half* __restrict__ Og)
{
    extern __shared__ __half smh[];
    __half* Qs = smh + 2 * STG2;    // overlaps stage 2 (consumed pre-loop)
    const uint32_t sbase  = (uint32_t)__cvta_generic_to_shared(smh);
    const uint32_t qsbase = (uint32_t)__cvta_generic_to_shared(Qs);

    const int tid  = threadIdx.x;
    const int lane = tid & 31, warp = tid >> 5;
    const int g = lane >> 2, t = lane & 3;
    const int Rr = warp * 16;
    const int it = blockIdx.x, h = blockIdx.y, b = blockIdx.z;

    const __half* qb = Qg + ((size_t)b * NN + it * 128) * INNER + h * DH;
    const __half* kb = Kg + (size_t)b * MM * INNER + h * DH;
    const __half* vb = Vg + (size_t)b * MM * INNER + h * DH;

    const int a_row = lane & 15, a_col = (lane >> 4) * 8;
    const int k_row = (lane & 7) + ((lane >> 4) & 1) * 8;
    const int k_col = ((lane >> 3) & 1) * 8;
    const int v_row = (lane & 7) + ((lane >> 3) & 1) * 8;
    const int v_col = ((lane >> 4) & 1) * 8;

    auto load_chunk = [&](int buf, int j0) {
        __half* Ks = smh + buf * STG2;
        __half* Vs = Ks + KSTG;
        #pragma unroll
        for (int i = 0; i < 4; i++) {
            int id = tid + i * 256;
            int r = id >> 3, c = (id & 7) * 8;
            cp16g(&Ks[r * 72 + c], &kb[(size_t)(j0 + r) * INNER + c]);
            cp16g(&Vs[r * 72 + c], &vb[(size_t)(j0 + r) * INNER + c]);
        }
    };

    #pragma unroll
    for (int i = 0; i < 4; i++) {
        int id = tid + i * 256;
        int r = id >> 3, c = (id & 7) * 8;
        cp16g(&Qs[r * 72 + c], &qb[(size_t)r * INNER + c]);
    }
    cp_commit();                 // group: Q
    load_chunk(0, 0);
    cp_commit();                 // group: chunk0
    load_chunk(1, KVROWS);
    cp_commit();                 // group: chunk1
    cp_wait2();                  // Q resident
    __syncthreads();

    uint32_t qf[4][4];
    #pragma unroll
    for (int ks = 0; ks < 4; ks++) {
        uint32_t addr = qsbase + (uint32_t)(((Rr + a_row) * 72 + ks * 16 + a_col) << 1);
        ldsm4(qf[ks][0], qf[ks][1], qf[ks][2], qf[ks][3], addr);
    }
    __syncthreads();             // Q reads done before stage-2 reload

    float of[8][4];
    #pragma unroll
    for (int i = 0; i < 8; i++)
        #pragma unroll
        for (int q = 0; q < 4; q++) of[i][q] = 0.f;
    float lacc[4] = {0.f, 0.f, 0.f, 0.f};   // l via P @ ones (rows g, g+8)
    float m0r = -INFINITY, m1r = -INFINITY;

    const int nch = MM / KVROWS;   // 16
    for (int ch = 0; ch < nch; ch++) {
        const int cur = ch % 3;
        if (ch + 2 < nch) load_chunk((ch + 2) % 3, (ch + 2) * KVROWS);
        cp_commit();

        const uint32_t kbase = sbase + (uint32_t)(cur * STG2) * 2;
        const uint32_t vbase = kbase + (uint32_t)KSTG * 2;

        #pragma unroll
        for (int sub = 0; sub < 2; sub++) {
            const int roff = sub * 64;

            // S = Q K^T (log2 domain)
            float sacc[8][4];
            #pragma unroll
            for (int i = 0; i < 8; i++)
                #pragma unroll
                for (int q = 0; q < 4; q++) sacc[i][q] = 0.f;
            #pragma unroll
            for (int ks = 0; ks < 4; ks++) {
                #pragma unroll
                for (int n2 = 0; n2 < 4; n2++) {
                    uint32_t kf0, kf1, kf2, kf3;
                    uint32_t addr = kbase +
                        (uint32_t)(((roff + n2 * 16 + k_row) * 72 + ks * 16 + k_col) << 1);
                    ldsm4(kf0, kf1, kf2, kf3, addr);
                    mma16(sacc[n2*2],   qf[ks][0], qf[ks][1], qf[ks][2], qf[ks][3], kf0, kf1);
                    mma16(sacc[n2*2+1], qf[ks][0], qf[ks][1], qf[ks][2], qf[ks][3], kf2, kf3);
                }
            }

            // local max per row-group (needed regardless)
            float rmax0 = -INFINITY, rmax1 = -INFINITY;
            #pragma unroll
            for (int nt = 0; nt < 8; nt++) {
                rmax0 = fmaxf(rmax0, fmaxf(sacc[nt][0], sacc[nt][1]));
                rmax1 = fmaxf(rmax1, fmaxf(sacc[nt][2], sacc[nt][3]));
            }

            // record-max vote: if no lane beats its running max, the quad max
            // can't either -> mn == m exactly, c == 1, nothing to rescale.
            float mn0 = m0r, mn1 = m1r;
            if (__any_sync(0xffffffffu, (rmax0 > m0r) || (rmax1 > m1r))) {
                rmax0 = fmaxf(rmax0, __shfl_xor_sync(0xffffffffu, rmax0, 1));
                rmax0 = fmaxf(rmax0, __shfl_xor_sync(0xffffffffu, rmax0, 2));
                rmax1 = fmaxf(rmax1, __shfl_xor_sync(0xffffffffu, rmax1, 1));
                rmax1 = fmaxf(rmax1, __shfl_xor_sync(0xffffffffu, rmax1, 2));
                mn0 = fmaxf(m0r, rmax0);
                mn1 = fmaxf(m1r, rmax1);
                float c0 = exp2f(m0r - mn0), c1 = exp2f(m1r - mn1);
                m0r = mn0; m1r = mn1;
                #pragma unroll
                for (int nt = 0; nt < 8; nt++) {
                    of[nt][0] *= c0; of[nt][1] *= c0;
                    of[nt][2] *= c1; of[nt][3] *= c1;
                }
                lacc[0] *= c0;
                lacc[2] *= c1;
            }

            // exp2 -> fp16 PV A-fragments
            uint32_t pf[4][4];
            #pragma unroll
            for (int ks = 0; ks < 4; ks++) {
                #pragma unroll
                for (int half = 0; half < 2; half++) {
                    const int nt = 2 * ks + half;
                    __half2 e01 = h2exp2(__floats2half2_rn(sacc[nt][0] - mn0, sacc[nt][1] - mn0));
                    __half2 e23 = h2exp2(__floats2half2_rn(sacc[nt][2] - mn1, sacc[nt][3] - mn1));
                    pf[ks][2*half]   = h2_as_u32(e01);
                    pf[ks][2*half+1] = h2_as_u32(e23);
                }
            }

            // O += P @ V, and l += P @ ones (tensor-core row sums)
            #pragma unroll
            for (int ks = 0; ks < 4; ks++) {
                mma16(lacc, pf[ks][0], pf[ks][1], pf[ks][2], pf[ks][3],
                      H2_ONES, H2_ONES);
                #pragma unroll
                for (int n2 = 0; n2 < 4; n2++) {
                    uint32_t vf0, vf1, vf2, vf3;
                    uint32_t addr = vbase +
                        (uint32_t)(((roff + ks * 16 + v_row) * 72 + n2 * 16 + v_col) << 1);
                    ldsm4t(vf0, vf1, vf2, vf3, addr);
                    mma16(of[n2*2],   pf[ks][0], pf[ks][1], pf[ks][2], pf[ks][3], vf0, vf1);
                    mma16(of[n2*2+1], pf[ks][0], pf[ks][1], pf[ks][2], pf[ks][3], vf2, vf3);
                }
            }
        }

        cp_wait1();
        __syncthreads();
    }

    float inv0 = 1.f / lacc[0], inv1 = 1.f / lacc[2];
    int row0 = it * 128 + Rr + g, row1 = row0 + 8;
    #pragma unroll
    for (int nt = 0; nt < 8; nt++) {
        *(__half2*)&Og[((size_t)b * NN + row0) * INNER + h * DH + nt * 8 + 2 * t] =
            __floats2half2_rn(of[nt][0] * inv0, of[nt][1] * inv0);
        *(__half2*)&Og[((size_t)b * NN + row1) * INNER + h * DH + nt * 8 + 2 * t] =
            __floats2half2_rn(of[nt][2] * inv1, of[nt][3] * inv1);
    }
}

// ---------------------------------------------------------------------------
// Launch
// ---------------------------------------------------------------------------
extern "C" void kernel_launch(void* const* d_in, const int* in_sizes, int n_in,
                              void* d_out, int out_size)
{
    (void)in_sizes; (void)n_in; (void)out_size;
    const float* x     = (const float*)d_in[0];
    const float* cond  = (const float*)d_in[1];
    const float* lnx_g = (const float*)d_in[2];
    const float* lnx_b = (const float*)d_in[3];
    const float* lnc_g = (const float*)d_in[4];
    const float* lnc_b = (const float*)d_in[5];
    const float* Wq    = (const float*)d_in[6];
    const float* Wk    = (const float*)d_in[7];
    const float* Wv    = (const float*)d_in[8];
    const float* Wo    = (const float*)d_in[9];
    const float* bo    = (const float*)d_in[10];
    const float* lnf_g = (const float*)d_in[11];
    const float* lnf_b = (const float*)d_in[12];
    float* out = (float*)d_out;

    __half *q, *k, *v, *ao;
    float *y;
    cudaGetSymbolAddress((void**)&q,  g_q);
    cudaGetSymbolAddress((void**)&k,  g_k);
    cudaGetSymbolAddress((void**)&v,  g_v);
    cudaGetSymbolAddress((void**)&ao, g_ao);
    cudaGetSymbolAddress((void**)&y,  g_y);

    cudaFuncSetAttribute(qkv_gemm, cudaFuncAttributeMaxDynamicSharedMemorySize, GEMM_SMEM);
    cudaFuncSetAttribute(gemm_o,  cudaFuncAttributeMaxDynamicSharedMemorySize, GEMM_SMEM);
    cudaFuncSetAttribute(attn_h,  cudaFuncAttributeMaxDynamicSharedMemorySize, ATTN_SMEM);

    f2h_all_kernel<<<(N4_TOT + 255)/256, 256>>>((const float4*)Wq, (const float4*)Wk,
                                                (const float4*)Wv, (const float4*)Wo);

    ln_in_dual<<<(BB * NN + BB * MM) / 8, 256>>>(x, lnx_g, lnx_b, cond, lnc_g, lnc_b);

    dim3 gthr(256);
    qkv_gemm<<<dim3(INNER / 128, (BB * NN) / 128, 3), gthr, GEMM_SMEM>>>();

    dim3 ga(NN / 128, HH, BB);
    attn_h<<<ga, gthr, ATTN_SMEM>>>(q, k, v, ao);

    gemm_o<<<dim3(DQ / 128, (BB * NN) / 128), gthr, GEMM_SMEM>>>(bo, x);

    ln_out<<<(BB * NN) / 8, 256>>>(y, lnf_g, lnf_b, out);
}

// round 15
// speedup vs baseline: 7.4219x; 1.0265x over previous
#include <cuda_runtime.h>
#include <cuda_fp16.h>
#include <math.h>
#include <stdint.h>

#define BB 4
#define NN 2048
#define MM 2048
#define DQ 512
#define DC 768
#define HH 8
#define DH 64
#define INNER 512

// 0.125 * log2(e): folds attention scale + base-2 exp domain into Q projection.
#define QSCALE 0.18033688011112042f

// ---------------------------------------------------------------------------
// Scratch (device globals -- no allocation allowed)
// ---------------------------------------------------------------------------
__device__ __half g_xn[BB*NN*DQ];
__device__ __half g_cn[BB*MM*DC];
__device__ __half g_q [BB*NN*INNER];
__device__ __half g_k [BB*MM*INNER];
__device__ __half g_v [BB*MM*INNER];
__device__ __half g_ao[BB*NN*INNER];
__device__ float  g_y [BB*NN*DQ];
__device__ __half g_wq[DQ*INNER];
__device__ __half g_wk[DC*INNER];
__device__ __half g_wv[DC*INNER];
__device__ __half g_wo[INNER*DQ];

// ---------------------------------------------------------------------------
// PTX helpers
// ---------------------------------------------------------------------------
__device__ __forceinline__ uint32_t h2_as_u32(__half2 h) {
    return *reinterpret_cast<uint32_t*>(&h);
}
__device__ __forceinline__ void cp16g(void* dst_smem, const void* src) {
    uint32_t d = (uint32_t)__cvta_generic_to_shared(dst_smem);
    asm volatile("cp.async.cg.shared.global [%0], [%1], 16;" :: "r"(d), "l"(src));
}
__device__ __forceinline__ void cp_commit() {
    asm volatile("cp.async.commit_group;" ::: "memory");
}
__device__ __forceinline__ void cp_wait1() {
    asm volatile("cp.async.wait_group 1;" ::: "memory");
}
__device__ __forceinline__ void cp_wait2() {
    asm volatile("cp.async.wait_group 2;" ::: "memory");
}
__device__ __forceinline__ void ldsm4(uint32_t& r0, uint32_t& r1, uint32_t& r2, uint32_t& r3, uint32_t a) {
    asm volatile("ldmatrix.sync.aligned.m8n8.x4.shared.b16 {%0,%1,%2,%3}, [%4];"
                 : "=r"(r0), "=r"(r1), "=r"(r2), "=r"(r3) : "r"(a));
}
__device__ __forceinline__ void ldsm4t(uint32_t& r0, uint32_t& r1, uint32_t& r2, uint32_t& r3, uint32_t a) {
    asm volatile("ldmatrix.sync.aligned.m8n8.x4.trans.shared.b16 {%0,%1,%2,%3}, [%4];"
                 : "=r"(r0), "=r"(r1), "=r"(r2), "=r"(r3) : "r"(a));
}
__device__ __forceinline__ void mma16(float* c, uint32_t a0, uint32_t a1, uint32_t a2, uint32_t a3,
                                      uint32_t b0, uint32_t b1) {
    asm volatile(
        "mma.sync.aligned.m16n8k16.row.col.f32.f16.f16.f32 "
        "{%0,%1,%2,%3},{%4,%5,%6,%7},{%8,%9},{%0,%1,%2,%3};"
        : "+f"(c[0]), "+f"(c[1]), "+f"(c[2]), "+f"(c[3])
        : "r"(a0), "r"(a1), "r"(a2), "r"(a3), "r"(b0), "r"(b1));
}

// all-ones fp16x2 B fragment (1.0, 1.0)
#define H2_ONES 0x3C003C00u

// ---------------------------------------------------------------------------
// Fused prep: input LayerNorms (warp-per-row) + weight f2h, one launch.
// Blocks [0, LN_BLK): LN rows.  Blocks [LN_BLK, LN_BLK+F2H_BLK): f2h.
// ---------------------------------------------------------------------------
#define LN_ROWS (BB*NN + BB*MM)          // 16384
#define LN_BLK  (LN_ROWS / 8)            // 2048
#define N4_WQ (DQ*INNER/4)
#define N4_WK (DC*INNER/4)
#define N4_WV (DC*INNER/4)
#define N4_WO (INNER*DQ/4)
#define N4_TOT (N4_WQ + N4_WK + N4_WV + N4_WO)   // 327680
#define F2H_BLK ((N4_TOT + 255) / 256)   // 1280

__global__ __launch_bounds__(256) void prep_kernel(
    const float* __restrict__ x,    const float* __restrict__ xg, const float* __restrict__ xb,
    const float* __restrict__ cnd,  const float* __restrict__ cg, const float* __restrict__ cb,
    const float4* __restrict__ wq, const float4* __restrict__ wk,
    const float4* __restrict__ wv, const float4* __restrict__ wo)
{
    if (blockIdx.x >= LN_BLK) {
        // f2h branch
        int i = (blockIdx.x - LN_BLK) * blockDim.x + threadIdx.x;
        if (i >= N4_TOT) return;
        const float4* src;
        __half2* dst;
        int j = i;
        if (j < N4_WQ)                 { src = wq; dst = (__half2*)g_wq; }
        else if ((j -= N4_WQ) < N4_WK) { src = wk; dst = (__half2*)g_wk; }
        else if ((j -= N4_WK) < N4_WV) { src = wv; dst = (__half2*)g_wv; }
        else { j -= N4_WV;               src = wo; dst = (__half2*)g_wo; }
        float4 v = src[j];
        dst[2*j]   = __floats2half2_rn(v.x, v.y);
        dst[2*j+1] = __floats2half2_rn(v.z, v.w);
        return;
    }

    // LN branch: warp per row
    const int warp = threadIdx.x >> 5, lane = threadIdx.x & 31;
    int row = blockIdx.x * 8 + warp;

    const float* in; const float* gw; const float* bw; __half* out; int D;
    if (row < BB * NN) { in = x; gw = xg; bw = xb; out = g_xn; D = DQ; }
    else { row -= BB * NN; in = cnd; gw = cg; bw = cb; out = g_cn; D = DC; }
    const int nv = D / 128;

    const float4* x4 = (const float4*)(in + (size_t)row * D);
    float4 v[6];
    float s = 0.f, sq = 0.f;
    #pragma unroll 6
    for (int i = 0; i < nv; i++) {
        v[i] = x4[lane + 32 * i];
        s  += v[i].x + v[i].y + v[i].z + v[i].w;
        sq += v[i].x * v[i].x + v[i].y * v[i].y + v[i].z * v[i].z + v[i].w * v[i].w;
    }
    #pragma unroll
    for (int off = 16; off; off >>= 1) {
        s  += __shfl_xor_sync(0xffffffffu, s,  off);
        sq += __shfl_xor_sync(0xffffffffu, sq, off);
    }
    const float mu   = s * (1.0f / D);
    const float var  = sq * (1.0f / D) - mu * mu;
    const float rstd = rsqrtf(var + 1e-5f);

    const float4* g4 = (const float4*)gw;
    const float4* b4 = (const float4*)bw;
    __half2* o2 = (__half2*)out + (size_t)row * (D / 2);
    #pragma unroll 6
    for (int i = 0; i < nv; i++) {
        float4 g = g4[lane + 32 * i], b = b4[lane + 32 * i];
        float rx = (v[i].x - mu) * rstd * g.x + b.x;
        float ry = (v[i].y - mu) * rstd * g.y + b.y;
        float rz = (v[i].z - mu) * rstd * g.z + b.z;
        float rw = (v[i].w - mu) * rstd * g.w + b.w;
        o2[(lane + 32 * i) * 2]     = __floats2half2_rn(rx, ry);
        o2[(lane + 32 * i) * 2 + 1] = __floats2half2_rn(rz, rw);
    }
}

// Warp-per-row final LayerNorm (fp32 in/out, D=512)
__global__ __launch_bounds__(256) void ln_out(
    const float* __restrict__ in, const float* __restrict__ gw,
    const float* __restrict__ bw, float* __restrict__ outp)
{
    const int warp = threadIdx.x >> 5, lane = threadIdx.x & 31;
    const int row = blockIdx.x * 8 + warp;

    const float4* x4 = (const float4*)(in + (size_t)row * DQ);
    float4 v[4];
    float s = 0.f, sq = 0.f;
    #pragma unroll
    for (int i = 0; i < 4; i++) {
        v[i] = x4[lane + 32 * i];
        s  += v[i].x + v[i].y + v[i].z + v[i].w;
        sq += v[i].x * v[i].x + v[i].y * v[i].y + v[i].z * v[i].z + v[i].w * v[i].w;
    }
    #pragma unroll
    for (int off = 16; off; off >>= 1) {
        s  += __shfl_xor_sync(0xffffffffu, s,  off);
        sq += __shfl_xor_sync(0xffffffffu, sq, off);
    }
    const float mu   = s * (1.0f / DQ);
    const float var  = sq * (1.0f / DQ) - mu * mu;
    const float rstd = rsqrtf(var + 1e-5f);

    const float4* g4 = (const float4*)gw;
    const float4* b4 = (const float4*)bw;
    float4* o4 = (float4*)(outp + (size_t)row * DQ);
    #pragma unroll
    for (int i = 0; i < 4; i++) {
        float4 g = g4[lane + 32 * i], b = b4[lane + 32 * i], r;
        r.x = (v[i].x - mu) * rstd * g.x + b.x;
        r.y = (v[i].y - mu) * rstd * g.y + b.y;
        r.z = (v[i].z - mu) * rstd * g.z + b.z;
        r.w = (v[i].w - mu) * rstd * g.w + b.w;
        o4[lane + 32 * i] = r;
    }
}

// ---------------------------------------------------------------------------
// GEMM tile config
// ---------------------------------------------------------------------------
#define GS_A 9216                      // 128*72 halves
#define GS_B 8704                      // 64*136 halves
#define GSTG (GS_A + GS_B)             // 17920 halves / stage
#define GEMM_SMEM (3 * GSTG * 2)       // 107520 bytes

// ---------------------------------------------------------------------------
// Merged Q/K/V projection: one launch, grid.z selects the matrix.
// LPT ordering: launch z=0,1 -> long K/V gemms (K=768) first; z=2 -> Q last.
// ---------------------------------------------------------------------------
__global__ __launch_bounds__(256, 2) void qkv_gemm()
{
    extern __shared__ __half smh[];
    const uint32_t sbase = (uint32_t)__cvta_generic_to_shared(smh);

    const __half* A; const __half* W; __half* C; int K; float osc;
    if (blockIdx.z == 0)      { A = g_cn; W = g_wk; C = g_k; K = DC; osc = 1.0f; }
    else if (blockIdx.z == 1) { A = g_cn; W = g_wv; C = g_v; K = DC; osc = 1.0f; }
    else                      { A = g_xn; W = g_wq; C = g_q; K = DQ; osc = QSCALE; }

    const int tid = threadIdx.x;
    const int lane = tid & 31, warp = tid >> 5;
    const int wm = (warp >> 2) * 64;
    const int wn = (warp & 3) * 32;
    const int m0 = blockIdx.y * 128;
    const int n0 = blockIdx.x * 128;
    const int g = lane >> 2, t = lane & 3;

    const int a_row = lane & 15, a_col = (lane >> 4) * 8;
    const int b_row = (lane & 7) + ((lane >> 3) & 1) * 8;
    const int b_col = ((lane >> 4) & 1) * 8;

    float acc[4][4][4];
    #pragma unroll
    for (int i = 0; i < 4; i++)
        #pragma unroll
        for (int j = 0; j < 4; j++)
            #pragma unroll
            for (int q = 0; q < 4; q++) acc[i][j][q] = 0.f;

    auto load_tile = [&](int kt, int buf) {
        int k0 = kt * 64;
        __half* As = smh + buf * GSTG;
        __half* Bs = smh + buf * GSTG + GS_A;
        #pragma unroll
        for (int i = 0; i < 4; i++) {
            int id = tid + i * 256;
            int ar = id >> 3, ac = (id & 7) * 8;
            cp16g(&As[ar * 72 + ac], &A[(size_t)(m0 + ar) * K + k0 + ac]);
            int br = id >> 4, bc = (id & 15) * 8;
            cp16g(&Bs[br * 136 + bc], &W[(size_t)(k0 + br) * INNER + n0 + bc]);
        }
    };

    const int ntiles = K / 64;
    load_tile(0, 0); cp_commit();
    load_tile(1, 1); cp_commit();
    cp_wait1();
    __syncthreads();

    for (int kt = 0; kt < ntiles; kt++) {
        const int cur = kt % 3;
        if (kt + 2 < ntiles) load_tile(kt + 2, (kt + 2) % 3);
        cp_commit();

        const uint32_t abase = sbase + (uint32_t)(cur * GSTG) * 2;
        const uint32_t bbase = abase + (uint32_t)GS_A * 2;

        #pragma unroll
        for (int ks = 0; ks < 4; ks++) {
            uint32_t af[4][4];
            #pragma unroll
            for (int mt = 0; mt < 4; mt++) {
                uint32_t addr = abase +
                    (uint32_t)(((wm + mt * 16 + a_row) * 72 + ks * 16 + a_col) << 1);
                ldsm4(af[mt][0], af[mt][1], af[mt][2], af[mt][3], addr);
            }
            uint32_t bf[8];
            #pragma unroll
            for (int n2 = 0; n2 < 2; n2++) {
                uint32_t addr = bbase +
                    (uint32_t)(((ks * 16 + b_row) * 136 + wn + n2 * 16 + b_col) << 1);
                ldsm4t(bf[n2*4], bf[n2*4+1], bf[n2*4+2], bf[n2*4+3], addr);
            }
            #pragma unroll
            for (int mt = 0; mt < 4; mt++)
                #pragma unroll
                for (int nt = 0; nt < 4; nt++)
                    mma16(acc[mt][nt], af[mt][0], af[mt][1], af[mt][2], af[mt][3],
                          bf[nt*2], bf[nt*2+1]);
        }

        cp_wait1();
        __syncthreads();
    }

    #pragma unroll
    for (int mt = 0; mt < 4; mt++) {
        int row = m0 + wm + mt * 16 + g;
        #pragma unroll
        for (int nt = 0; nt < 4; nt++) {
            int col = n0 + wn + nt * 8 + 2 * t;
            *(__half2*)&C[(size_t)row * INNER + col] =
                __floats2half2_rn(acc[mt][nt][0] * osc, acc[mt][nt][1] * osc);
            *(__half2*)&C[(size_t)(row + 8) * INNER + col] =
                __floats2half2_rn(acc[mt][nt][2] * osc, acc[mt][nt][3] * osc);
        }
    }
}

// ---------------------------------------------------------------------------
// O-projection GEMM (fp32 out + bias + residual)
// ---------------------------------------------------------------------------
__global__ __launch_bounds__(256, 2) void gemm_o(
    const float* __restrict__ bias, const float* __restrict__ resid)
{
    extern __shared__ __half smh[];
    const uint32_t sbase = (uint32_t)__cvta_generic_to_shared(smh);
    const __half* A = g_ao;
    const __half* W = g_wo;
    float* Cf = g_y;
    const int K = INNER, N = DQ;

    const int tid = threadIdx.x;
    const int lane = tid & 31, warp = tid >> 5;
    const int wm = (warp >> 2) * 64;
    const int wn = (warp & 3) * 32;
    const int m0 = blockIdx.y * 128;
    const int n0 = blockIdx.x * 128;
    const int g = lane >> 2, t = lane & 3;

    const int a_row = lane & 15, a_col = (lane >> 4) * 8;
    const int b_row = (lane & 7) + ((lane >> 3) & 1) * 8;
    const int b_col = ((lane >> 4) & 1) * 8;

    float acc[4][4][4];
    #pragma unroll
    for (int i = 0; i < 4; i++)
        #pragma unroll
        for (int j = 0; j < 4; j++)
            #pragma unroll
            for (int q = 0; q < 4; q++) acc[i][j][q] = 0.f;

    auto load_tile = [&](int kt, int buf) {
        int k0 = kt * 64;
        __half* As = smh + buf * GSTG;
        __half* Bs = smh + buf * GSTG + GS_A;
        #pragma unroll
        for (int i = 0; i < 4; i++) {
            int id = tid + i * 256;
            int ar = id >> 3, ac = (id & 7) * 8;
            cp16g(&As[ar * 72 + ac], &A[(size_t)(m0 + ar) * K + k0 + ac]);
            int br = id >> 4, bc = (id & 15) * 8;
            cp16g(&Bs[br * 136 + bc], &W[(size_t)(k0 + br) * N + n0 + bc]);
        }
    };

    const int ntiles = K / 64;
    load_tile(0, 0); cp_commit();
    load_tile(1, 1); cp_commit();
    cp_wait1();
    __syncthreads();

    for (int kt = 0; kt < ntiles; kt++) {
        const int cur = kt % 3;
        if (kt + 2 < ntiles) load_tile(kt + 2, (kt + 2) % 3);
        cp_commit();

        const uint32_t abase = sbase + (uint32_t)(cur * GSTG) * 2;
        const uint32_t bbase = abase + (uint32_t)GS_A * 2;

        #pragma unroll
        for (int ks = 0; ks < 4; ks++) {
            uint32_t af[4][4];
            #pragma unroll
            for (int mt = 0; mt < 4; mt++) {
                uint32_t addr = abase +
                    (uint32_t)(((wm + mt * 16 + a_row) * 72 + ks * 16 + a_col) << 1);
                ldsm4(af[mt][0], af[mt][1], af[mt][2], af[mt][3], addr);
            }
            uint32_t bf[8];
            #pragma unroll
            for (int n2 = 0; n2 < 2; n2++) {
                uint32_t addr = bbase +
                    (uint32_t)(((ks * 16 + b_row) * 136 + wn + n2 * 16 + b_col) << 1);
                ldsm4t(bf[n2*4], bf[n2*4+1], bf[n2*4+2], bf[n2*4+3], addr);
            }
            #pragma unroll
            for (int mt = 0; mt < 4; mt++)
                #pragma unroll
                for (int nt = 0; nt < 4; nt++)
                    mma16(acc[mt][nt], af[mt][0], af[mt][1], af[mt][2], af[mt][3],
                          bf[nt*2], bf[nt*2+1]);
        }

        cp_wait1();
        __syncthreads();
    }

    #pragma unroll
    for (int mt = 0; mt < 4; mt++) {
        int row = m0 + wm + mt * 16 + g;
        #pragma unroll
        for (int nt = 0; nt < 4; nt++) {
            int col = n0 + wn + nt * 8 + 2 * t;
            float2 r01 = { acc[mt][nt][0], acc[mt][nt][1] };
            float2 r23 = { acc[mt][nt][2], acc[mt][nt][3] };
            float2 bb = *(const float2*)&bias[col];
            r01.x += bb.x; r01.y += bb.y;
            r23.x += bb.x; r23.y += bb.y;
            float2 e0 = *(const float2*)&resid[(size_t)row * N + col];
            float2 e1 = *(const float2*)&resid[(size_t)(row + 8) * N + col];
            r01.x += e0.x; r01.y += e0.y;
            r23.x += e1.x; r23.y += e1.y;
            *(float2*)&Cf[(size_t)row * N + col]       = r01;
            *(float2*)&Cf[(size_t)(row + 8) * N + col] = r23;
        }
    }
}

// ---------------------------------------------------------------------------
// fp16 flash attention (unchanged from round-14 best): FA2 register-P,
// base-2 f16x2 softmax, tensor-core l, record-max vote skip.
// ---------------------------------------------------------------------------
#define KVROWS 128
#define KSTG (KVROWS * 72)                       // 9216 halves (K per stage)
#define STG2 (2 * KSTG)                          // K+V per stage, halves
#define ATTN_SMEM (3 * STG2 * 2)                 // 110592 bytes

__global__ __launch_bounds__(256, 2) void attn_h(
    const __half* __restrict__ Qg, const __half* __restrict__ Kg,
    const __half* __restrict__ Vg, __half* __restrict__ Og)
{
    extern __shared__ __half smh[];
    __half* Qs = smh + 2 * STG2;    // overlaps stage 2 (consumed pre-loop)
    const uint32_t sbase  = (uint32_t)__cvta_generic_to_shared(smh);
    const uint32_t qsbase = (uint32_t)__cvta_generic_to_shared(Qs);

    const int tid  = threadIdx.x;
    const int lane = tid & 31, warp = tid >> 5;
    const int g = lane >> 2, t = lane & 3;
    const int Rr = warp * 16;
    const int it = blockIdx.x, h = blockIdx.y, b = blockIdx.z;

    const __half* qb = Qg + ((size_t)b * NN + it * 128) * INNER + h * DH;
    const __half* kb = Kg + (size_t)b * MM * INNER + h * DH;
    const __half* vb = Vg + (size_t)b * MM * INNER + h * DH;

    const int a_row = lane & 15, a_col = (lane >> 4) * 8;
    const int k_row = (lane & 7) + ((lane >> 4) & 1) * 8;
    const int k_col = ((lane >> 3) & 1) * 8;
    const int v_row = (lane & 7) + ((lane >> 3) & 1) * 8;
    const int v_col = ((lane >> 4) & 1) * 8;

    auto load_chunk = [&](int buf, int j0) {
        __half* Ks = smh + buf * STG2;
        __half* Vs = Ks + KSTG;
        #pragma unroll
        for (int i = 0; i < 4; i++) {
            int id = tid + i * 256;
            int r = id >> 3, c = (id & 7) * 8;
            cp16g(&Ks[r * 72 + c], &kb[(size_t)(j0 + r) * INNER + c]);
            cp16g(&Vs[r * 72 + c], &vb[(size_t)(j0 + r) * INNER + c]);
        }
    };

    #pragma unroll
    for (int i = 0; i < 4; i++) {
        int id = tid + i * 256;
        int r = id >> 3, c = (id & 7) * 8;
        cp16g(&Qs[r * 72 + c], &qb[(size_t)r * INNER + c]);
    }
    cp_commit();                 // group: Q
    load_chunk(0, 0);
    cp_commit();                 // group: chunk0
    load_chunk(1, KVROWS);
    cp_commit();                 // group: chunk1
    cp_wait2();                  // Q resident
    __syncthreads();

    uint32_t qf[4][4];
    #pragma unroll
    for (int ks = 0; ks < 4; ks++) {
        uint32_t addr = qsbase + (uint32_t)(((Rr + a_row) * 72 + ks * 16 + a_col) << 1);
        ldsm4(qf[ks][0], qf[ks][1], qf[ks][2], qf[ks][3], addr);
    }
    __syncthreads();             // Q reads done before stage-2 reload

    float of[8][4];
    #pragma unroll
    for (int i = 0; i < 8; i++)
        #pragma unroll
        for (int q = 0; q < 4; q++) of[i][q] = 0.f;
    float lacc[4] = {0.f, 0.f, 0.f, 0.f};   // l via P @ ones (rows g, g+8)
    float m0r = -INFINITY, m1r = -INFINITY;

    const int nch = MM / KVROWS;   // 16
    for (int ch = 0; ch < nch; ch++) {
        const int cur = ch % 3;
        if (ch + 2 < nch) load_chunk((ch + 2) % 3, (ch + 2) * KVROWS);
        cp_commit();

        const uint32_t kbase = sbase + (uint32_t)(cur * STG2) * 2;
        const uint32_t vbase = kbase + (uint32_t)KSTG * 2;

        #pragma unroll
        for (int sub = 0; sub < 2; sub++) {
            const int roff = sub * 64;

            // S = Q K^T (log2 domain)
            float sacc[8][4];
            #pragma unroll
            for (int i = 0; i < 8; i++)
                #pragma unroll
                for (int q = 0; q < 4; q++) sacc[i][q] = 0.f;
            #pragma unroll
            for (int ks = 0; ks < 4; ks++) {
                #pragma unroll
                for (int n2 = 0; n2 < 4; n2++) {
                    uint32_t kf0, kf1, kf2, kf3;
                    uint32_t addr = kbase +
                        (uint32_t)(((roff + n2 * 16 + k_row) * 72 + ks * 16 + k_col) << 1);
                    ldsm4(kf0, kf1, kf2, kf3, addr);
                    mma16(sacc[n2*2],   qf[ks][0], qf[ks][1], qf[ks][2], qf[ks][3], kf0, kf1);
                    mma16(sacc[n2*2+1], qf[ks][0], qf[ks][1], qf[ks][2], qf[ks][3], kf2, kf3);
                }
            }

            // local max per row-group
            float rmax0 = -INFINITY, rmax1 = -INFINITY;
            #pragma unroll
            for (int nt = 0; nt < 8; nt++) {
                rmax0 = fmaxf(rmax0, fmaxf(sacc[nt][0], sacc[nt][1]));
                rmax1 = fmaxf(rmax1, fmaxf(sacc[nt][2], sacc[nt][3]));
            }

            // record-max vote: skip shuffle chain + rescale when max unchanged
            float mn0 = m0r, mn1 = m1r;
            if (__any_sync(0xffffffffu, (rmax0 > m0r) || (rmax1 > m1r))) {
                rmax0 = fmaxf(rmax0, __shfl_xor_sync(0xffffffffu, rmax0, 1));
                rmax0 = fmaxf(rmax0, __shfl_xor_sync(0xffffffffu, rmax0, 2));
                rmax1 = fmaxf(rmax1, __shfl_xor_sync(0xffffffffu, rmax1, 1));
                rmax1 = fmaxf(rmax1, __shfl_xor_sync(0xffffffffu, rmax1, 2));
                mn0 = fmaxf(m0r, rmax0);
                mn1 = fmaxf(m1r, rmax1);
                float c0 = exp2f(m0r - mn0), c1 = exp2f(m1r - mn1);
                m0r = mn0; m1r = mn1;
                #pragma unroll
                for (int nt = 0; nt < 8; nt++) {
                    of[nt][0] *= c0; of[nt][1] *= c0;
                    of[nt][2] *= c1; of[nt][3] *= c1;
                }
                lacc[0] *= c0;
                lacc[2] *= c1;
            }

            // exp2 -> fp16 PV A-fragments
            uint32_t pf[4][4];
            #pragma unroll
            for (int ks = 0; ks < 4; ks++) {
                #pragma unroll
                for (int half = 0; half < 2; half++) {
                    const int nt = 2 * ks + half;
                    __half2 e01 = h2exp2(__floats2half2_rn(sacc[nt][0] - mn0, sacc[nt][1] - mn0));
                    __half2 e23 = h2exp2(__floats2half2_rn(sacc[nt][2] - mn1, sacc[nt][3] - mn1));
                    pf[ks][2*half]   = h2_as_u32(e01);
                    pf[ks][2*half+1] = h2_as_u32(e23);
                }
            }

            // O += P @ V, and l += P @ ones (tensor-core row sums)
            #pragma unroll
            for (int ks = 0; ks < 4; ks++) {
                mma16(lacc, pf[ks][0], pf[ks][1], pf[ks][2], pf[ks][3],
                      H2_ONES, H2_ONES);
                #pragma unroll
                for (int n2 = 0; n2 < 4; n2++) {
                    uint32_t vf0, vf1, vf2, vf3;
                    uint32_t addr = vbase +
                        (uint32_t)(((roff + ks * 16 + v_row) * 72 + n2 * 16 + v_col) << 1);
                    ldsm4t(vf0, vf1, vf2, vf3, addr);
                    mma16(of[n2*2],   pf[ks][0], pf[ks][1], pf[ks][2], pf[ks][3], vf0, vf1);
                    mma16(of[n2*2+1], pf[ks][0], pf[ks][1], pf[ks][2], pf[ks][3], vf2, vf3);
                }
            }
        }

        cp_wait1();
        __syncthreads();
    }

    float inv0 = 1.f / lacc[0], inv1 = 1.f / lacc[2];
    int row0 = it * 128 + Rr + g, row1 = row0 + 8;
    #pragma unroll
    for (int nt = 0; nt < 8; nt++) {
        *(__half2*)&Og[((size_t)b * NN + row0) * INNER + h * DH + nt * 8 + 2 * t] =
            __floats2half2_rn(of[nt][0] * inv0, of[nt][1] * inv0);
        *(__half2*)&Og[((size_t)b * NN + row1) * INNER + h * DH + nt * 8 + 2 * t] =
            __floats2half2_rn(of[nt][2] * inv1, of[nt][3] * inv1);
    }
}

// ---------------------------------------------------------------------------
// Launch
// ---------------------------------------------------------------------------
extern "C" void kernel_launch(void* const* d_in, const int* in_sizes, int n_in,
                              void* d_out, int out_size)
{
    (void)in_sizes; (void)n_in; (void)out_size;
    const float* x     = (const float*)d_in[0];
    const float* cond  = (const float*)d_in[1];
    const float* lnx_g = (const float*)d_in[2];
    const float* lnx_b = (const float*)d_in[3];
    const float* lnc_g = (const float*)d_in[4];
    const float* lnc_b = (const float*)d_in[5];
    const float* Wq    = (const float*)d_in[6];
    const float* Wk    = (const float*)d_in[7];
    const float* Wv    = (const float*)d_in[8];
    const float* Wo    = (const float*)d_in[9];
    const float* bo    = (const float*)d_in[10];
    const float* lnf_g = (const float*)d_in[11];
    const float* lnf_b = (const float*)d_in[12];
    float* out = (float*)d_out;

    __half *q, *k, *v, *ao;
    float *y;
    cudaGetSymbolAddress((void**)&q,  g_q);
    cudaGetSymbolAddress((void**)&k,  g_k);
    cudaGetSymbolAddress((void**)&v,  g_v);
    cudaGetSymbolAddress((void**)&ao, g_ao);
    cudaGetSymbolAddress((void**)&y,  g_y);

    cudaFuncSetAttribute(qkv_gemm, cudaFuncAttributeMaxDynamicSharedMemorySize, GEMM_SMEM);
    cudaFuncSetAttribute(gemm_o,  cudaFuncAttributeMaxDynamicSharedMemorySize, GEMM_SMEM);
    cudaFuncSetAttribute(attn_h,  cudaFuncAttributeMaxDynamicSharedMemorySize, ATTN_SMEM);

    prep_kernel<<<LN_BLK + F2H_BLK, 256>>>(x, lnx_g, lnx_b, cond, lnc_g, lnc_b,
                                           (const float4*)Wq, (const float4*)Wk,
                                           (const float4*)Wv, (const float4*)Wo);

    dim3 gthr(256);
    qkv_gemm<<<dim3(INNER / 128, (BB * NN) / 128, 3), gthr, GEMM_SMEM>>>();

    dim3 ga(NN / 128, HH, BB);
    attn_h<<<ga, gthr, ATTN_SMEM>>>(q, k, v, ao);

    gemm_o<<<dim3(DQ / 128, (BB * NN) / 128), gthr, GEMM_SMEM>>>(bo, x);

    ln_out<<<(BB * NN) / 8, 256>>>(y, lnf_g, lnf_b, out);
}